// round 1
// baseline (speedup 1.0000x reference)
#include <cuda_runtime.h>
#include <cstdint>

// Problem constants
#define B_ 2
#define T_ 4096
#define H_ 4
#define HD 32
#define P_ 2048
#define TK 6144           // P_ + T_
#define DM 128            // D_MODEL
#define RSQRT_HD 0.17677669529663687f

typedef unsigned long long u64;

// ---------------- scratch (device globals; no allocation allowed) ------------
__device__ float g_q[(size_t)B_ * H_ * T_ * HD];      // [B][H][T][32], pre-scaled by 1/sqrt(hd)
__device__ float g_k[(size_t)B_ * H_ * TK * HD];      // [B][H][TK][32]
__device__ float g_v[(size_t)B_ * H_ * TK * HD];
__device__ float g_ctx[(size_t)B_ * T_ * DM];         // [B][T][128] head-interleaved

// ---------------- packed f32x2 helpers --------------------------------------
__device__ __forceinline__ u64 ffma2(u64 a, u64 b, u64 c) {
    u64 d;
    asm("fma.rn.f32x2 %0, %1, %2, %3;" : "=l"(d) : "l"(a), "l"(b), "l"(c));
    return d;
}
__device__ __forceinline__ u64 add2(u64 a, u64 b) {
    u64 d;
    asm("add.rn.f32x2 %0, %1, %2;" : "=l"(d) : "l"(a), "l"(b));
    return d;
}
__device__ __forceinline__ u64 pack2(float lo, float hi) {
    u64 d;
    asm("mov.b64 %0, {%1, %2};" : "=l"(d) : "f"(lo), "f"(hi));
    return d;
}
__device__ __forceinline__ void unpack2(u64 v, float& lo, float& hi) {
    asm("mov.b64 {%0, %1}, %2;" : "=f"(lo), "=f"(hi) : "l"(v));
}

// ---------------- GEMM 1: qkv = x @ Wqkv, scatter to g_q/g_k/g_v ------------
// A: [8192,128] row-major (x), W: [128,384] row-major.
// Tile 64x64, BK=16, 256 threads, 4x4 per thread.
__global__ void __launch_bounds__(256) gemm_qkv(const float* __restrict__ A,
                                                const float* __restrict__ W) {
    __shared__ float As[16][68];   // transposed chunk: As[k][m]
    __shared__ float Ws[16][68];   // Ws[k][n]
    const int tx = threadIdx.x & 15;
    const int ty = threadIdx.x >> 4;
    const int m0 = blockIdx.x * 64;
    const int n0 = blockIdx.y * 64;

    float c[4][4];
#pragma unroll
    for (int i = 0; i < 4; i++)
#pragma unroll
        for (int j = 0; j < 4; j++) c[i][j] = 0.f;

    for (int k0 = 0; k0 < 128; k0 += 16) {
#pragma unroll
        for (int i = 0; i < 4; i++) {
            int lin = threadIdx.x + 256 * i;       // 0..1023
            int m = lin >> 4, kk = lin & 15;
            As[kk][m] = A[(size_t)(m0 + m) * 128 + k0 + kk];
        }
#pragma unroll
        for (int i = 0; i < 4; i++) {
            int lin = threadIdx.x + 256 * i;
            int kk = lin >> 6, n = lin & 63;
            Ws[kk][n] = W[(size_t)(k0 + kk) * 384 + n0 + n];
        }
        __syncthreads();
#pragma unroll
        for (int kk = 0; kk < 16; kk++) {
            float4 a = *(const float4*)&As[kk][4 * ty];
            float4 b = *(const float4*)&Ws[kk][4 * tx];
            const float av[4] = {a.x, a.y, a.z, a.w};
            const float bv[4] = {b.x, b.y, b.z, b.w};
#pragma unroll
            for (int i = 0; i < 4; i++)
#pragma unroll
                for (int j = 0; j < 4; j++) c[i][j] = fmaf(av[i], bv[j], c[i][j]);
        }
        __syncthreads();
    }

    // scatter epilogue
#pragma unroll
    for (int i = 0; i < 4; i++) {
        const int m = m0 + 4 * ty + i;
        const int b = m >> 12;          // /T_
        const int t = m & (T_ - 1);
#pragma unroll
        for (int j = 0; j < 4; j++) {
            const int n = n0 + 4 * tx + j;
            const int sec = n >> 7;      // /128
            const int r = n & 127;
            const int h = r >> 5;
            const int d = r & 31;
            const float val = c[i][j];
            if (sec == 0) {
                g_q[(((size_t)(b * H_ + h) * T_) + t) * HD + d] = val * RSQRT_HD;
            } else if (sec == 1) {
                g_k[(((size_t)(b * H_ + h) * TK) + P_ + t) * HD + d] = val;
            } else {
                g_v[(((size_t)(b * H_ + h) * TK) + P_ + t) * HD + d] = val;
            }
        }
    }
}

// ---------------- prefix copy: pk/pv -> g_k/g_v[:, :P] ----------------------
__global__ void prefix_copy(const float4* __restrict__ pk, const float4* __restrict__ pv) {
    int idx = blockIdx.x * blockDim.x + threadIdx.x;   // over B*H*P*32/4 = 131072 float4
    if (idx < B_ * H_ * P_ * HD / 4) {
        const int per_bh = P_ * HD / 4;                // 16384
        int bh = idx / per_bh;
        int rem = idx - bh * per_bh;
        ((float4*)g_k)[(size_t)bh * (TK * HD / 4) + rem] = pk[idx];
        ((float4*)g_v)[(size_t)bh * (TK * HD / 4) + rem] = pv[idx];
    }
}

// ---------------- attention: thread-per-query flash (no running max) --------
__device__ __forceinline__ void attn_step(const u64* __restrict__ kr,
                                          const u64* __restrict__ vr,
                                          const u64* __restrict__ q2,
                                          u64* __restrict__ acc,
                                          float& l, bool valid) {
    u64 s0 = 0ULL, s1 = 0ULL, s2 = 0ULL, s3 = 0ULL;
#pragma unroll
    for (int d = 0; d < 16; d += 4) {
        s0 = ffma2(q2[d + 0], kr[d + 0], s0);
        s1 = ffma2(q2[d + 1], kr[d + 1], s1);
        s2 = ffma2(q2[d + 2], kr[d + 2], s2);
        s3 = ffma2(q2[d + 3], kr[d + 3], s3);
    }
    u64 t01 = add2(s0, s1);
    u64 t23 = add2(s2, s3);
    u64 tt = add2(t01, t23);
    float lo, hi;
    unpack2(tt, lo, hi);
    float s = lo + hi;                          // q pre-scaled by 1/sqrt(hd)
    float p = valid ? __expf(s) : 0.f;          // scores ~N(0,1): no overflow risk
    l += p;
    u64 p2 = pack2(p, p);
#pragma unroll
    for (int d = 0; d < 16; d++) acc[d] = ffma2(p2, vr[d], acc[d]);
}

__global__ void __launch_bounds__(128) attn_kernel() {
    __shared__ u64 Ks[64 * 16];    // 64 keys x 32 floats
    __shared__ u64 Vs[64 * 16];

    const int b = blockIdx.z;
    const int h = blockIdx.y;
    // heaviest q-blocks first for better wave packing
    const int q0 = (gridDim.x - 1 - blockIdx.x) * 128;
    const int tid = threadIdx.x;
    const int qi = q0 + tid;

    const float* qp = g_q + (((size_t)(b * H_ + h) * T_) + qi) * HD;
    u64 q2[16];
#pragma unroll
    for (int d = 0; d < 16; d++) q2[d] = ((const u64*)qp)[d];

    u64 acc[16];
#pragma unroll
    for (int d = 0; d < 16; d++) acc[d] = 0ULL;
    float l = 0.f;

    const float4* kbase = (const float4*)(g_k + (size_t)(b * H_ + h) * TK * HD);
    const float4* vbase = (const float4*)(g_v + (size_t)(b * H_ + h) * TK * HD);

    const int nfull = (P_ + q0) >> 6;   // tiles of 64 keys fully valid for ALL threads
    const int ntot = nfull + 2;         // [P+q0, P+q0+128) is the per-thread masked region
    const int kmax = P_ + qi;           // inclusive causal bound for this query

    for (int t = 0; t < ntot; t++) {
        const int j0 = t << 6;
        __syncthreads();
#pragma unroll
        for (int i = 0; i < 4; i++) {
            const int f = tid + (i << 7);                 // 0..511 float4 slots
            ((float4*)Ks)[f] = kbase[(size_t)j0 * 8 + f]; // 8 float4 per key-row
            ((float4*)Vs)[f] = vbase[(size_t)j0 * 8 + f];
        }
        __syncthreads();

        if (t < nfull) {
#pragma unroll 2
            for (int j = 0; j < 64; j++)
                attn_step(&Ks[j * 16], &Vs[j * 16], q2, acc, l, true);
        } else {
#pragma unroll 2
            for (int j = 0; j < 64; j++) {
                const bool ok = (j0 + j) <= kmax;
                attn_step(&Ks[j * 16], &Vs[j * 16], q2, acc, l, ok);
            }
        }
    }

    const float inv = 1.f / l;
    float* op = g_ctx + ((size_t)b * T_ + qi) * DM + h * HD;
#pragma unroll
    for (int d = 0; d < 16; d++) {
        float lo, hi;
        unpack2(acc[d], lo, hi);
        float2 o = make_float2(lo * inv, hi * inv);
        *(float2*)&op[2 * d] = o;
    }
}

// ---------------- GEMM 2: out = g_ctx @ Wout --------------------------------
__global__ void __launch_bounds__(256) gemm_out(const float* __restrict__ W,
                                               float* __restrict__ out) {
    __shared__ float As[16][68];
    __shared__ float Ws[16][68];
    const int tx = threadIdx.x & 15;
    const int ty = threadIdx.x >> 4;
    const int m0 = blockIdx.x * 64;
    const int n0 = blockIdx.y * 64;

    float c[4][4];
#pragma unroll
    for (int i = 0; i < 4; i++)
#pragma unroll
        for (int j = 0; j < 4; j++) c[i][j] = 0.f;

    for (int k0 = 0; k0 < 128; k0 += 16) {
#pragma unroll
        for (int i = 0; i < 4; i++) {
            int lin = threadIdx.x + 256 * i;
            int m = lin >> 4, kk = lin & 15;
            As[kk][m] = g_ctx[(size_t)(m0 + m) * 128 + k0 + kk];
        }
#pragma unroll
        for (int i = 0; i < 4; i++) {
            int lin = threadIdx.x + 256 * i;
            int kk = lin >> 6, n = lin & 63;
            Ws[kk][n] = W[(size_t)(k0 + kk) * 128 + n0 + n];
        }
        __syncthreads();
#pragma unroll
        for (int kk = 0; kk < 16; kk++) {
            float4 a = *(const float4*)&As[kk][4 * ty];
            float4 b = *(const float4*)&Ws[kk][4 * tx];
            const float av[4] = {a.x, a.y, a.z, a.w};
            const float bv[4] = {b.x, b.y, b.z, b.w};
#pragma unroll
            for (int i = 0; i < 4; i++)
#pragma unroll
                for (int j = 0; j < 4; j++) c[i][j] = fmaf(av[i], bv[j], c[i][j]);
        }
        __syncthreads();
    }

#pragma unroll
    for (int i = 0; i < 4; i++) {
        const int m = m0 + 4 * ty + i;
#pragma unroll
        for (int j = 0; j < 4; j++) {
            const int n = n0 + 4 * tx + j;
            out[(size_t)m * 128 + n] = c[i][j];
        }
    }
}

// ---------------- launch ----------------------------------------------------
extern "C" void kernel_launch(void* const* d_in, const int* in_sizes, int n_in,
                              void* d_out, int out_size) {
    const float* x    = (const float*)d_in[0];
    const float* pk   = (const float*)d_in[1];
    const float* pv   = (const float*)d_in[2];
    const float* Wqkv = (const float*)d_in[3];
    const float* Wout = (const float*)d_in[4];
    float* out = (float*)d_out;

    // 1) QKV projection + scatter (8192x384x128)
    {
        dim3 grid(8192 / 64, 384 / 64);
        gemm_qkv<<<grid, 256>>>(x, Wqkv);
    }
    // 2) prefix KV copy (independent of 1, but same stream is fine)
    {
        int n4 = B_ * H_ * P_ * HD / 4;   // 131072
        prefix_copy<<<(n4 + 255) / 256, 256>>>((const float4*)pk, (const float4*)pv);
    }
    // 3) attention
    {
        dim3 grid(T_ / 128, H_, B_);
        attn_kernel<<<grid, 128>>>();
    }
    // 4) output projection (8192x128x128)
    {
        dim3 grid(8192 / 64, 128 / 64);
        gemm_out<<<grid, 256>>>(Wout, out);
    }
}

// round 2
// speedup vs baseline: 1.3511x; 1.3511x over previous
#include <cuda_runtime.h>
#include <cstdint>

// Problem constants
#define B_ 2
#define T_ 4096
#define H_ 4
#define HD 32
#define P_ 2048
#define TK 6144           // P_ + T_
#define DM 128            // D_MODEL
#define KS 4              // key splits for attention
#define RSQRT_HD 0.17677669529663687f

typedef unsigned long long u64;

// ---------------- scratch (device globals; no allocation allowed) ------------
__device__ float g_q[(size_t)B_ * H_ * T_ * HD];      // [BH][T][32], pre-scaled by 1/sqrt(hd)
__device__ float g_k[(size_t)B_ * H_ * TK * HD];      // [BH][TK][32]
__device__ float g_v[(size_t)B_ * H_ * TK * HD];
__device__ float g_ctx[(size_t)B_ * T_ * DM];         // [B][T][128] head-interleaved
__device__ float g_pacc[(size_t)KS * B_ * H_ * T_ * HD];  // split partial numerators
__device__ float g_pl[(size_t)KS * B_ * H_ * T_];         // split partial denominators

// ---------------- packed f32x2 helpers --------------------------------------
__device__ __forceinline__ u64 ffma2(u64 a, u64 b, u64 c) {
    u64 d;
    asm("fma.rn.f32x2 %0, %1, %2, %3;" : "=l"(d) : "l"(a), "l"(b), "l"(c));
    return d;
}
__device__ __forceinline__ u64 add2(u64 a, u64 b) {
    u64 d;
    asm("add.rn.f32x2 %0, %1, %2;" : "=l"(d) : "l"(a), "l"(b));
    return d;
}
__device__ __forceinline__ u64 pack2(float lo, float hi) {
    u64 d;
    asm("mov.b64 %0, {%1, %2};" : "=l"(d) : "f"(lo), "f"(hi));
    return d;
}
__device__ __forceinline__ void unpack2(u64 v, float& lo, float& hi) {
    asm("mov.b64 {%0, %1}, %2;" : "=f"(lo), "=f"(hi) : "l"(v));
}

// ---------------- GEMM 1: qkv = x @ Wqkv, scatter to g_q/g_k/g_v ------------
__global__ void __launch_bounds__(256) gemm_qkv(const float* __restrict__ A,
                                                const float* __restrict__ W) {
    __shared__ float As[16][68];
    __shared__ float Ws[16][68];
    const int tx = threadIdx.x & 15;
    const int ty = threadIdx.x >> 4;
    const int m0 = blockIdx.x * 64;
    const int n0 = blockIdx.y * 64;

    float c[4][4];
#pragma unroll
    for (int i = 0; i < 4; i++)
#pragma unroll
        for (int j = 0; j < 4; j++) c[i][j] = 0.f;

    for (int k0 = 0; k0 < 128; k0 += 16) {
#pragma unroll
        for (int i = 0; i < 4; i++) {
            int lin = threadIdx.x + 256 * i;
            int m = lin >> 4, kk = lin & 15;
            As[kk][m] = A[(size_t)(m0 + m) * 128 + k0 + kk];
        }
#pragma unroll
        for (int i = 0; i < 4; i++) {
            int lin = threadIdx.x + 256 * i;
            int kk = lin >> 6, n = lin & 63;
            Ws[kk][n] = W[(size_t)(k0 + kk) * 384 + n0 + n];
        }
        __syncthreads();
#pragma unroll
        for (int kk = 0; kk < 16; kk++) {
            float4 a = *(const float4*)&As[kk][4 * ty];
            float4 b = *(const float4*)&Ws[kk][4 * tx];
            const float av[4] = {a.x, a.y, a.z, a.w};
            const float bv[4] = {b.x, b.y, b.z, b.w};
#pragma unroll
            for (int i = 0; i < 4; i++)
#pragma unroll
                for (int j = 0; j < 4; j++) c[i][j] = fmaf(av[i], bv[j], c[i][j]);
        }
        __syncthreads();
    }

#pragma unroll
    for (int i = 0; i < 4; i++) {
        const int m = m0 + 4 * ty + i;
        const int b = m >> 12;
        const int t = m & (T_ - 1);
#pragma unroll
        for (int j = 0; j < 4; j++) {
            const int n = n0 + 4 * tx + j;
            const int sec = n >> 7;
            const int r = n & 127;
            const int h = r >> 5;
            const int d = r & 31;
            const float val = c[i][j];
            if (sec == 0) {
                g_q[(((size_t)(b * H_ + h) * T_) + t) * HD + d] = val * RSQRT_HD;
            } else if (sec == 1) {
                g_k[(((size_t)(b * H_ + h) * TK) + P_ + t) * HD + d] = val;
            } else {
                g_v[(((size_t)(b * H_ + h) * TK) + P_ + t) * HD + d] = val;
            }
        }
    }
}

// ---------------- prefix copy: pk/pv -> g_k/g_v[:, :P] ----------------------
__global__ void prefix_copy(const float4* __restrict__ pk, const float4* __restrict__ pv) {
    int idx = blockIdx.x * blockDim.x + threadIdx.x;
    if (idx < B_ * H_ * P_ * HD / 4) {
        const int per_bh = P_ * HD / 4;
        int bh = idx / per_bh;
        int rem = idx - bh * per_bh;
        ((float4*)g_k)[(size_t)bh * (TK * HD / 4) + rem] = pk[idx];
        ((float4*)g_v)[(size_t)bh * (TK * HD / 4) + rem] = pv[idx];
    }
}

// ---------------- attention: split-K, thread-per-query, no running max ------
__device__ __forceinline__ void attn_step(const u64* __restrict__ kr,
                                          const u64* __restrict__ vr,
                                          const u64* __restrict__ q2,
                                          u64* __restrict__ acc,
                                          float& l, bool valid) {
    u64 s0 = 0ULL, s1 = 0ULL, s2 = 0ULL, s3 = 0ULL;
#pragma unroll
    for (int d = 0; d < 16; d += 4) {
        s0 = ffma2(q2[d + 0], kr[d + 0], s0);
        s1 = ffma2(q2[d + 1], kr[d + 1], s1);
        s2 = ffma2(q2[d + 2], kr[d + 2], s2);
        s3 = ffma2(q2[d + 3], kr[d + 3], s3);
    }
    u64 t01 = add2(s0, s1);
    u64 t23 = add2(s2, s3);
    u64 tt = add2(t01, t23);
    float lo, hi;
    unpack2(tt, lo, hi);
    float s = lo + hi;
    float p = valid ? __expf(s) : 0.f;   // scores ~N(0,1): no overflow risk
    l += p;
    u64 p2 = pack2(p, p);
#pragma unroll
    for (int d = 0; d < 16; d++) acc[d] = ffma2(p2, vr[d], acc[d]);
}

__global__ void __launch_bounds__(128) attn_split() {
    __shared__ u64 Ks[64 * 16];    // 64 keys x 32 floats
    __shared__ u64 Vs[64 * 16];

    const int split = blockIdx.y;
    const int bh = blockIdx.z;
    const int q0 = blockIdx.x * 128;
    const int tid = threadIdx.x;
    const int qi = q0 + tid;

    const float* qp = g_q + (((size_t)bh * T_) + qi) * HD;
    u64 q2[16];
#pragma unroll
    for (int d = 0; d < 16; d++) q2[d] = ((const u64*)qp)[d];

    u64 acc[16];
#pragma unroll
    for (int d = 0; d < 16; d++) acc[d] = 0ULL;
    float l = 0.f;

    const float4* kbase = (const float4*)(g_k + (size_t)bh * TK * HD);
    const float4* vbase = (const float4*)(g_v + (size_t)bh * TK * HD);

    const int nfull = (P_ + q0) >> 6;    // tiles fully valid for ALL threads of block
    const int ntot = nfull + 2;          // last 2 tiles are per-thread masked
    const int t_begin = (ntot * split) / KS;
    const int t_end = (ntot * (split + 1)) / KS;
    const int kmax = P_ + qi;            // inclusive causal bound

    for (int t = t_begin; t < t_end; t++) {
        const int j0 = t << 6;
        __syncthreads();
#pragma unroll
        for (int i = 0; i < 4; i++) {
            const int f = tid + (i << 7);
            ((float4*)Ks)[f] = kbase[(size_t)j0 * 8 + f];
            ((float4*)Vs)[f] = vbase[(size_t)j0 * 8 + f];
        }
        __syncthreads();

        if (t < nfull) {
#pragma unroll 2
            for (int j = 0; j < 64; j++)
                attn_step(&Ks[j * 16], &Vs[j * 16], q2, acc, l, true);
        } else {
#pragma unroll 2
            for (int j = 0; j < 64; j++) {
                const bool ok = (j0 + j) <= kmax;
                attn_step(&Ks[j * 16], &Vs[j * 16], q2, acc, l, ok);
            }
        }
    }

    // store partials
    u64* pa = (u64*)(g_pacc + (((size_t)split * (B_ * H_) + bh) * T_ + qi) * HD);
#pragma unroll
    for (int d = 0; d < 16; d++) pa[d] = acc[d];
    g_pl[((size_t)split * (B_ * H_) + bh) * T_ + qi] = l;
}

// ---------------- combine splits -> g_ctx -----------------------------------
__global__ void __launch_bounds__(256) attn_combine() {
    const int idx = blockIdx.x * blockDim.x + threadIdx.x;   // one thread per query
    if (idx >= B_ * H_ * T_) return;
    const int bh = idx >> 12;       // / T_
    const int qi = idx & (T_ - 1);
    const int b = bh >> 2;
    const int h = bh & 3;

    float l = 0.f;
#pragma unroll
    for (int s = 0; s < KS; s++)
        l += g_pl[((size_t)s * (B_ * H_) + bh) * T_ + qi];
    const float inv = 1.f / l;

    float* op = g_ctx + ((size_t)b * T_ + qi) * DM + h * HD;
#pragma unroll
    for (int d = 0; d < 16; d++) {
        float lo = 0.f, hi = 0.f;
#pragma unroll
        for (int s = 0; s < KS; s++) {
            const u64 v = ((const u64*)(g_pacc + (((size_t)s * (B_ * H_) + bh) * T_ + qi) * HD))[d];
            float a, bb;
            unpack2(v, a, bb);
            lo += a; hi += bb;
        }
        *(float2*)&op[2 * d] = make_float2(lo * inv, hi * inv);
    }
}

// ---------------- GEMM 2: out = g_ctx @ Wout --------------------------------
__global__ void __launch_bounds__(256) gemm_out(const float* __restrict__ W,
                                               float* __restrict__ out) {
    __shared__ float As[16][68];
    __shared__ float Ws[16][68];
    const int tx = threadIdx.x & 15;
    const int ty = threadIdx.x >> 4;
    const int m0 = blockIdx.x * 64;
    const int n0 = blockIdx.y * 64;

    float c[4][4];
#pragma unroll
    for (int i = 0; i < 4; i++)
#pragma unroll
        for (int j = 0; j < 4; j++) c[i][j] = 0.f;

    for (int k0 = 0; k0 < 128; k0 += 16) {
#pragma unroll
        for (int i = 0; i < 4; i++) {
            int lin = threadIdx.x + 256 * i;
            int m = lin >> 4, kk = lin & 15;
            As[kk][m] = g_ctx[(size_t)(m0 + m) * 128 + k0 + kk];
        }
#pragma unroll
        for (int i = 0; i < 4; i++) {
            int lin = threadIdx.x + 256 * i;
            int kk = lin >> 6, n = lin & 63;
            Ws[kk][n] = W[(size_t)(k0 + kk) * 128 + n0 + n];
        }
        __syncthreads();
#pragma unroll
        for (int kk = 0; kk < 16; kk++) {
            float4 a = *(const float4*)&As[kk][4 * ty];
            float4 b = *(const float4*)&Ws[kk][4 * tx];
            const float av[4] = {a.x, a.y, a.z, a.w};
            const float bv[4] = {b.x, b.y, b.z, b.w};
#pragma unroll
            for (int i = 0; i < 4; i++)
#pragma unroll
                for (int j = 0; j < 4; j++) c[i][j] = fmaf(av[i], bv[j], c[i][j]);
        }
        __syncthreads();
    }

#pragma unroll
    for (int i = 0; i < 4; i++) {
        const int m = m0 + 4 * ty + i;
#pragma unroll
        for (int j = 0; j < 4; j++) {
            const int n = n0 + 4 * tx + j;
            out[(size_t)m * 128 + n] = c[i][j];
        }
    }
}

// ---------------- launch ----------------------------------------------------
extern "C" void kernel_launch(void* const* d_in, const int* in_sizes, int n_in,
                              void* d_out, int out_size) {
    const float* x    = (const float*)d_in[0];
    const float* pk   = (const float*)d_in[1];
    const float* pv   = (const float*)d_in[2];
    const float* Wqkv = (const float*)d_in[3];
    const float* Wout = (const float*)d_in[4];
    float* out = (float*)d_out;

    {
        int n4 = B_ * H_ * P_ * HD / 4;
        prefix_copy<<<(n4 + 255) / 256, 256>>>((const float4*)pk, (const float4*)pv);
    }
    {
        dim3 grid(8192 / 64, 384 / 64);
        gemm_qkv<<<grid, 256>>>(x, Wqkv);
    }
    {
        dim3 grid(T_ / 128, KS, B_ * H_);
        attn_split<<<grid, 128>>>();
    }
    {
        attn_combine<<<(B_ * H_ * T_ + 255) / 256, 256>>>();
    }
    {
        dim3 grid(8192 / 64, 128 / 64);
        gemm_out<<<grid, 256>>>(Wout, out);
    }
}

// round 3
// speedup vs baseline: 2.8889x; 2.1382x over previous
#include <cuda_runtime.h>
#include <cstdint>

// Problem constants
#define B_ 2
#define T_ 4096
#define H_ 4
#define HD 32
#define P_ 2048
#define TK 6144           // P_ + T_
#define DM 128            // D_MODEL
#define RSQRT_HD 0.17677669529663687f

// ---------------- scratch (device globals; no allocation allowed) ------------
__device__ float g_q[(size_t)B_ * H_ * T_ * HD];      // [BH][T][32], pre-scaled by 1/sqrt(hd)
__device__ float g_k[(size_t)B_ * H_ * TK * HD];      // [BH][TK][32]
__device__ float g_v[(size_t)B_ * H_ * TK * HD];
__device__ float g_ctx[(size_t)B_ * T_ * DM];         // [B][T][128] head-interleaved

// ---------------- tf32 mma helpers ------------------------------------------
__device__ __forceinline__ uint32_t f2tf(float f) {
    uint32_t r;
    asm("cvt.rna.tf32.f32 %0, %1;" : "=r"(r) : "f"(f));
    return r;
}
__device__ __forceinline__ void mma8(float* c, const uint32_t* a, uint32_t b0, uint32_t b1) {
    asm("mma.sync.aligned.m16n8k8.row.col.f32.tf32.tf32.f32 "
        "{%0,%1,%2,%3},{%4,%5,%6,%7},{%8,%9},{%0,%1,%2,%3};"
        : "+f"(c[0]), "+f"(c[1]), "+f"(c[2]), "+f"(c[3])
        : "r"(a[0]), "r"(a[1]), "r"(a[2]), "r"(a[3]), "r"(b0), "r"(b1));
}

// ---------------- GEMM 1: qkv = x @ Wqkv, scatter to g_q/g_k/g_v ------------
__global__ void __launch_bounds__(256) gemm_qkv(const float* __restrict__ A,
                                                const float* __restrict__ W) {
    __shared__ float As[16][68];
    __shared__ float Ws[16][68];
    const int tx = threadIdx.x & 15;
    const int ty = threadIdx.x >> 4;
    const int m0 = blockIdx.x * 64;
    const int n0 = blockIdx.y * 64;

    float c[4][4];
#pragma unroll
    for (int i = 0; i < 4; i++)
#pragma unroll
        for (int j = 0; j < 4; j++) c[i][j] = 0.f;

    for (int k0 = 0; k0 < 128; k0 += 16) {
#pragma unroll
        for (int i = 0; i < 4; i++) {
            int lin = threadIdx.x + 256 * i;
            int m = lin >> 4, kk = lin & 15;
            As[kk][m] = A[(size_t)(m0 + m) * 128 + k0 + kk];
        }
#pragma unroll
        for (int i = 0; i < 4; i++) {
            int lin = threadIdx.x + 256 * i;
            int kk = lin >> 6, n = lin & 63;
            Ws[kk][n] = W[(size_t)(k0 + kk) * 384 + n0 + n];
        }
        __syncthreads();
#pragma unroll
        for (int kk = 0; kk < 16; kk++) {
            float4 a = *(const float4*)&As[kk][4 * ty];
            float4 b = *(const float4*)&Ws[kk][4 * tx];
            const float av[4] = {a.x, a.y, a.z, a.w};
            const float bv[4] = {b.x, b.y, b.z, b.w};
#pragma unroll
            for (int i = 0; i < 4; i++)
#pragma unroll
                for (int j = 0; j < 4; j++) c[i][j] = fmaf(av[i], bv[j], c[i][j]);
        }
        __syncthreads();
    }

#pragma unroll
    for (int i = 0; i < 4; i++) {
        const int m = m0 + 4 * ty + i;
        const int b = m >> 12;
        const int t = m & (T_ - 1);
#pragma unroll
        for (int j = 0; j < 4; j++) {
            const int n = n0 + 4 * tx + j;
            const int sec = n >> 7;
            const int r = n & 127;
            const int h = r >> 5;
            const int d = r & 31;
            const float val = c[i][j];
            if (sec == 0) {
                g_q[(((size_t)(b * H_ + h) * T_) + t) * HD + d] = val * RSQRT_HD;
            } else if (sec == 1) {
                g_k[(((size_t)(b * H_ + h) * TK) + P_ + t) * HD + d] = val;
            } else {
                g_v[(((size_t)(b * H_ + h) * TK) + P_ + t) * HD + d] = val;
            }
        }
    }
}

// ---------------- prefix copy -----------------------------------------------
__global__ void prefix_copy(const float4* __restrict__ pk, const float4* __restrict__ pv) {
    int idx = blockIdx.x * blockDim.x + threadIdx.x;
    if (idx < B_ * H_ * P_ * HD / 4) {
        const int per_bh = P_ * HD / 4;
        int bh = idx / per_bh;
        int rem = idx - bh * per_bh;
        ((float4*)g_k)[(size_t)bh * (TK * HD / 4) + rem] = pk[idx];
        ((float4*)g_v)[(size_t)bh * (TK * HD / 4) + rem] = pv[idx];
    }
}

// ---------------- tensor-core attention -------------------------------------
// Block: 64 threads = 2 warps. Warp w handles 32 queries (2 m16 chunks).
// q-tile 64 per block. Key tiles of 64. tf32 mma m16n8k8.
// No running max (scores ~N(0,1)); normalize once at the end.
__global__ void __launch_bounds__(64) attn_tc() {
    __shared__ float Ks[64][36];          // keys x headdim (tf32 bits), pad 36
    __shared__ float Vs[64][40];          // keys x headdim (tf32 bits), pad 40
    __shared__ float Ps[2][32][36];       // per-warp P half-tile (32q x 32k permuted)

    const int tid = threadIdx.x;
    const int w = tid >> 5;
    const int lane = tid & 31;
    const int g = lane >> 2;              // 0..7
    const int t4 = lane & 3;              // 0..3

    const int bh = blockIdx.x & 7;
    const int qt = 63 - (blockIdx.x >> 3);   // heavy q-tiles first
    const int q0 = qt * 64;
    const int b = bh >> 2;
    const int h = bh & 3;
    const int wq = q0 + w * 32;           // warp's first query

    // ---- Q fragments (persistent, tf32, pre-scaled by 1/sqrt(hd)) ----
    uint32_t qa[2][4][4];                  // [m-chunk][d-chunk][reg]
    {
        const float* qb = g_q + ((size_t)bh * T_) * HD;
#pragma unroll
        for (int m = 0; m < 2; m++) {
            const int r0 = wq + m * 16 + g;
#pragma unroll
            for (int dc = 0; dc < 4; dc++) {
                qa[m][dc][0] = f2tf(qb[(size_t)r0 * HD + dc * 8 + t4]);
                qa[m][dc][1] = f2tf(qb[(size_t)(r0 + 8) * HD + dc * 8 + t4]);
                qa[m][dc][2] = f2tf(qb[(size_t)r0 * HD + dc * 8 + t4 + 4]);
                qa[m][dc][3] = f2tf(qb[(size_t)(r0 + 8) * HD + dc * 8 + t4 + 4]);
            }
        }
    }

    float O[2][4][4];
#pragma unroll
    for (int m = 0; m < 2; m++)
#pragma unroll
        for (int dc = 0; dc < 4; dc++)
#pragma unroll
            for (int r = 0; r < 4; r++) O[m][dc][r] = 0.f;
    float lsum[2][2] = {{0.f, 0.f}, {0.f, 0.f}};

    const float* kb = g_k + (size_t)bh * TK * HD;
    const float* vb = g_v + (size_t)bh * TK * HD;
    const int ntiles = (P_ + q0) / 64 + 1;   // only the last tile is masked

    for (int t = 0; t < ntiles; t++) {
        const int j0 = t * 64;
        __syncthreads();
        // ---- load K/V tile (convert to tf32 at store) ----
#pragma unroll
        for (int i = 0; i < 8; i++) {
            const int fidx = tid + i * 64;          // 0..511 float4s
            const int key = fidx >> 3;
            const int d0 = (fidx & 7) << 2;
            float4 kv = *(const float4*)(kb + (size_t)(j0 + key) * HD + d0);
            float4 o;
            o.x = __uint_as_float(f2tf(kv.x)); o.y = __uint_as_float(f2tf(kv.y));
            o.z = __uint_as_float(f2tf(kv.z)); o.w = __uint_as_float(f2tf(kv.w));
            *(float4*)&Ks[key][d0] = o;
            float4 vv = *(const float4*)(vb + (size_t)(j0 + key) * HD + d0);
            o.x = __uint_as_float(f2tf(vv.x)); o.y = __uint_as_float(f2tf(vv.y));
            o.z = __uint_as_float(f2tf(vv.z)); o.w = __uint_as_float(f2tf(vv.w));
            *(float4*)&Vs[key][d0] = o;
        }
        __syncthreads();

        // ---- S = Q K^T (64q x 64k per block; this warp: 32q x 64k) ----
        float S[2][8][4];
#pragma unroll
        for (int nc = 0; nc < 8; nc++) {
#pragma unroll
            for (int m = 0; m < 2; m++)
#pragma unroll
                for (int r = 0; r < 4; r++) S[m][nc][r] = 0.f;
#pragma unroll
            for (int dc = 0; dc < 4; dc++) {
                const uint32_t b0 = __float_as_uint(Ks[nc * 8 + g][dc * 8 + t4]);
                const uint32_t b1 = __float_as_uint(Ks[nc * 8 + g][dc * 8 + t4 + 4]);
                mma8(S[0][nc], qa[0][dc], b0, b1);
                mma8(S[1][nc], qa[1][dc], b0, b1);
            }
        }

        // ---- softmax (no max-sub) + PV, in 32-key halves ----
        const bool diag = (t == ntiles - 1);
#pragma unroll
        for (int half = 0; half < 2; half++) {
#pragma unroll
            for (int ncl = 0; ncl < 4; ncl++) {
                const int nc = half * 4 + ncl;
#pragma unroll
                for (int m = 0; m < 2; m++) {
                    const float* s = S[m][nc];
                    float p0, p1, p2, p3;
                    if (diag) {
                        const int rbase = w * 32 + m * 16 + g;  // local row in 64-q tile
                        const int col0 = nc * 8 + 2 * t4;
                        p0 = (col0     <= rbase)     ? __expf(s[0]) : 0.f;
                        p1 = (col0 + 1 <= rbase)     ? __expf(s[1]) : 0.f;
                        p2 = (col0     <= rbase + 8) ? __expf(s[2]) : 0.f;
                        p3 = (col0 + 1 <= rbase + 8) ? __expf(s[3]) : 0.f;
                    } else {
                        p0 = __expf(s[0]); p1 = __expf(s[1]);
                        p2 = __expf(s[2]); p3 = __expf(s[3]);
                    }
                    lsum[m][0] += p0 + p1;
                    lsum[m][1] += p2 + p3;
                    // permuted store: element (row, c=2t4+e) -> col'' = (c&3)*8 + ncl*2 + (c>>2)
                    const int c0 = 2 * t4, c1 = 2 * t4 + 1;
                    const int pc0 = (c0 & 3) * 8 + ncl * 2 + (c0 >> 2);
                    const int pc1 = (c1 & 3) * 8 + ncl * 2 + (c1 >> 2);
                    const int r0 = m * 16 + g;
                    Ps[w][r0][pc0]     = __uint_as_float(f2tf(p0));
                    Ps[w][r0][pc1]     = __uint_as_float(f2tf(p1));
                    Ps[w][r0 + 8][pc0] = __uint_as_float(f2tf(p2));
                    Ps[w][r0 + 8][pc1] = __uint_as_float(f2tf(p3));
                }
            }
            __syncwarp();
            // PV for this half: O += P_half @ V_half
#pragma unroll
            for (int ks = 0; ks < 4; ks++) {
                uint32_t A[2][4];
#pragma unroll
                for (int m = 0; m < 2; m++) {
                    const float2 v0 = *(const float2*)&Ps[w][m * 16 + g][t4 * 8 + ks * 2];
                    const float2 v1 = *(const float2*)&Ps[w][m * 16 + g + 8][t4 * 8 + ks * 2];
                    A[m][0] = __float_as_uint(v0.x);
                    A[m][2] = __float_as_uint(v0.y);
                    A[m][1] = __float_as_uint(v1.x);
                    A[m][3] = __float_as_uint(v1.y);
                }
                const int kk = (half * 4 + ks) * 8;
#pragma unroll
                for (int dc = 0; dc < 4; dc++) {
                    const uint32_t b0 = __float_as_uint(Vs[kk + t4][dc * 8 + g]);
                    const uint32_t b1 = __float_as_uint(Vs[kk + t4 + 4][dc * 8 + g]);
                    mma8(O[0][dc], A[0], b0, b1);
                    mma8(O[1][dc], A[1], b0, b1);
                }
            }
            __syncwarp();
        }
    }

    // ---- epilogue: row-sum reduce + normalize + write ctx ----
#pragma unroll
    for (int m = 0; m < 2; m++) {
        float l0 = lsum[m][0];
        l0 += __shfl_xor_sync(0xFFFFFFFFu, l0, 1);
        l0 += __shfl_xor_sync(0xFFFFFFFFu, l0, 2);
        float l1 = lsum[m][1];
        l1 += __shfl_xor_sync(0xFFFFFFFFu, l1, 1);
        l1 += __shfl_xor_sync(0xFFFFFFFFu, l1, 2);
        const float inv0 = 1.f / l0;
        const float inv1 = 1.f / l1;
        const int r0 = wq + m * 16 + g;
        float* o0 = g_ctx + ((size_t)b * T_ + r0) * DM + h * HD;
        float* o1 = g_ctx + ((size_t)b * T_ + r0 + 8) * DM + h * HD;
#pragma unroll
        for (int dc = 0; dc < 4; dc++) {
            const int col = dc * 8 + 2 * t4;
            *(float2*)&o0[col] = make_float2(O[m][dc][0] * inv0, O[m][dc][1] * inv0);
            *(float2*)&o1[col] = make_float2(O[m][dc][2] * inv1, O[m][dc][3] * inv1);
        }
    }
}

// ---------------- GEMM 2: out = g_ctx @ Wout --------------------------------
__global__ void __launch_bounds__(256) gemm_out(const float* __restrict__ W,
                                               float* __restrict__ out) {
    __shared__ float As[16][68];
    __shared__ float Ws[16][68];
    const int tx = threadIdx.x & 15;
    const int ty = threadIdx.x >> 4;
    const int m0 = blockIdx.x * 64;
    const int n0 = blockIdx.y * 64;

    float c[4][4];
#pragma unroll
    for (int i = 0; i < 4; i++)
#pragma unroll
        for (int j = 0; j < 4; j++) c[i][j] = 0.f;

    for (int k0 = 0; k0 < 128; k0 += 16) {
#pragma unroll
        for (int i = 0; i < 4; i++) {
            int lin = threadIdx.x + 256 * i;
            int m = lin >> 4, kk = lin & 15;
            As[kk][m] = g_ctx[(size_t)(m0 + m) * 128 + k0 + kk];
        }
#pragma unroll
        for (int i = 0; i < 4; i++) {
            int lin = threadIdx.x + 256 * i;
            int kk = lin >> 6, n = lin & 63;
            Ws[kk][n] = W[(size_t)(k0 + kk) * 128 + n0 + n];
        }
        __syncthreads();
#pragma unroll
        for (int kk = 0; kk < 16; kk++) {
            float4 a = *(const float4*)&As[kk][4 * ty];
            float4 b = *(const float4*)&Ws[kk][4 * tx];
            const float av[4] = {a.x, a.y, a.z, a.w};
            const float bv[4] = {b.x, b.y, b.z, b.w};
#pragma unroll
            for (int i = 0; i < 4; i++)
#pragma unroll
                for (int j = 0; j < 4; j++) c[i][j] = fmaf(av[i], bv[j], c[i][j]);
        }
        __syncthreads();
    }

#pragma unroll
    for (int i = 0; i < 4; i++) {
        const int m = m0 + 4 * ty + i;
#pragma unroll
        for (int j = 0; j < 4; j++) {
            const int n = n0 + 4 * tx + j;
            out[(size_t)m * 128 + n] = c[i][j];
        }
    }
}

// ---------------- launch ----------------------------------------------------
extern "C" void kernel_launch(void* const* d_in, const int* in_sizes, int n_in,
                              void* d_out, int out_size) {
    const float* x    = (const float*)d_in[0];
    const float* pk   = (const float*)d_in[1];
    const float* pv   = (const float*)d_in[2];
    const float* Wqkv = (const float*)d_in[3];
    const float* Wout = (const float*)d_in[4];
    float* out = (float*)d_out;

    {
        int n4 = B_ * H_ * P_ * HD / 4;
        prefix_copy<<<(n4 + 255) / 256, 256>>>((const float4*)pk, (const float4*)pv);
    }
    {
        dim3 grid(8192 / 64, 384 / 64);
        gemm_qkv<<<grid, 256>>>(x, Wqkv);
    }
    {
        attn_tc<<<512, 64>>>();
    }
    {
        dim3 grid(8192 / 64, 128 / 64);
        gemm_out<<<grid, 256>>>(Wout, out);
    }
}

// round 4
// speedup vs baseline: 2.9697x; 1.0280x over previous
#include <cuda_runtime.h>
#include <cstdint>

// Problem constants
#define B_ 2
#define T_ 4096
#define H_ 4
#define HD 32
#define P_ 2048
#define TK 6144           // P_ + T_
#define DM 128            // D_MODEL
#define RSQRT_HD 0.17677669529663687f

// ---------------- scratch (device globals; no allocation allowed) ------------
// g_q/g_k/g_v hold tf32 bit patterns (as float); g_q pre-scaled by 1/sqrt(hd)
__device__ float g_q[(size_t)B_ * H_ * T_ * HD];
__device__ float g_k[(size_t)B_ * H_ * TK * HD];
__device__ float g_v[(size_t)B_ * H_ * TK * HD];
__device__ float g_ctx[(size_t)B_ * T_ * DM];         // [B][T][128] head-interleaved

// ---------------- tf32 mma helpers ------------------------------------------
__device__ __forceinline__ uint32_t f2tf(float f) {
    uint32_t r;
    asm("cvt.rna.tf32.f32 %0, %1;" : "=r"(r) : "f"(f));
    return r;
}
__device__ __forceinline__ void mma8(float* c, const uint32_t* a, uint32_t b0, uint32_t b1) {
    asm("mma.sync.aligned.m16n8k8.row.col.f32.tf32.tf32.f32 "
        "{%0,%1,%2,%3},{%4,%5,%6,%7},{%8,%9},{%0,%1,%2,%3};"
        : "+f"(c[0]), "+f"(c[1]), "+f"(c[2]), "+f"(c[3])
        : "r"(a[0]), "r"(a[1]), "r"(a[2]), "r"(a[3]), "r"(b0), "r"(b1));
}

// ---------------- GEMM 1: qkv = x @ Wqkv, scatter to g_q/g_k/g_v (tf32) -----
__global__ void __launch_bounds__(256) gemm_qkv(const float* __restrict__ A,
                                                const float* __restrict__ W) {
    __shared__ float As[16][68];
    __shared__ float Ws[16][68];
    const int tx = threadIdx.x & 15;
    const int ty = threadIdx.x >> 4;
    const int m0 = blockIdx.x * 64;
    const int n0 = blockIdx.y * 64;

    float c[4][4];
#pragma unroll
    for (int i = 0; i < 4; i++)
#pragma unroll
        for (int j = 0; j < 4; j++) c[i][j] = 0.f;

    for (int k0 = 0; k0 < 128; k0 += 16) {
#pragma unroll
        for (int i = 0; i < 4; i++) {
            int lin = threadIdx.x + 256 * i;
            int m = lin >> 4, kk = lin & 15;
            As[kk][m] = A[(size_t)(m0 + m) * 128 + k0 + kk];
        }
#pragma unroll
        for (int i = 0; i < 4; i++) {
            int lin = threadIdx.x + 256 * i;
            int kk = lin >> 6, n = lin & 63;
            Ws[kk][n] = W[(size_t)(k0 + kk) * 384 + n0 + n];
        }
        __syncthreads();
#pragma unroll
        for (int kk = 0; kk < 16; kk++) {
            float4 a = *(const float4*)&As[kk][4 * ty];
            float4 b = *(const float4*)&Ws[kk][4 * tx];
            const float av[4] = {a.x, a.y, a.z, a.w};
            const float bv[4] = {b.x, b.y, b.z, b.w};
#pragma unroll
            for (int i = 0; i < 4; i++)
#pragma unroll
                for (int j = 0; j < 4; j++) c[i][j] = fmaf(av[i], bv[j], c[i][j]);
        }
        __syncthreads();
    }

#pragma unroll
    for (int i = 0; i < 4; i++) {
        const int m = m0 + 4 * ty + i;
        const int b = m >> 12;
        const int t = m & (T_ - 1);
#pragma unroll
        for (int j = 0; j < 4; j++) {
            const int n = n0 + 4 * tx + j;
            const int sec = n >> 7;
            const int r = n & 127;
            const int h = r >> 5;
            const int d = r & 31;
            const float val = c[i][j];
            if (sec == 0) {
                g_q[(((size_t)(b * H_ + h) * T_) + t) * HD + d] =
                    __uint_as_float(f2tf(val * RSQRT_HD));
            } else if (sec == 1) {
                g_k[(((size_t)(b * H_ + h) * TK) + P_ + t) * HD + d] =
                    __uint_as_float(f2tf(val));
            } else {
                g_v[(((size_t)(b * H_ + h) * TK) + P_ + t) * HD + d] =
                    __uint_as_float(f2tf(val));
            }
        }
    }
}

// ---------------- prefix copy (convert to tf32) ------------------------------
__global__ void prefix_copy(const float4* __restrict__ pk, const float4* __restrict__ pv) {
    int idx = blockIdx.x * blockDim.x + threadIdx.x;
    if (idx < B_ * H_ * P_ * HD / 4) {
        const int per_bh = P_ * HD / 4;
        int bh = idx / per_bh;
        int rem = idx - bh * per_bh;
        float4 k = pk[idx], v = pv[idx], o;
        o.x = __uint_as_float(f2tf(k.x)); o.y = __uint_as_float(f2tf(k.y));
        o.z = __uint_as_float(f2tf(k.z)); o.w = __uint_as_float(f2tf(k.w));
        ((float4*)g_k)[(size_t)bh * (TK * HD / 4) + rem] = o;
        o.x = __uint_as_float(f2tf(v.x)); o.y = __uint_as_float(f2tf(v.y));
        o.z = __uint_as_float(f2tf(v.z)); o.w = __uint_as_float(f2tf(v.w));
        ((float4*)g_v)[(size_t)bh * (TK * HD / 4) + rem] = o;
    }
}

// ---------------- tensor-core attention -------------------------------------
// 128 threads = 4 warps; q-tile 128 (warp w owns queries q0+32w .. +31).
// Key tiles of 64, tf32 mma m16n8k8. No running max; normalize at end.
__global__ void __launch_bounds__(128) attn_tc() {
    __shared__ float Ks[64][36];          // keys x headdim (tf32 bits)
    __shared__ float Vs[64][40];
    __shared__ float Ps[4][32][36];       // per-warp P half-tile (32q x 32k permuted)

    const int tid = threadIdx.x;
    const int w = tid >> 5;
    const int lane = tid & 31;
    const int g = lane >> 2;              // 0..7
    const int t4 = lane & 3;              // 0..3

    const int bh = blockIdx.x & 7;
    const int idx = blockIdx.x >> 3;      // 0..31
    const int qt = (idx < 19) ? (31 - idx) : (idx - 19);  // heavy+light pairing
    const int q0 = qt * 128;
    const int b = bh >> 2;
    const int h = bh & 3;
    const int wq = q0 + w * 32;           // warp's first query

    // ---- Q fragments (tf32 bits, pre-scaled) ----
    uint32_t qa[2][4][4];
    {
        const uint32_t* qb = (const uint32_t*)(g_q + ((size_t)bh * T_) * HD);
#pragma unroll
        for (int m = 0; m < 2; m++) {
            const int r0 = wq + m * 16 + g;
#pragma unroll
            for (int dc = 0; dc < 4; dc++) {
                qa[m][dc][0] = qb[(size_t)r0 * HD + dc * 8 + t4];
                qa[m][dc][1] = qb[(size_t)(r0 + 8) * HD + dc * 8 + t4];
                qa[m][dc][2] = qb[(size_t)r0 * HD + dc * 8 + t4 + 4];
                qa[m][dc][3] = qb[(size_t)(r0 + 8) * HD + dc * 8 + t4 + 4];
            }
        }
    }

    float O[2][4][4];
#pragma unroll
    for (int m = 0; m < 2; m++)
#pragma unroll
        for (int dc = 0; dc < 4; dc++)
#pragma unroll
            for (int r = 0; r < 4; r++) O[m][dc][r] = 0.f;
    float lsum[2][2] = {{0.f, 0.f}, {0.f, 0.f}};

    const float4* kb = (const float4*)(g_k + (size_t)bh * TK * HD);
    const float4* vb = (const float4*)(g_v + (size_t)bh * TK * HD);
    const int nfull = (P_ + q0) >> 6;     // diag tile for warps 0,1
    const int ntot = nfull + 2;           // diag tile for warps 2,3 is nfull+1

    for (int t = 0; t < ntot; t++) {
        const int j0 = t << 6;
        __syncthreads();
        // ---- load K/V tile (already tf32): 512 float4 each, 128 threads ----
#pragma unroll
        for (int i = 0; i < 4; i++) {
            const int f = tid + (i << 7);          // 0..511
            const int key = f >> 3;
            const int d0 = (f & 7) << 2;
            *(float4*)&Ks[key][d0] = kb[(size_t)j0 * 8 + f];
            *(float4*)&Vs[key][d0] = vb[(size_t)j0 * 8 + f];
        }
        __syncthreads();

        const bool isdiag = (t == nfull + (w >> 1));
        if (t > nfull && (w >> 1) == 0) continue;   // fully-masked tile for warps 0,1

        // ---- S = Q K^T (this warp: 32q x 64k) ----
        float S[2][8][4];
#pragma unroll
        for (int nc = 0; nc < 8; nc++) {
#pragma unroll
            for (int m = 0; m < 2; m++)
#pragma unroll
                for (int r = 0; r < 4; r++) S[m][nc][r] = 0.f;
#pragma unroll
            for (int dc = 0; dc < 4; dc++) {
                const uint32_t b0 = __float_as_uint(Ks[nc * 8 + g][dc * 8 + t4]);
                const uint32_t b1 = __float_as_uint(Ks[nc * 8 + g][dc * 8 + t4 + 4]);
                mma8(S[0][nc], qa[0][dc], b0, b1);
                mma8(S[1][nc], qa[1][dc], b0, b1);
            }
        }

        // ---- softmax (no max-sub) + PV in 32-key halves ----
#pragma unroll
        for (int half = 0; half < 2; half++) {
#pragma unroll
            for (int ncl = 0; ncl < 4; ncl++) {
                const int nc = half * 4 + ncl;
#pragma unroll
                for (int m = 0; m < 2; m++) {
                    const float* s = S[m][nc];
                    float p0, p1, p2, p3;
                    if (isdiag) {
                        const int rbase = 32 * (w & 1) + m * 16 + g;
                        const int col0 = nc * 8 + 2 * t4;
                        p0 = (col0     <= rbase)     ? __expf(s[0]) : 0.f;
                        p1 = (col0 + 1 <= rbase)     ? __expf(s[1]) : 0.f;
                        p2 = (col0     <= rbase + 8) ? __expf(s[2]) : 0.f;
                        p3 = (col0 + 1 <= rbase + 8) ? __expf(s[3]) : 0.f;
                    } else {
                        p0 = __expf(s[0]); p1 = __expf(s[1]);
                        p2 = __expf(s[2]); p3 = __expf(s[3]);
                    }
                    lsum[m][0] += p0 + p1;
                    lsum[m][1] += p2 + p3;
                    const int c0 = 2 * t4, c1 = 2 * t4 + 1;
                    const int pc0 = (c0 & 3) * 8 + ncl * 2 + (c0 >> 2);
                    const int pc1 = (c1 & 3) * 8 + ncl * 2 + (c1 >> 2);
                    const int r0 = m * 16 + g;
                    Ps[w][r0][pc0]     = __uint_as_float(f2tf(p0));
                    Ps[w][r0][pc1]     = __uint_as_float(f2tf(p1));
                    Ps[w][r0 + 8][pc0] = __uint_as_float(f2tf(p2));
                    Ps[w][r0 + 8][pc1] = __uint_as_float(f2tf(p3));
                }
            }
            __syncwarp();
#pragma unroll
            for (int ks = 0; ks < 4; ks++) {
                uint32_t A[2][4];
#pragma unroll
                for (int m = 0; m < 2; m++) {
                    const float2 v0 = *(const float2*)&Ps[w][m * 16 + g][t4 * 8 + ks * 2];
                    const float2 v1 = *(const float2*)&Ps[w][m * 16 + g + 8][t4 * 8 + ks * 2];
                    A[m][0] = __float_as_uint(v0.x);
                    A[m][2] = __float_as_uint(v0.y);
                    A[m][1] = __float_as_uint(v1.x);
                    A[m][3] = __float_as_uint(v1.y);
                }
                const int kk = (half * 4 + ks) * 8;
#pragma unroll
                for (int dc = 0; dc < 4; dc++) {
                    const uint32_t b0 = __float_as_uint(Vs[kk + t4][dc * 8 + g]);
                    const uint32_t b1 = __float_as_uint(Vs[kk + t4 + 4][dc * 8 + g]);
                    mma8(O[0][dc], A[0], b0, b1);
                    mma8(O[1][dc], A[1], b0, b1);
                }
            }
            __syncwarp();
        }
    }

    // ---- epilogue ----
#pragma unroll
    for (int m = 0; m < 2; m++) {
        float l0 = lsum[m][0];
        l0 += __shfl_xor_sync(0xFFFFFFFFu, l0, 1);
        l0 += __shfl_xor_sync(0xFFFFFFFFu, l0, 2);
        float l1 = lsum[m][1];
        l1 += __shfl_xor_sync(0xFFFFFFFFu, l1, 1);
        l1 += __shfl_xor_sync(0xFFFFFFFFu, l1, 2);
        const float inv0 = 1.f / l0;
        const float inv1 = 1.f / l1;
        const int r0 = wq + m * 16 + g;
        float* o0 = g_ctx + ((size_t)b * T_ + r0) * DM + h * HD;
        float* o1 = g_ctx + ((size_t)b * T_ + r0 + 8) * DM + h * HD;
#pragma unroll
        for (int dc = 0; dc < 4; dc++) {
            const int col = dc * 8 + 2 * t4;
            *(float2*)&o0[col] = make_float2(O[m][dc][0] * inv0, O[m][dc][1] * inv0);
            *(float2*)&o1[col] = make_float2(O[m][dc][2] * inv1, O[m][dc][3] * inv1);
        }
    }
}

// ---------------- GEMM 2: out = g_ctx @ Wout --------------------------------
__global__ void __launch_bounds__(256) gemm_out(const float* __restrict__ W,
                                               float* __restrict__ out) {
    __shared__ float As[16][68];
    __shared__ float Ws[16][68];
    const int tx = threadIdx.x & 15;
    const int ty = threadIdx.x >> 4;
    const int m0 = blockIdx.x * 64;
    const int n0 = blockIdx.y * 64;

    float c[4][4];
#pragma unroll
    for (int i = 0; i < 4; i++)
#pragma unroll
        for (int j = 0; j < 4; j++) c[i][j] = 0.f;

    for (int k0 = 0; k0 < 128; k0 += 16) {
#pragma unroll
        for (int i = 0; i < 4; i++) {
            int lin = threadIdx.x + 256 * i;
            int m = lin >> 4, kk = lin & 15;
            As[kk][m] = g_ctx[(size_t)(m0 + m) * 128 + k0 + kk];
        }
#pragma unroll
        for (int i = 0; i < 4; i++) {
            int lin = threadIdx.x + 256 * i;
            int kk = lin >> 6, n = lin & 63;
            Ws[kk][n] = W[(size_t)(k0 + kk) * 128 + n0 + n];
        }
        __syncthreads();
#pragma unroll
        for (int kk = 0; kk < 16; kk++) {
            float4 a = *(const float4*)&As[kk][4 * ty];
            float4 b = *(const float4*)&Ws[kk][4 * tx];
            const float av[4] = {a.x, a.y, a.z, a.w};
            const float bv[4] = {b.x, b.y, b.z, b.w};
#pragma unroll
            for (int i = 0; i < 4; i++)
#pragma unroll
                for (int j = 0; j < 4; j++) c[i][j] = fmaf(av[i], bv[j], c[i][j]);
        }
        __syncthreads();
    }

#pragma unroll
    for (int i = 0; i < 4; i++) {
        const int m = m0 + 4 * ty + i;
#pragma unroll
        for (int j = 0; j < 4; j++) {
            const int n = n0 + 4 * tx + j;
            out[(size_t)m * 128 + n] = c[i][j];
        }
    }
}

// ---------------- launch ----------------------------------------------------
extern "C" void kernel_launch(void* const* d_in, const int* in_sizes, int n_in,
                              void* d_out, int out_size) {
    const float* x    = (const float*)d_in[0];
    const float* pk   = (const float*)d_in[1];
    const float* pv   = (const float*)d_in[2];
    const float* Wqkv = (const float*)d_in[3];
    const float* Wout = (const float*)d_in[4];
    float* out = (float*)d_out;

    {
        int n4 = B_ * H_ * P_ * HD / 4;
        prefix_copy<<<(n4 + 255) / 256, 256>>>((const float4*)pk, (const float4*)pv);
    }
    {
        dim3 grid(8192 / 64, 384 / 64);
        gemm_qkv<<<grid, 256>>>(x, Wqkv);
    }
    {
        attn_tc<<<256, 128>>>();
    }
    {
        dim3 grid(8192 / 64, 128 / 64);
        gemm_out<<<grid, 256>>>(Wout, out);
    }
}

// round 5
// speedup vs baseline: 3.6414x; 1.2262x over previous
#include <cuda_runtime.h>
#include <cstdint>

// Problem constants
#define B_ 2
#define T_ 4096
#define H_ 4
#define HD 32
#define P_ 2048
#define TK 6144           // P_ + T_
#define DM 128            // D_MODEL
#define KS 4              // key splits
#define RSQRT_HD 0.17677669529663687f

// ---------------- scratch (device globals; no allocation allowed) ------------
// g_q/g_k/g_v hold tf32 bit patterns (as float); g_q pre-scaled by 1/sqrt(hd)
__device__ float g_q[(size_t)B_ * H_ * T_ * HD];
__device__ float g_k[(size_t)B_ * H_ * TK * HD];
__device__ float g_v[(size_t)B_ * H_ * TK * HD];
__device__ float g_ctx[(size_t)B_ * T_ * DM];             // [B][T][128]
__device__ float g_pacc[(size_t)KS * B_ * H_ * T_ * HD];  // partial numerators
__device__ float g_pl[(size_t)KS * B_ * H_ * T_];         // partial denominators

// ---------------- tf32 mma helpers ------------------------------------------
__device__ __forceinline__ uint32_t f2tf(float f) {
    uint32_t r;
    asm("cvt.rna.tf32.f32 %0, %1;" : "=r"(r) : "f"(f));
    return r;
}
__device__ __forceinline__ void mma8(float* c, const uint32_t* a, uint32_t b0, uint32_t b1) {
    asm("mma.sync.aligned.m16n8k8.row.col.f32.tf32.tf32.f32 "
        "{%0,%1,%2,%3},{%4,%5,%6,%7},{%8,%9},{%0,%1,%2,%3};"
        : "+f"(c[0]), "+f"(c[1]), "+f"(c[2]), "+f"(c[3])
        : "r"(a[0]), "r"(a[1]), "r"(a[2]), "r"(a[3]), "r"(b0), "r"(b1));
}

// ---------------- GEMM 1: qkv = x @ Wqkv, scatter (tf32) --------------------
__global__ void __launch_bounds__(256) gemm_qkv(const float* __restrict__ A,
                                                const float* __restrict__ W) {
    __shared__ float As[16][68];
    __shared__ float Ws[16][68];
    const int tx = threadIdx.x & 15;
    const int ty = threadIdx.x >> 4;
    const int m0 = blockIdx.x * 64;
    const int n0 = blockIdx.y * 64;

    float c[4][4];
#pragma unroll
    for (int i = 0; i < 4; i++)
#pragma unroll
        for (int j = 0; j < 4; j++) c[i][j] = 0.f;

    for (int k0 = 0; k0 < 128; k0 += 16) {
#pragma unroll
        for (int i = 0; i < 4; i++) {
            int lin = threadIdx.x + 256 * i;
            int m = lin >> 4, kk = lin & 15;
            As[kk][m] = A[(size_t)(m0 + m) * 128 + k0 + kk];
        }
#pragma unroll
        for (int i = 0; i < 4; i++) {
            int lin = threadIdx.x + 256 * i;
            int kk = lin >> 6, n = lin & 63;
            Ws[kk][n] = W[(size_t)(k0 + kk) * 384 + n0 + n];
        }
        __syncthreads();
#pragma unroll
        for (int kk = 0; kk < 16; kk++) {
            float4 a = *(const float4*)&As[kk][4 * ty];
            float4 b = *(const float4*)&Ws[kk][4 * tx];
            const float av[4] = {a.x, a.y, a.z, a.w};
            const float bv[4] = {b.x, b.y, b.z, b.w};
#pragma unroll
            for (int i = 0; i < 4; i++)
#pragma unroll
                for (int j = 0; j < 4; j++) c[i][j] = fmaf(av[i], bv[j], c[i][j]);
        }
        __syncthreads();
    }

#pragma unroll
    for (int i = 0; i < 4; i++) {
        const int m = m0 + 4 * ty + i;
        const int b = m >> 12;
        const int t = m & (T_ - 1);
#pragma unroll
        for (int j = 0; j < 4; j++) {
            const int n = n0 + 4 * tx + j;
            const int sec = n >> 7;
            const int r = n & 127;
            const int h = r >> 5;
            const int d = r & 31;
            const float val = c[i][j];
            if (sec == 0) {
                g_q[(((size_t)(b * H_ + h) * T_) + t) * HD + d] =
                    __uint_as_float(f2tf(val * RSQRT_HD));
            } else if (sec == 1) {
                g_k[(((size_t)(b * H_ + h) * TK) + P_ + t) * HD + d] =
                    __uint_as_float(f2tf(val));
            } else {
                g_v[(((size_t)(b * H_ + h) * TK) + P_ + t) * HD + d] =
                    __uint_as_float(f2tf(val));
            }
        }
    }
}

// ---------------- prefix copy (convert to tf32) ------------------------------
__global__ void prefix_copy(const float4* __restrict__ pk, const float4* __restrict__ pv) {
    int idx = blockIdx.x * blockDim.x + threadIdx.x;
    if (idx < B_ * H_ * P_ * HD / 4) {
        const int per_bh = P_ * HD / 4;
        int bh = idx / per_bh;
        int rem = idx - bh * per_bh;
        float4 k = pk[idx], v = pv[idx], o;
        o.x = __uint_as_float(f2tf(k.x)); o.y = __uint_as_float(f2tf(k.y));
        o.z = __uint_as_float(f2tf(k.z)); o.w = __uint_as_float(f2tf(k.w));
        ((float4*)g_k)[(size_t)bh * (TK * HD / 4) + rem] = o;
        o.x = __uint_as_float(f2tf(v.x)); o.y = __uint_as_float(f2tf(v.y));
        o.z = __uint_as_float(f2tf(v.z)); o.w = __uint_as_float(f2tf(v.w));
        ((float4*)g_v)[(size_t)bh * (TK * HD / 4) + rem] = o;
    }
}

// ---------------- tensor-core attention, split-K -----------------------------
// 128 threads = 4 warps; q-tile 128 (warp w owns 32 queries).
// grid = (32 q-tiles, KS splits, 8 bh). Key tiles of 64, tf32 mma.
// No running max; partials combine additively in attn_combine.
__global__ void __launch_bounds__(128) attn_tc() {
    __shared__ float Ks[64][36];
    __shared__ float Vs[64][40];
    __shared__ float Ps[4][32][36];

    const int tid = threadIdx.x;
    const int w = tid >> 5;
    const int lane = tid & 31;
    const int g = lane >> 2;
    const int t4 = lane & 3;

    const int qt = 31 - blockIdx.x;      // heavy q-tiles first
    const int split = blockIdx.y;
    const int bh = blockIdx.z;
    const int q0 = qt * 128;
    const int wq = q0 + w * 32;

    // ---- Q fragments (tf32 bits, pre-scaled) ----
    uint32_t qa[2][4][4];
    {
        const uint32_t* qb = (const uint32_t*)(g_q + ((size_t)bh * T_) * HD);
#pragma unroll
        for (int m = 0; m < 2; m++) {
            const int r0 = wq + m * 16 + g;
#pragma unroll
            for (int dc = 0; dc < 4; dc++) {
                qa[m][dc][0] = qb[(size_t)r0 * HD + dc * 8 + t4];
                qa[m][dc][1] = qb[(size_t)(r0 + 8) * HD + dc * 8 + t4];
                qa[m][dc][2] = qb[(size_t)r0 * HD + dc * 8 + t4 + 4];
                qa[m][dc][3] = qb[(size_t)(r0 + 8) * HD + dc * 8 + t4 + 4];
            }
        }
    }

    float O[2][4][4];
#pragma unroll
    for (int m = 0; m < 2; m++)
#pragma unroll
        for (int dc = 0; dc < 4; dc++)
#pragma unroll
            for (int r = 0; r < 4; r++) O[m][dc][r] = 0.f;
    float lsum[2][2] = {{0.f, 0.f}, {0.f, 0.f}};

    const float4* kb = (const float4*)(g_k + (size_t)bh * TK * HD);
    const float4* vb = (const float4*)(g_v + (size_t)bh * TK * HD);
    const int nfull = (P_ + q0) >> 6;     // diag tile for warps 0,1
    const int ntot = nfull + 2;           // diag tile for warps 2,3 is nfull+1
    const int t_begin = (ntot * split) / KS;
    const int t_end = (ntot * (split + 1)) / KS;

    for (int t = t_begin; t < t_end; t++) {
        const int j0 = t << 6;
        __syncthreads();
#pragma unroll
        for (int i = 0; i < 4; i++) {
            const int f = tid + (i << 7);
            const int key = f >> 3;
            const int d0 = (f & 7) << 2;
            *(float4*)&Ks[key][d0] = kb[(size_t)j0 * 8 + f];
            *(float4*)&Vs[key][d0] = vb[(size_t)j0 * 8 + f];
        }
        __syncthreads();

        const bool isdiag = (t == nfull + (w >> 1));
        if (t > nfull && (w >> 1) == 0) continue;   // fully masked for warps 0,1

        // ---- S = Q K^T ----
        float S[2][8][4];
#pragma unroll
        for (int nc = 0; nc < 8; nc++) {
#pragma unroll
            for (int m = 0; m < 2; m++)
#pragma unroll
                for (int r = 0; r < 4; r++) S[m][nc][r] = 0.f;
#pragma unroll
            for (int dc = 0; dc < 4; dc++) {
                const uint32_t b0 = __float_as_uint(Ks[nc * 8 + g][dc * 8 + t4]);
                const uint32_t b1 = __float_as_uint(Ks[nc * 8 + g][dc * 8 + t4 + 4]);
                mma8(S[0][nc], qa[0][dc], b0, b1);
                mma8(S[1][nc], qa[1][dc], b0, b1);
            }
        }

        // ---- softmax (no max-sub) + PV in 32-key halves ----
#pragma unroll
        for (int half = 0; half < 2; half++) {
#pragma unroll
            for (int ncl = 0; ncl < 4; ncl++) {
                const int nc = half * 4 + ncl;
#pragma unroll
                for (int m = 0; m < 2; m++) {
                    const float* s = S[m][nc];
                    float p0, p1, p2, p3;
                    if (isdiag) {
                        const int rbase = 32 * (w & 1) + m * 16 + g;
                        const int col0 = nc * 8 + 2 * t4;
                        p0 = (col0     <= rbase)     ? __expf(s[0]) : 0.f;
                        p1 = (col0 + 1 <= rbase)     ? __expf(s[1]) : 0.f;
                        p2 = (col0     <= rbase + 8) ? __expf(s[2]) : 0.f;
                        p3 = (col0 + 1 <= rbase + 8) ? __expf(s[3]) : 0.f;
                    } else {
                        p0 = __expf(s[0]); p1 = __expf(s[1]);
                        p2 = __expf(s[2]); p3 = __expf(s[3]);
                    }
                    lsum[m][0] += p0 + p1;
                    lsum[m][1] += p2 + p3;
                    const int c0 = 2 * t4, c1 = 2 * t4 + 1;
                    const int pc0 = (c0 & 3) * 8 + ncl * 2 + (c0 >> 2);
                    const int pc1 = (c1 & 3) * 8 + ncl * 2 + (c1 >> 2);
                    const int r0 = m * 16 + g;
                    Ps[w][r0][pc0]     = __uint_as_float(f2tf(p0));
                    Ps[w][r0][pc1]     = __uint_as_float(f2tf(p1));
                    Ps[w][r0 + 8][pc0] = __uint_as_float(f2tf(p2));
                    Ps[w][r0 + 8][pc1] = __uint_as_float(f2tf(p3));
                }
            }
            __syncwarp();
#pragma unroll
            for (int ks = 0; ks < 4; ks++) {
                uint32_t A[2][4];
#pragma unroll
                for (int m = 0; m < 2; m++) {
                    const float2 v0 = *(const float2*)&Ps[w][m * 16 + g][t4 * 8 + ks * 2];
                    const float2 v1 = *(const float2*)&Ps[w][m * 16 + g + 8][t4 * 8 + ks * 2];
                    A[m][0] = __float_as_uint(v0.x);
                    A[m][2] = __float_as_uint(v0.y);
                    A[m][1] = __float_as_uint(v1.x);
                    A[m][3] = __float_as_uint(v1.y);
                }
                const int kk = (half * 4 + ks) * 8;
#pragma unroll
                for (int dc = 0; dc < 4; dc++) {
                    const uint32_t b0 = __float_as_uint(Vs[kk + t4][dc * 8 + g]);
                    const uint32_t b1 = __float_as_uint(Vs[kk + t4 + 4][dc * 8 + g]);
                    mma8(O[0][dc], A[0], b0, b1);
                    mma8(O[1][dc], A[1], b0, b1);
                }
            }
            __syncwarp();
        }
    }

    // ---- store partials (unnormalized) ----
    const size_t pbase = ((size_t)split * (B_ * H_) + bh) * T_;
#pragma unroll
    for (int m = 0; m < 2; m++) {
        float l0 = lsum[m][0];
        l0 += __shfl_xor_sync(0xFFFFFFFFu, l0, 1);
        l0 += __shfl_xor_sync(0xFFFFFFFFu, l0, 2);
        float l1 = lsum[m][1];
        l1 += __shfl_xor_sync(0xFFFFFFFFu, l1, 1);
        l1 += __shfl_xor_sync(0xFFFFFFFFu, l1, 2);
        const int r0 = wq + m * 16 + g;
        if (t4 == 0) {
            g_pl[pbase + r0] = l0;
            g_pl[pbase + r0 + 8] = l1;
        }
        float* p0 = g_pacc + (pbase + r0) * HD;
        float* p1 = g_pacc + (pbase + r0 + 8) * HD;
#pragma unroll
        for (int dc = 0; dc < 4; dc++) {
            const int col = dc * 8 + 2 * t4;
            *(float2*)&p0[col] = make_float2(O[m][dc][0], O[m][dc][1]);
            *(float2*)&p1[col] = make_float2(O[m][dc][2], O[m][dc][3]);
        }
    }
}

// ---------------- combine splits -> g_ctx ------------------------------------
// One thread per float4 of one query's output: 8 bh * 4096 q * 8 f4 = 262144.
__global__ void __launch_bounds__(256) attn_combine() {
    const int idx = blockIdx.x * 256 + threadIdx.x;
    const int q_lin = idx >> 3;          // bh*T_ + qi
    const int f = idx & 7;               // which float4 of 8
    const int bh = q_lin >> 12;
    const int qi = q_lin & (T_ - 1);
    const int b = bh >> 2;
    const int h = bh & 3;

    float l = 0.f;
    float4 acc = make_float4(0.f, 0.f, 0.f, 0.f);
#pragma unroll
    for (int s = 0; s < KS; s++) {
        const size_t pb = ((size_t)s * (B_ * H_) + bh) * T_;
        l += g_pl[pb + qi];
        const float4 v = *(const float4*)(g_pacc + (pb + qi) * HD + f * 4);
        acc.x += v.x; acc.y += v.y; acc.z += v.z; acc.w += v.w;
    }
    const float inv = 1.f / l;
    float* op = g_ctx + ((size_t)b * T_ + qi) * DM + h * HD + f * 4;
    *(float4*)op = make_float4(acc.x * inv, acc.y * inv, acc.z * inv, acc.w * inv);
}

// ---------------- GEMM 2: out = g_ctx @ Wout --------------------------------
__global__ void __launch_bounds__(256) gemm_out(const float* __restrict__ W,
                                               float* __restrict__ out) {
    __shared__ float As[16][68];
    __shared__ float Ws[16][68];
    const int tx = threadIdx.x & 15;
    const int ty = threadIdx.x >> 4;
    const int m0 = blockIdx.x * 64;
    const int n0 = blockIdx.y * 64;

    float c[4][4];
#pragma unroll
    for (int i = 0; i < 4; i++)
#pragma unroll
        for (int j = 0; j < 4; j++) c[i][j] = 0.f;

    for (int k0 = 0; k0 < 128; k0 += 16) {
#pragma unroll
        for (int i = 0; i < 4; i++) {
            int lin = threadIdx.x + 256 * i;
            int m = lin >> 4, kk = lin & 15;
            As[kk][m] = g_ctx[(size_t)(m0 + m) * 128 + k0 + kk];
        }
#pragma unroll
        for (int i = 0; i < 4; i++) {
            int lin = threadIdx.x + 256 * i;
            int kk = lin >> 6, n = lin & 63;
            Ws[kk][n] = W[(size_t)(k0 + kk) * 128 + n0 + n];
        }
        __syncthreads();
#pragma unroll
        for (int kk = 0; kk < 16; kk++) {
            float4 a = *(const float4*)&As[kk][4 * ty];
            float4 b = *(const float4*)&Ws[kk][4 * tx];
            const float av[4] = {a.x, a.y, a.z, a.w};
            const float bv[4] = {b.x, b.y, b.z, b.w};
#pragma unroll
            for (int i = 0; i < 4; i++)
#pragma unroll
                for (int j = 0; j < 4; j++) c[i][j] = fmaf(av[i], bv[j], c[i][j]);
        }
        __syncthreads();
    }

#pragma unroll
    for (int i = 0; i < 4; i++) {
        const int m = m0 + 4 * ty + i;
#pragma unroll
        for (int j = 0; j < 4; j++) {
            const int n = n0 + 4 * tx + j;
            out[(size_t)m * 128 + n] = c[i][j];
        }
    }
}

// ---------------- launch ----------------------------------------------------
extern "C" void kernel_launch(void* const* d_in, const int* in_sizes, int n_in,
                              void* d_out, int out_size) {
    const float* x    = (const float*)d_in[0];
    const float* pk   = (const float*)d_in[1];
    const float* pv   = (const float*)d_in[2];
    const float* Wqkv = (const float*)d_in[3];
    const float* Wout = (const float*)d_in[4];
    float* out = (float*)d_out;

    {
        int n4 = B_ * H_ * P_ * HD / 4;
        prefix_copy<<<(n4 + 255) / 256, 256>>>((const float4*)pk, (const float4*)pv);
    }
    {
        dim3 grid(8192 / 64, 384 / 64);
        gemm_qkv<<<grid, 256>>>(x, Wqkv);
    }
    {
        dim3 grid(32, KS, B_ * H_);
        attn_tc<<<grid, 128>>>();
    }
    {
        attn_combine<<<(B_ * H_ * T_ * 8) / 256, 256>>>();
    }
    {
        dim3 grid(8192 / 64, 128 / 64);
        gemm_out<<<grid, 256>>>(Wout, out);
    }
}

// round 6
// speedup vs baseline: 4.4163x; 1.2128x over previous
#include <cuda_runtime.h>
#include <cstdint>

// Problem constants
#define B_ 2
#define T_ 4096
#define H_ 4
#define HD 32
#define P_ 2048
#define TK 6144           // P_ + T_
#define DM 128            // D_MODEL
#define KS 4              // key splits
#define RSQRT_HD 0.17677669529663687f

// ---------------- scratch (device globals; no allocation allowed) ------------
// g_q/g_k/g_v hold tf32 bit patterns (as float); g_q pre-scaled by 1/sqrt(hd)
__device__ float g_q[(size_t)B_ * H_ * T_ * HD];
__device__ float g_k[(size_t)B_ * H_ * TK * HD];
__device__ float g_v[(size_t)B_ * H_ * TK * HD];
__device__ float g_ctx[(size_t)B_ * T_ * DM];             // [B][T][128]
__device__ float g_pacc[(size_t)KS * B_ * H_ * T_ * HD];  // partial numerators
__device__ float g_pl[(size_t)KS * B_ * H_ * T_];         // partial denominators

// ---------------- tf32 mma helpers ------------------------------------------
__device__ __forceinline__ uint32_t f2tf(float f) {
    uint32_t r;
    asm("cvt.rna.tf32.f32 %0, %1;" : "=r"(r) : "f"(f));
    return r;
}
__device__ __forceinline__ void mma8(float* c, const uint32_t* a, uint32_t b0, uint32_t b1) {
    asm("mma.sync.aligned.m16n8k8.row.col.f32.tf32.tf32.f32 "
        "{%0,%1,%2,%3},{%4,%5,%6,%7},{%8,%9},{%0,%1,%2,%3};"
        : "+f"(c[0]), "+f"(c[1]), "+f"(c[2]), "+f"(c[3])
        : "r"(a[0]), "r"(a[1]), "r"(a[2]), "r"(a[3]), "r"(b0), "r"(b1));
}

// ---------------- GEMM 1: qkv = x @ Wqkv, scatter (tf32) --------------------
__global__ void __launch_bounds__(256) gemm_qkv(const float* __restrict__ A,
                                                const float* __restrict__ W) {
    __shared__ float As[16][68];
    __shared__ float Ws[16][68];
    const int tx = threadIdx.x & 15;
    const int ty = threadIdx.x >> 4;
    const int m0 = blockIdx.x * 64;
    const int n0 = blockIdx.y * 64;

    float c[4][4];
#pragma unroll
    for (int i = 0; i < 4; i++)
#pragma unroll
        for (int j = 0; j < 4; j++) c[i][j] = 0.f;

    for (int k0 = 0; k0 < 128; k0 += 16) {
#pragma unroll
        for (int i = 0; i < 4; i++) {
            int lin = threadIdx.x + 256 * i;
            int m = lin >> 4, kk = lin & 15;
            As[kk][m] = A[(size_t)(m0 + m) * 128 + k0 + kk];
        }
#pragma unroll
        for (int i = 0; i < 4; i++) {
            int lin = threadIdx.x + 256 * i;
            int kk = lin >> 6, n = lin & 63;
            Ws[kk][n] = W[(size_t)(k0 + kk) * 384 + n0 + n];
        }
        __syncthreads();
#pragma unroll
        for (int kk = 0; kk < 16; kk++) {
            float4 a = *(const float4*)&As[kk][4 * ty];
            float4 b = *(const float4*)&Ws[kk][4 * tx];
            const float av[4] = {a.x, a.y, a.z, a.w};
            const float bv[4] = {b.x, b.y, b.z, b.w};
#pragma unroll
            for (int i = 0; i < 4; i++)
#pragma unroll
                for (int j = 0; j < 4; j++) c[i][j] = fmaf(av[i], bv[j], c[i][j]);
        }
        __syncthreads();
    }

#pragma unroll
    for (int i = 0; i < 4; i++) {
        const int m = m0 + 4 * ty + i;
        const int b = m >> 12;
        const int t = m & (T_ - 1);
#pragma unroll
        for (int j = 0; j < 4; j++) {
            const int n = n0 + 4 * tx + j;
            const int sec = n >> 7;
            const int r = n & 127;
            const int h = r >> 5;
            const int d = r & 31;
            const float val = c[i][j];
            if (sec == 0) {
                g_q[(((size_t)(b * H_ + h) * T_) + t) * HD + d] =
                    __uint_as_float(f2tf(val * RSQRT_HD));
            } else if (sec == 1) {
                g_k[(((size_t)(b * H_ + h) * TK) + P_ + t) * HD + d] =
                    __uint_as_float(f2tf(val));
            } else {
                g_v[(((size_t)(b * H_ + h) * TK) + P_ + t) * HD + d] =
                    __uint_as_float(f2tf(val));
            }
        }
    }
}

// ---------------- prefix copy (convert to tf32) ------------------------------
__global__ void prefix_copy(const float4* __restrict__ pk, const float4* __restrict__ pv) {
    int idx = blockIdx.x * blockDim.x + threadIdx.x;
    if (idx < B_ * H_ * P_ * HD / 4) {
        const int per_bh = P_ * HD / 4;
        int bh = idx / per_bh;
        int rem = idx - bh * per_bh;
        float4 k = pk[idx], v = pv[idx], o;
        o.x = __uint_as_float(f2tf(k.x)); o.y = __uint_as_float(f2tf(k.y));
        o.z = __uint_as_float(f2tf(k.z)); o.w = __uint_as_float(f2tf(k.w));
        ((float4*)g_k)[(size_t)bh * (TK * HD / 4) + rem] = o;
        o.x = __uint_as_float(f2tf(v.x)); o.y = __uint_as_float(f2tf(v.y));
        o.z = __uint_as_float(f2tf(v.z)); o.w = __uint_as_float(f2tf(v.w));
        ((float4*)g_v)[(size_t)bh * (TK * HD / 4) + rem] = o;
    }
}

// ---------------- tensor-core attention, split-K, register-transpose --------
// 128 threads = 4 warps; q-tile 128 (warp w owns 32 queries).
// grid = (32 q-tiles, KS splits, 8 bh). Key tiles of 64, tf32 mma.
// P never touches smem: S C-fragments -> exp -> quad shuffles -> PV A-frags.
__global__ void __launch_bounds__(128) attn_tc() {
    __shared__ float Ks[64][36];
    __shared__ float Vs[64][40];

    const int tid = threadIdx.x;
    const int w = tid >> 5;
    const int lane = tid & 31;
    const int g = lane >> 2;
    const int t4 = lane & 3;
    const int quad = lane & ~3;
    const int srcA = quad | (t4 >> 1);          // owner of col t4
    const int srcB = quad | ((t4 >> 1) + 2);    // owner of col t4+4
    const bool odd = (t4 & 1);

    const int qt = 31 - blockIdx.x;      // heavy q-tiles first
    const int split = blockIdx.y;
    const int bh = blockIdx.z;
    const int q0 = qt * 128;
    const int wq = q0 + w * 32;

    // ---- Q fragments (tf32 bits, pre-scaled) ----
    uint32_t qa[2][4][4];
    {
        const uint32_t* qb = (const uint32_t*)(g_q + ((size_t)bh * T_) * HD);
#pragma unroll
        for (int m = 0; m < 2; m++) {
            const int r0 = wq + m * 16 + g;
#pragma unroll
            for (int dc = 0; dc < 4; dc++) {
                qa[m][dc][0] = qb[(size_t)r0 * HD + dc * 8 + t4];
                qa[m][dc][1] = qb[(size_t)(r0 + 8) * HD + dc * 8 + t4];
                qa[m][dc][2] = qb[(size_t)r0 * HD + dc * 8 + t4 + 4];
                qa[m][dc][3] = qb[(size_t)(r0 + 8) * HD + dc * 8 + t4 + 4];
            }
        }
    }

    float O[2][4][4];
#pragma unroll
    for (int m = 0; m < 2; m++)
#pragma unroll
        for (int dc = 0; dc < 4; dc++)
#pragma unroll
            for (int r = 0; r < 4; r++) O[m][dc][r] = 0.f;
    float lsum[2][2] = {{0.f, 0.f}, {0.f, 0.f}};

    const float4* kb = (const float4*)(g_k + (size_t)bh * TK * HD);
    const float4* vb = (const float4*)(g_v + (size_t)bh * TK * HD);
    const int nfull = (P_ + q0) >> 6;     // diag tile for warps 0,1
    const int ntot = nfull + 2;           // diag tile for warps 2,3 is nfull+1
    const int t_begin = (ntot * split) / KS;
    const int t_end = (ntot * (split + 1)) / KS;

    for (int t = t_begin; t < t_end; t++) {
        const int j0 = t << 6;
        __syncthreads();
#pragma unroll
        for (int i = 0; i < 4; i++) {
            const int f = tid + (i << 7);
            const int key = f >> 3;
            const int d0 = (f & 7) << 2;
            *(float4*)&Ks[key][d0] = kb[(size_t)j0 * 8 + f];
            *(float4*)&Vs[key][d0] = vb[(size_t)j0 * 8 + f];
        }
        __syncthreads();

        const bool isdiag = (t == nfull + (w >> 1));
        if (t > nfull && (w >> 1) == 0) continue;   // fully masked for warps 0,1

        // ---- per 8-key chunk: S-mma -> exp/mask -> shuffle -> PV-mma ----
#pragma unroll
        for (int nc = 0; nc < 8; nc++) {
            float S[2][4];
#pragma unroll
            for (int m = 0; m < 2; m++)
#pragma unroll
                for (int r = 0; r < 4; r++) S[m][r] = 0.f;
#pragma unroll
            for (int dc = 0; dc < 4; dc++) {
                const uint32_t b0 = __float_as_uint(Ks[nc * 8 + g][dc * 8 + t4]);
                const uint32_t b1 = __float_as_uint(Ks[nc * 8 + g][dc * 8 + t4 + 4]);
                mma8(S[0], qa[0][dc], b0, b1);
                mma8(S[1], qa[1][dc], b0, b1);
            }

            float P[2][4];
#pragma unroll
            for (int m = 0; m < 2; m++) {
                if (isdiag) {
                    const int rbase = 32 * (w & 1) + m * 16 + g;
                    const int col0 = nc * 8 + 2 * t4;
                    P[m][0] = (col0     <= rbase)     ? __expf(S[m][0]) : 0.f;
                    P[m][1] = (col0 + 1 <= rbase)     ? __expf(S[m][1]) : 0.f;
                    P[m][2] = (col0     <= rbase + 8) ? __expf(S[m][2]) : 0.f;
                    P[m][3] = (col0 + 1 <= rbase + 8) ? __expf(S[m][3]) : 0.f;
                } else {
                    P[m][0] = __expf(S[m][0]); P[m][1] = __expf(S[m][1]);
                    P[m][2] = __expf(S[m][2]); P[m][3] = __expf(S[m][3]);
                }
                lsum[m][0] += P[m][0] + P[m][1];
                lsum[m][1] += P[m][2] + P[m][3];
            }

            // quad-shuffle C-frag (cols 2t4,2t4+1) -> A-frag (cols t4,t4+4)
            uint32_t A[2][4];
#pragma unroll
            for (int m = 0; m < 2; m++) {
                const float e0a = __shfl_sync(0xFFFFFFFFu, P[m][0], srcA);
                const float e1a = __shfl_sync(0xFFFFFFFFu, P[m][1], srcA);
                const float e0b = __shfl_sync(0xFFFFFFFFu, P[m][0], srcB);
                const float e1b = __shfl_sync(0xFFFFFFFFu, P[m][1], srcB);
                const float e2a = __shfl_sync(0xFFFFFFFFu, P[m][2], srcA);
                const float e3a = __shfl_sync(0xFFFFFFFFu, P[m][3], srcA);
                const float e2b = __shfl_sync(0xFFFFFFFFu, P[m][2], srcB);
                const float e3b = __shfl_sync(0xFFFFFFFFu, P[m][3], srcB);
                A[m][0] = __float_as_uint(odd ? e1a : e0a);  // P[g][t4]
                A[m][1] = __float_as_uint(odd ? e3a : e2a);  // P[g+8][t4]
                A[m][2] = __float_as_uint(odd ? e1b : e0b);  // P[g][t4+4]
                A[m][3] = __float_as_uint(odd ? e3b : e2b);  // P[g+8][t4+4]
            }

            // PV: O += P[:, nc*8:+8] @ V[nc*8:+8, :]
#pragma unroll
            for (int dc = 0; dc < 4; dc++) {
                const uint32_t b0 = __float_as_uint(Vs[nc * 8 + t4][dc * 8 + g]);
                const uint32_t b1 = __float_as_uint(Vs[nc * 8 + t4 + 4][dc * 8 + g]);
                mma8(O[0][dc], A[0], b0, b1);
                mma8(O[1][dc], A[1], b0, b1);
            }
        }
    }

    // ---- store partials (unnormalized) ----
    const size_t pbase = ((size_t)split * (B_ * H_) + bh) * T_;
#pragma unroll
    for (int m = 0; m < 2; m++) {
        float l0 = lsum[m][0];
        l0 += __shfl_xor_sync(0xFFFFFFFFu, l0, 1);
        l0 += __shfl_xor_sync(0xFFFFFFFFu, l0, 2);
        float l1 = lsum[m][1];
        l1 += __shfl_xor_sync(0xFFFFFFFFu, l1, 1);
        l1 += __shfl_xor_sync(0xFFFFFFFFu, l1, 2);
        const int r0 = wq + m * 16 + g;
        if (t4 == 0) {
            g_pl[pbase + r0] = l0;
            g_pl[pbase + r0 + 8] = l1;
        }
        float* p0 = g_pacc + (pbase + r0) * HD;
        float* p1 = g_pacc + (pbase + r0 + 8) * HD;
#pragma unroll
        for (int dc = 0; dc < 4; dc++) {
            const int col = dc * 8 + 2 * t4;
            *(float2*)&p0[col] = make_float2(O[m][dc][0], O[m][dc][1]);
            *(float2*)&p1[col] = make_float2(O[m][dc][2], O[m][dc][3]);
        }
    }
}

// ---------------- combine splits -> g_ctx ------------------------------------
__global__ void __launch_bounds__(256) attn_combine() {
    const int idx = blockIdx.x * 256 + threadIdx.x;
    const int q_lin = idx >> 3;          // bh*T_ + qi
    const int f = idx & 7;               // which float4 of 8
    const int bh = q_lin >> 12;
    const int qi = q_lin & (T_ - 1);
    const int b = bh >> 2;
    const int h = bh & 3;

    float l = 0.f;
    float4 acc = make_float4(0.f, 0.f, 0.f, 0.f);
#pragma unroll
    for (int s = 0; s < KS; s++) {
        const size_t pb = ((size_t)s * (B_ * H_) + bh) * T_;
        l += g_pl[pb + qi];
        const float4 v = *(const float4*)(g_pacc + (pb + qi) * HD + f * 4);
        acc.x += v.x; acc.y += v.y; acc.z += v.z; acc.w += v.w;
    }
    const float inv = 1.f / l;
    float* op = g_ctx + ((size_t)b * T_ + qi) * DM + h * HD + f * 4;
    *(float4*)op = make_float4(acc.x * inv, acc.y * inv, acc.z * inv, acc.w * inv);
}

// ---------------- GEMM 2: out = g_ctx @ Wout --------------------------------
__global__ void __launch_bounds__(256) gemm_out(const float* __restrict__ W,
                                               float* __restrict__ out) {
    __shared__ float As[16][68];
    __shared__ float Ws[16][68];
    const int tx = threadIdx.x & 15;
    const int ty = threadIdx.x >> 4;
    const int m0 = blockIdx.x * 64;
    const int n0 = blockIdx.y * 64;

    float c[4][4];
#pragma unroll
    for (int i = 0; i < 4; i++)
#pragma unroll
        for (int j = 0; j < 4; j++) c[i][j] = 0.f;

    for (int k0 = 0; k0 < 128; k0 += 16) {
#pragma unroll
        for (int i = 0; i < 4; i++) {
            int lin = threadIdx.x + 256 * i;
            int m = lin >> 4, kk = lin & 15;
            As[kk][m] = g_ctx[(size_t)(m0 + m) * 128 + k0 + kk];
        }
#pragma unroll
        for (int i = 0; i < 4; i++) {
            int lin = threadIdx.x + 256 * i;
            int kk = lin >> 6, n = lin & 63;
            Ws[kk][n] = W[(size_t)(k0 + kk) * 128 + n0 + n];
        }
        __syncthreads();
#pragma unroll
        for (int kk = 0; kk < 16; kk++) {
            float4 a = *(const float4*)&As[kk][4 * ty];
            float4 b = *(const float4*)&Ws[kk][4 * tx];
            const float av[4] = {a.x, a.y, a.z, a.w};
            const float bv[4] = {b.x, b.y, b.z, b.w};
#pragma unroll
            for (int i = 0; i < 4; i++)
#pragma unroll
                for (int j = 0; j < 4; j++) c[i][j] = fmaf(av[i], bv[j], c[i][j]);
        }
        __syncthreads();
    }

#pragma unroll
    for (int i = 0; i < 4; i++) {
        const int m = m0 + 4 * ty + i;
#pragma unroll
        for (int j = 0; j < 4; j++) {
            const int n = n0 + 4 * tx + j;
            out[(size_t)m * 128 + n] = c[i][j];
        }
    }
}

// ---------------- launch ----------------------------------------------------
extern "C" void kernel_launch(void* const* d_in, const int* in_sizes, int n_in,
                              void* d_out, int out_size) {
    const float* x    = (const float*)d_in[0];
    const float* pk   = (const float*)d_in[1];
    const float* pv   = (const float*)d_in[2];
    const float* Wqkv = (const float*)d_in[3];
    const float* Wout = (const float*)d_in[4];
    float* out = (float*)d_out;

    {
        int n4 = B_ * H_ * P_ * HD / 4;
        prefix_copy<<<(n4 + 255) / 256, 256>>>((const float4*)pk, (const float4*)pv);
    }
    {
        dim3 grid(8192 / 64, 384 / 64);
        gemm_qkv<<<grid, 256>>>(x, Wqkv);
    }
    {
        dim3 grid(32, KS, B_ * H_);
        attn_tc<<<grid, 128>>>();
    }
    {
        attn_combine<<<(B_ * H_ * T_ * 8) / 256, 256>>>();
    }
    {
        dim3 grid(8192 / 64, 128 / 64);
        gemm_out<<<grid, 256>>>(Wout, out);
    }
}

// round 7
// speedup vs baseline: 5.8063x; 1.3147x over previous
#include <cuda_runtime.h>
#include <cuda_fp16.h>
#include <cstdint>

// Problem constants
#define B_ 2
#define T_ 4096
#define H_ 4
#define HD 32
#define P_ 2048
#define TK 6144           // P_ + T_
#define DM 128            // D_MODEL
#define KS 4              // key splits
#define RSQRT_HD 0.17677669529663687f

// ---------------- scratch (device globals; no allocation allowed) ------------
// g_q/g_k hold tf32 bit patterns (as float); g_q pre-scaled by 1/sqrt(hd)
// g_v holds raw fp32; g_vt holds fp16 transposed [bh][d][TK]
__device__ float g_q[(size_t)B_ * H_ * T_ * HD];
__device__ float g_k[(size_t)B_ * H_ * TK * HD];
__device__ float g_v[(size_t)B_ * H_ * TK * HD];
__device__ __align__(16) __half g_vt[(size_t)B_ * H_ * HD * TK];
__device__ float g_ctx[(size_t)B_ * T_ * DM];             // [B][T][128]
__device__ float g_pacc[(size_t)KS * B_ * H_ * T_ * HD];  // partial numerators
__device__ float g_pl[(size_t)KS * B_ * H_ * T_];         // partial denominators

// ---------------- mma helpers ------------------------------------------------
__device__ __forceinline__ uint32_t f2tf(float f) {
    uint32_t r;
    asm("cvt.rna.tf32.f32 %0, %1;" : "=r"(r) : "f"(f));
    return r;
}
__device__ __forceinline__ void mma8(float* c, const uint32_t* a, uint32_t b0, uint32_t b1) {
    asm("mma.sync.aligned.m16n8k8.row.col.f32.tf32.tf32.f32 "
        "{%0,%1,%2,%3},{%4,%5,%6,%7},{%8,%9},{%0,%1,%2,%3};"
        : "+f"(c[0]), "+f"(c[1]), "+f"(c[2]), "+f"(c[3])
        : "r"(a[0]), "r"(a[1]), "r"(a[2]), "r"(a[3]), "r"(b0), "r"(b1));
}
__device__ __forceinline__ void mma16h(float* c, const uint32_t* a, uint32_t b0, uint32_t b1) {
    asm("mma.sync.aligned.m16n8k16.row.col.f32.f16.f16.f32 "
        "{%0,%1,%2,%3},{%4,%5,%6,%7},{%8,%9},{%0,%1,%2,%3};"
        : "+f"(c[0]), "+f"(c[1]), "+f"(c[2]), "+f"(c[3])
        : "r"(a[0]), "r"(a[1]), "r"(a[2]), "r"(a[3]), "r"(b0), "r"(b1));
}
__device__ __forceinline__ uint32_t packh2(float lo, float hi) {
    __half2 h = __float22half2_rn(make_float2(lo, hi));
    return *reinterpret_cast<uint32_t*>(&h);
}

// ---------------- GEMM 1: qkv = x @ Wqkv, scatter ----------------------------
__global__ void __launch_bounds__(256) gemm_qkv(const float* __restrict__ A,
                                                const float* __restrict__ W) {
    __shared__ float As[16][68];
    __shared__ float Ws[16][68];
    const int tx = threadIdx.x & 15;
    const int ty = threadIdx.x >> 4;
    const int m0 = blockIdx.x * 64;
    const int n0 = blockIdx.y * 64;

    float c[4][4];
#pragma unroll
    for (int i = 0; i < 4; i++)
#pragma unroll
        for (int j = 0; j < 4; j++) c[i][j] = 0.f;

    for (int k0 = 0; k0 < 128; k0 += 16) {
#pragma unroll
        for (int i = 0; i < 4; i++) {
            int lin = threadIdx.x + 256 * i;
            int m = lin >> 4, kk = lin & 15;
            As[kk][m] = A[(size_t)(m0 + m) * 128 + k0 + kk];
        }
#pragma unroll
        for (int i = 0; i < 4; i++) {
            int lin = threadIdx.x + 256 * i;
            int kk = lin >> 6, n = lin & 63;
            Ws[kk][n] = W[(size_t)(k0 + kk) * 384 + n0 + n];
        }
        __syncthreads();
#pragma unroll
        for (int kk = 0; kk < 16; kk++) {
            float4 a = *(const float4*)&As[kk][4 * ty];
            float4 b = *(const float4*)&Ws[kk][4 * tx];
            const float av[4] = {a.x, a.y, a.z, a.w};
            const float bv[4] = {b.x, b.y, b.z, b.w};
#pragma unroll
            for (int i = 0; i < 4; i++)
#pragma unroll
                for (int j = 0; j < 4; j++) c[i][j] = fmaf(av[i], bv[j], c[i][j]);
        }
        __syncthreads();
    }

#pragma unroll
    for (int i = 0; i < 4; i++) {
        const int m = m0 + 4 * ty + i;
        const int b = m >> 12;
        const int t = m & (T_ - 1);
#pragma unroll
        for (int j = 0; j < 4; j++) {
            const int n = n0 + 4 * tx + j;
            const int sec = n >> 7;
            const int r = n & 127;
            const int h = r >> 5;
            const int d = r & 31;
            const float val = c[i][j];
            if (sec == 0) {
                g_q[(((size_t)(b * H_ + h) * T_) + t) * HD + d] =
                    __uint_as_float(f2tf(val * RSQRT_HD));
            } else if (sec == 1) {
                g_k[(((size_t)(b * H_ + h) * TK) + P_ + t) * HD + d] =
                    __uint_as_float(f2tf(val));
            } else {
                g_v[(((size_t)(b * H_ + h) * TK) + P_ + t) * HD + d] = val;
            }
        }
    }
}

// ---------------- prefix copy (K to tf32, V raw) -----------------------------
__global__ void prefix_copy(const float4* __restrict__ pk, const float4* __restrict__ pv) {
    int idx = blockIdx.x * blockDim.x + threadIdx.x;
    if (idx < B_ * H_ * P_ * HD / 4) {
        const int per_bh = P_ * HD / 4;
        int bh = idx / per_bh;
        int rem = idx - bh * per_bh;
        float4 k = pk[idx], o;
        o.x = __uint_as_float(f2tf(k.x)); o.y = __uint_as_float(f2tf(k.y));
        o.z = __uint_as_float(f2tf(k.z)); o.w = __uint_as_float(f2tf(k.w));
        ((float4*)g_k)[(size_t)bh * (TK * HD / 4) + rem] = o;
        ((float4*)g_v)[(size_t)bh * (TK * HD / 4) + rem] = pv[idx];
    }
}

// ---------------- V transpose: g_v [bh][key][d] fp32 -> g_vt [bh][d][key] fp16
__global__ void __launch_bounds__(128) v_transpose() {
    __shared__ __half S[HD][72];
    const int bh = blockIdx.y;
    const int j0 = blockIdx.x * 64;
    const int tid = threadIdx.x;

#pragma unroll
    for (int i = 0; i < 4; i++) {
        const int f = tid + i * 128;       // 0..511 float4s
        const int key = f >> 3;
        const int d0 = (f & 7) << 2;
        float4 v = *(const float4*)(g_v + ((size_t)bh * TK + j0 + key) * HD + d0);
        S[d0 + 0][key] = __float2half_rn(v.x);
        S[d0 + 1][key] = __float2half_rn(v.y);
        S[d0 + 2][key] = __float2half_rn(v.z);
        S[d0 + 3][key] = __float2half_rn(v.w);
    }
    __syncthreads();
#pragma unroll
    for (int i = 0; i < 2; i++) {
        const int f = tid + i * 128;       // 0..255 uint4s
        const int d = f >> 3;
        const int part = f & 7;
        *(uint4*)(g_vt + ((size_t)(bh * HD + d)) * TK + j0 + part * 8) =
            *(const uint4*)&S[d][part * 8];
    }
}

// ---------------- tensor-core attention, split-K, fp16 PV --------------------
// 128 threads = 4 warps; q-tile 128 (warp w owns 32 queries).
// grid = (32 q-tiles, KS splits, 8 bh). QK: tf32 m16n8k8. PV: fp16 m16n8k16,
// with the S C-fragment packed directly into the PV A-fragment (no transpose).
__global__ void __launch_bounds__(128) attn_tc() {
    __shared__ float Ks[64][36];
    __shared__ __half Vst[HD][72];        // V transposed: [d][key], stride 72

    const int tid = threadIdx.x;
    const int w = tid >> 5;
    const int lane = tid & 31;
    const int g = lane >> 2;
    const int t4 = lane & 3;

    const int qt = 31 - blockIdx.x;      // heavy q-tiles first
    const int split = blockIdx.y;
    const int bh = blockIdx.z;
    const int q0 = qt * 128;
    const int wq = q0 + w * 32;

    // ---- Q fragments (tf32 bits, pre-scaled) ----
    uint32_t qa[2][4][4];
    {
        const uint32_t* qb = (const uint32_t*)(g_q + ((size_t)bh * T_) * HD);
#pragma unroll
        for (int m = 0; m < 2; m++) {
            const int r0 = wq + m * 16 + g;
#pragma unroll
            for (int dc = 0; dc < 4; dc++) {
                qa[m][dc][0] = qb[(size_t)r0 * HD + dc * 8 + t4];
                qa[m][dc][1] = qb[(size_t)(r0 + 8) * HD + dc * 8 + t4];
                qa[m][dc][2] = qb[(size_t)r0 * HD + dc * 8 + t4 + 4];
                qa[m][dc][3] = qb[(size_t)(r0 + 8) * HD + dc * 8 + t4 + 4];
            }
        }
    }

    float O[2][4][4];
#pragma unroll
    for (int m = 0; m < 2; m++)
#pragma unroll
        for (int dc = 0; dc < 4; dc++)
#pragma unroll
            for (int r = 0; r < 4; r++) O[m][dc][r] = 0.f;
    float lsum[2][2] = {{0.f, 0.f}, {0.f, 0.f}};

    const float4* kb = (const float4*)(g_k + (size_t)bh * TK * HD);
    const int nfull = (P_ + q0) >> 6;     // diag tile for warps 0,1
    const int ntot = nfull + 2;           // diag tile for warps 2,3 is nfull+1
    const int t_begin = (ntot * split) / KS;
    const int t_end = (ntot * (split + 1)) / KS;

    for (int t = t_begin; t < t_end; t++) {
        const int j0 = t << 6;
        __syncthreads();
        // K tile: 512 float4, 4 per thread
#pragma unroll
        for (int i = 0; i < 4; i++) {
            const int f = tid + (i << 7);
            const int key = f >> 3;
            const int d0 = (f & 7) << 2;
            *(float4*)&Ks[key][d0] = kb[(size_t)j0 * 8 + f];
        }
        // V tile (transposed, fp16): 256 uint4, 2 per thread
#pragma unroll
        for (int i = 0; i < 2; i++) {
            const int f = tid + (i << 7);
            const int d = f >> 3;
            const int part = f & 7;
            *(uint4*)&Vst[d][part * 8] =
                *(const uint4*)(g_vt + ((size_t)(bh * HD + d)) * TK + j0 + part * 8);
        }
        __syncthreads();

        const bool isdiag = (t == nfull + (w >> 1));
        if (t > nfull && (w >> 1) == 0) continue;   // fully masked for warps 0,1

        // ---- per 16-key pair: S-mma(x2 chunks) -> exp -> pack -> PV-mma ----
#pragma unroll
        for (int pr = 0; pr < 4; pr++) {
            const int nc0 = 2 * pr, nc1 = 2 * pr + 1;
            float S0[2][4], S1[2][4];
#pragma unroll
            for (int m = 0; m < 2; m++)
#pragma unroll
                for (int r = 0; r < 4; r++) { S0[m][r] = 0.f; S1[m][r] = 0.f; }
#pragma unroll
            for (int dc = 0; dc < 4; dc++) {
                const uint32_t k0a = __float_as_uint(Ks[nc0 * 8 + g][dc * 8 + t4]);
                const uint32_t k0b = __float_as_uint(Ks[nc0 * 8 + g][dc * 8 + t4 + 4]);
                mma8(S0[0], qa[0][dc], k0a, k0b);
                mma8(S0[1], qa[1][dc], k0a, k0b);
                const uint32_t k1a = __float_as_uint(Ks[nc1 * 8 + g][dc * 8 + t4]);
                const uint32_t k1b = __float_as_uint(Ks[nc1 * 8 + g][dc * 8 + t4 + 4]);
                mma8(S1[0], qa[0][dc], k1a, k1b);
                mma8(S1[1], qa[1][dc], k1a, k1b);
            }

            float P0[2][4], P1[2][4];
#pragma unroll
            for (int m = 0; m < 2; m++) {
                if (isdiag) {
                    const int rbase = 32 * (w & 1) + m * 16 + g;
                    const int c00 = nc0 * 8 + 2 * t4;
                    const int c10 = nc1 * 8 + 2 * t4;
                    P0[m][0] = (c00     <= rbase)     ? __expf(S0[m][0]) : 0.f;
                    P0[m][1] = (c00 + 1 <= rbase)     ? __expf(S0[m][1]) : 0.f;
                    P0[m][2] = (c00     <= rbase + 8) ? __expf(S0[m][2]) : 0.f;
                    P0[m][3] = (c00 + 1 <= rbase + 8) ? __expf(S0[m][3]) : 0.f;
                    P1[m][0] = (c10     <= rbase)     ? __expf(S1[m][0]) : 0.f;
                    P1[m][1] = (c10 + 1 <= rbase)     ? __expf(S1[m][1]) : 0.f;
                    P1[m][2] = (c10     <= rbase + 8) ? __expf(S1[m][2]) : 0.f;
                    P1[m][3] = (c10 + 1 <= rbase + 8) ? __expf(S1[m][3]) : 0.f;
                } else {
                    P0[m][0] = __expf(S0[m][0]); P0[m][1] = __expf(S0[m][1]);
                    P0[m][2] = __expf(S0[m][2]); P0[m][3] = __expf(S0[m][3]);
                    P1[m][0] = __expf(S1[m][0]); P1[m][1] = __expf(S1[m][1]);
                    P1[m][2] = __expf(S1[m][2]); P1[m][3] = __expf(S1[m][3]);
                }
                lsum[m][0] += P0[m][0] + P0[m][1] + P1[m][0] + P1[m][1];
                lsum[m][1] += P0[m][2] + P0[m][3] + P1[m][2] + P1[m][3];
            }

            // Pack S C-frag pairs directly into fp16 A-frag
            uint32_t A[2][4];
#pragma unroll
            for (int m = 0; m < 2; m++) {
                A[m][0] = packh2(P0[m][0], P0[m][1]);   // row g,   keys k0+2t4,+1
                A[m][1] = packh2(P0[m][2], P0[m][3]);   // row g+8, keys k0+2t4,+1
                A[m][2] = packh2(P1[m][0], P1[m][1]);   // row g,   keys k0+8+2t4,+1
                A[m][3] = packh2(P1[m][2], P1[m][3]);   // row g+8, keys k0+8+2t4,+1
            }

            // PV: O += P[:, k0:k0+16] @ V[k0:k0+16, :]
            const int k0 = pr * 16;
#pragma unroll
            for (int dc = 0; dc < 4; dc++) {
                const uint32_t b0 = *(const uint32_t*)&Vst[dc * 8 + g][k0 + 2 * t4];
                const uint32_t b1 = *(const uint32_t*)&Vst[dc * 8 + g][k0 + 2 * t4 + 8];
                mma16h(O[0][dc], A[0], b0, b1);
                mma16h(O[1][dc], A[1], b0, b1);
            }
        }
    }

    // ---- store partials (unnormalized) ----
    const size_t pbase = ((size_t)split * (B_ * H_) + bh) * T_;
#pragma unroll
    for (int m = 0; m < 2; m++) {
        float l0 = lsum[m][0];
        l0 += __shfl_xor_sync(0xFFFFFFFFu, l0, 1);
        l0 += __shfl_xor_sync(0xFFFFFFFFu, l0, 2);
        float l1 = lsum[m][1];
        l1 += __shfl_xor_sync(0xFFFFFFFFu, l1, 1);
        l1 += __shfl_xor_sync(0xFFFFFFFFu, l1, 2);
        const int r0 = wq + m * 16 + g;
        if (t4 == 0) {
            g_pl[pbase + r0] = l0;
            g_pl[pbase + r0 + 8] = l1;
        }
        float* p0 = g_pacc + (pbase + r0) * HD;
        float* p1 = g_pacc + (pbase + r0 + 8) * HD;
#pragma unroll
        for (int dc = 0; dc < 4; dc++) {
            const int col = dc * 8 + 2 * t4;
            *(float2*)&p0[col] = make_float2(O[m][dc][0], O[m][dc][1]);
            *(float2*)&p1[col] = make_float2(O[m][dc][2], O[m][dc][3]);
        }
    }
}

// ---------------- combine splits -> g_ctx ------------------------------------
__global__ void __launch_bounds__(256) attn_combine() {
    const int idx = blockIdx.x * 256 + threadIdx.x;
    const int q_lin = idx >> 3;          // bh*T_ + qi
    const int f = idx & 7;               // which float4 of 8
    const int bh = q_lin >> 12;
    const int qi = q_lin & (T_ - 1);
    const int b = bh >> 2;
    const int h = bh & 3;

    float l = 0.f;
    float4 acc = make_float4(0.f, 0.f, 0.f, 0.f);
#pragma unroll
    for (int s = 0; s < KS; s++) {
        const size_t pb = ((size_t)s * (B_ * H_) + bh) * T_;
        l += g_pl[pb + qi];
        const float4 v = *(const float4*)(g_pacc + (pb + qi) * HD + f * 4);
        acc.x += v.x; acc.y += v.y; acc.z += v.z; acc.w += v.w;
    }
    const float inv = 1.f / l;
    float* op = g_ctx + ((size_t)b * T_ + qi) * DM + h * HD + f * 4;
    *(float4*)op = make_float4(acc.x * inv, acc.y * inv, acc.z * inv, acc.w * inv);
}

// ---------------- GEMM 2: out = g_ctx @ Wout --------------------------------
__global__ void __launch_bounds__(256) gemm_out(const float* __restrict__ W,
                                               float* __restrict__ out) {
    __shared__ float As[16][68];
    __shared__ float Ws[16][68];
    const int tx = threadIdx.x & 15;
    const int ty = threadIdx.x >> 4;
    const int m0 = blockIdx.x * 64;
    const int n0 = blockIdx.y * 64;

    float c[4][4];
#pragma unroll
    for (int i = 0; i < 4; i++)
#pragma unroll
        for (int j = 0; j < 4; j++) c[i][j] = 0.f;

    for (int k0 = 0; k0 < 128; k0 += 16) {
#pragma unroll
        for (int i = 0; i < 4; i++) {
            int lin = threadIdx.x + 256 * i;
            int m = lin >> 4, kk = lin & 15;
            As[kk][m] = g_ctx[(size_t)(m0 + m) * 128 + k0 + kk];
        }
#pragma unroll
        for (int i = 0; i < 4; i++) {
            int lin = threadIdx.x + 256 * i;
            int kk = lin >> 6, n = lin & 63;
            Ws[kk][n] = W[(size_t)(k0 + kk) * 128 + n0 + n];
        }
        __syncthreads();
#pragma unroll
        for (int kk = 0; kk < 16; kk++) {
            float4 a = *(const float4*)&As[kk][4 * ty];
            float4 b = *(const float4*)&Ws[kk][4 * tx];
            const float av[4] = {a.x, a.y, a.z, a.w};
            const float bv[4] = {b.x, b.y, b.z, b.w};
#pragma unroll
            for (int i = 0; i < 4; i++)
#pragma unroll
                for (int j = 0; j < 4; j++) c[i][j] = fmaf(av[i], bv[j], c[i][j]);
        }
        __syncthreads();
    }

#pragma unroll
    for (int i = 0; i < 4; i++) {
        const int m = m0 + 4 * ty + i;
#pragma unroll
        for (int j = 0; j < 4; j++) {
            const int n = n0 + 4 * tx + j;
            out[(size_t)m * 128 + n] = c[i][j];
        }
    }
}

// ---------------- launch ----------------------------------------------------
extern "C" void kernel_launch(void* const* d_in, const int* in_sizes, int n_in,
                              void* d_out, int out_size) {
    const float* x    = (const float*)d_in[0];
    const float* pk   = (const float*)d_in[1];
    const float* pv   = (const float*)d_in[2];
    const float* Wqkv = (const float*)d_in[3];
    const float* Wout = (const float*)d_in[4];
    float* out = (float*)d_out;

    {
        int n4 = B_ * H_ * P_ * HD / 4;
        prefix_copy<<<(n4 + 255) / 256, 256>>>((const float4*)pk, (const float4*)pv);
    }
    {
        dim3 grid(8192 / 64, 384 / 64);
        gemm_qkv<<<grid, 256>>>(x, Wqkv);
    }
    {
        dim3 grid(TK / 64, B_ * H_);
        v_transpose<<<grid, 128>>>();
    }
    {
        dim3 grid(32, KS, B_ * H_);
        attn_tc<<<grid, 128>>>();
    }
    {
        attn_combine<<<(B_ * H_ * T_ * 8) / 256, 256>>>();
    }
    {
        dim3 grid(8192 / 64, 128 / 64);
        gemm_out<<<grid, 256>>>(Wout, out);
    }
}

// round 8
// speedup vs baseline: 6.8717x; 1.1835x over previous
#include <cuda_runtime.h>
#include <cuda_fp16.h>
#include <cstdint>

// Problem constants
#define B_ 2
#define T_ 4096
#define H_ 4
#define HD 32
#define P_ 2048
#define TK 6144           // P_ + T_
#define DM 128            // D_MODEL
#define KS 4              // key splits
#define RSQRT_HD 0.17677669529663687f

// ---------------- scratch (device globals; no allocation allowed) ------------
__device__ __align__(16) __half g_qh[(size_t)B_ * H_ * T_ * HD];   // fp16, pre-scaled
__device__ __align__(16) __half g_kh[(size_t)B_ * H_ * TK * HD];   // fp16 [bh][key][d]
__device__ float g_v[(size_t)B_ * H_ * TK * HD];                   // fp32 staging
__device__ __align__(16) __half g_vt[(size_t)B_ * H_ * HD * TK];   // fp16 [bh][d][key]
__device__ float g_ctx[(size_t)B_ * T_ * DM];
__device__ float g_pacc[(size_t)KS * B_ * H_ * T_ * HD];
__device__ float g_pl[(size_t)KS * B_ * H_ * T_];

// ---------------- mma helpers ------------------------------------------------
__device__ __forceinline__ void mma16h(float* c, const uint32_t* a, uint32_t b0, uint32_t b1) {
    asm("mma.sync.aligned.m16n8k16.row.col.f32.f16.f16.f32 "
        "{%0,%1,%2,%3},{%4,%5,%6,%7},{%8,%9},{%0,%1,%2,%3};"
        : "+f"(c[0]), "+f"(c[1]), "+f"(c[2]), "+f"(c[3])
        : "r"(a[0]), "r"(a[1]), "r"(a[2]), "r"(a[3]), "r"(b0), "r"(b1));
}
__device__ __forceinline__ uint32_t packh2(float lo, float hi) {
    __half2 h = __float22half2_rn(make_float2(lo, hi));
    return *reinterpret_cast<uint32_t*>(&h);
}

// ---------------- GEMM 1: qkv = x @ Wqkv, scatter ----------------------------
__global__ void __launch_bounds__(256) gemm_qkv(const float* __restrict__ A,
                                                const float* __restrict__ W) {
    __shared__ float As[16][68];
    __shared__ float Ws[16][68];
    const int tx = threadIdx.x & 15;
    const int ty = threadIdx.x >> 4;
    const int m0 = blockIdx.x * 64;
    const int n0 = blockIdx.y * 64;

    float c[4][4];
#pragma unroll
    for (int i = 0; i < 4; i++)
#pragma unroll
        for (int j = 0; j < 4; j++) c[i][j] = 0.f;

    for (int k0 = 0; k0 < 128; k0 += 16) {
#pragma unroll
        for (int i = 0; i < 4; i++) {
            int lin = threadIdx.x + 256 * i;
            int m = lin >> 4, kk = lin & 15;
            As[kk][m] = A[(size_t)(m0 + m) * 128 + k0 + kk];
        }
#pragma unroll
        for (int i = 0; i < 4; i++) {
            int lin = threadIdx.x + 256 * i;
            int kk = lin >> 6, n = lin & 63;
            Ws[kk][n] = W[(size_t)(k0 + kk) * 384 + n0 + n];
        }
        __syncthreads();
#pragma unroll
        for (int kk = 0; kk < 16; kk++) {
            float4 a = *(const float4*)&As[kk][4 * ty];
            float4 b = *(const float4*)&Ws[kk][4 * tx];
            const float av[4] = {a.x, a.y, a.z, a.w};
            const float bv[4] = {b.x, b.y, b.z, b.w};
#pragma unroll
            for (int i = 0; i < 4; i++)
#pragma unroll
                for (int j = 0; j < 4; j++) c[i][j] = fmaf(av[i], bv[j], c[i][j]);
        }
        __syncthreads();
    }

#pragma unroll
    for (int i = 0; i < 4; i++) {
        const int m = m0 + 4 * ty + i;
        const int b = m >> 12;
        const int t = m & (T_ - 1);
#pragma unroll
        for (int j = 0; j < 4; j++) {
            const int n = n0 + 4 * tx + j;
            const int sec = n >> 7;
            const int r = n & 127;
            const int h = r >> 5;
            const int d = r & 31;
            const float val = c[i][j];
            if (sec == 0) {
                g_qh[(((size_t)(b * H_ + h) * T_) + t) * HD + d] =
                    __float2half_rn(val * RSQRT_HD);
            } else if (sec == 1) {
                g_kh[(((size_t)(b * H_ + h) * TK) + P_ + t) * HD + d] =
                    __float2half_rn(val);
            } else {
                g_v[(((size_t)(b * H_ + h) * TK) + P_ + t) * HD + d] = val;
            }
        }
    }
}

// ---------------- prefix copy (K to fp16, V raw fp32) ------------------------
__global__ void prefix_copy(const float4* __restrict__ pk, const float4* __restrict__ pv) {
    int idx = blockIdx.x * blockDim.x + threadIdx.x;
    if (idx < B_ * H_ * P_ * HD / 4) {
        const int per_bh = P_ * HD / 4;
        int bh = idx / per_bh;
        int rem = idx - bh * per_bh;
        float4 k = pk[idx];
        __half2 h0 = __float22half2_rn(make_float2(k.x, k.y));
        __half2 h1 = __float22half2_rn(make_float2(k.z, k.w));
        uint2 kk = make_uint2(*(uint32_t*)&h0, *(uint32_t*)&h1);
        *(uint2*)(g_kh + ((size_t)bh * TK * HD) + rem * 4) = kk;
        ((float4*)g_v)[(size_t)bh * (TK * HD / 4) + rem] = pv[idx];
    }
}

// ---------------- V transpose: g_v [bh][key][d] fp32 -> g_vt [bh][d][key] fp16
__global__ void __launch_bounds__(128) v_transpose() {
    __shared__ __half S[HD][72];
    const int bh = blockIdx.y;
    const int j0 = blockIdx.x * 64;
    const int tid = threadIdx.x;

#pragma unroll
    for (int i = 0; i < 4; i++) {
        const int f = tid + i * 128;       // 0..511 float4s
        const int key = f >> 3;
        const int d0 = (f & 7) << 2;
        float4 v = *(const float4*)(g_v + ((size_t)bh * TK + j0 + key) * HD + d0);
        S[d0 + 0][key] = __float2half_rn(v.x);
        S[d0 + 1][key] = __float2half_rn(v.y);
        S[d0 + 2][key] = __float2half_rn(v.z);
        S[d0 + 3][key] = __float2half_rn(v.w);
    }
    __syncthreads();
#pragma unroll
    for (int i = 0; i < 2; i++) {
        const int f = tid + i * 128;       // 0..255 uint4s
        const int d = f >> 3;
        const int part = f & 7;
        *(uint4*)(g_vt + ((size_t)(bh * HD + d)) * TK + j0 + part * 8) =
            *(const uint4*)&S[d][part * 8];
    }
}

// ---------------- tensor-core attention: fp16 QK + fp16 PV, split-K ----------
// 128 threads = 4 warps; q-tile 128 (warp w owns 32 queries).
// grid = (32 q-tiles, KS splits, 8 bh). All mma m16n8k16 fp16, fp32 accum.
__global__ void __launch_bounds__(128) attn_tc() {
    __shared__ __half Kh[64][40];         // [key][d], stride 40 halves (conflict-free)
    __shared__ __half Vst[HD][72];        // [d][key], stride 72 halves

    const int tid = threadIdx.x;
    const int w = tid >> 5;
    const int lane = tid & 31;
    const int g = lane >> 2;
    const int t4 = lane & 3;

    const int qt = 31 - blockIdx.x;      // heavy q-tiles first
    const int split = blockIdx.y;
    const int bh = blockIdx.z;
    const int q0 = qt * 128;
    const int wq = q0 + w * 32;

    // ---- Q fragments: fp16 A-frags, [m][kc][reg] ----
    uint32_t qa[2][2][4];
    {
        const __half* qb = g_qh + ((size_t)bh * T_) * HD;
#pragma unroll
        for (int m = 0; m < 2; m++) {
            const int r0 = wq + m * 16 + g;
#pragma unroll
            for (int kc = 0; kc < 2; kc++) {
                const int c = kc * 16 + 2 * t4;
                qa[m][kc][0] = *(const uint32_t*)(qb + (size_t)r0 * HD + c);
                qa[m][kc][1] = *(const uint32_t*)(qb + (size_t)(r0 + 8) * HD + c);
                qa[m][kc][2] = *(const uint32_t*)(qb + (size_t)r0 * HD + c + 8);
                qa[m][kc][3] = *(const uint32_t*)(qb + (size_t)(r0 + 8) * HD + c + 8);
            }
        }
    }

    float O[2][4][4];
#pragma unroll
    for (int m = 0; m < 2; m++)
#pragma unroll
        for (int dc = 0; dc < 4; dc++)
#pragma unroll
            for (int r = 0; r < 4; r++) O[m][dc][r] = 0.f;
    float lsum[2][2] = {{0.f, 0.f}, {0.f, 0.f}};

    const uint4* kb = (const uint4*)(g_kh + (size_t)bh * TK * HD);   // 4 uint4 per key row
    const int nfull = (P_ + q0) >> 6;     // diag tile for warps 0,1
    const int ntot = nfull + 2;           // diag tile for warps 2,3 is nfull+1
    const int t_begin = (ntot * split) / KS;
    const int t_end = (ntot * (split + 1)) / KS;

    for (int t = t_begin; t < t_end; t++) {
        const int j0 = t << 6;
        __syncthreads();
        // K tile: 64 keys x 32 halves = 256 uint4, 2 per thread
#pragma unroll
        for (int i = 0; i < 2; i++) {
            const int f = tid + (i << 7);
            const int key = f >> 2;
            const int part = f & 3;
            *(uint4*)&Kh[key][part * 8] = kb[(size_t)j0 * 4 + f];
        }
        // V tile (transposed): 32 d x 64 keys = 256 uint4, 2 per thread
#pragma unroll
        for (int i = 0; i < 2; i++) {
            const int f = tid + (i << 7);
            const int d = f >> 3;
            const int part = f & 7;
            *(uint4*)&Vst[d][part * 8] =
                *(const uint4*)(g_vt + ((size_t)(bh * HD + d)) * TK + j0 + part * 8);
        }
        __syncthreads();

        const bool isdiag = (t == nfull + (w >> 1));
        if (t > nfull && (w >> 1) == 0) continue;   // fully masked for warps 0,1

        // ---- per 16-key pair: S-mma -> exp -> pack -> PV-mma ----
#pragma unroll
        for (int pr = 0; pr < 4; pr++) {
            const int nc0 = 2 * pr, nc1 = 2 * pr + 1;
            float S0[2][4], S1[2][4];
#pragma unroll
            for (int m = 0; m < 2; m++)
#pragma unroll
                for (int r = 0; r < 4; r++) { S0[m][r] = 0.f; S1[m][r] = 0.f; }
#pragma unroll
            for (int kc = 0; kc < 2; kc++) {
                const int c = kc * 16 + 2 * t4;
                const uint32_t k0a = *(const uint32_t*)&Kh[nc0 * 8 + g][c];
                const uint32_t k0b = *(const uint32_t*)&Kh[nc0 * 8 + g][c + 8];
                mma16h(S0[0], qa[0][kc], k0a, k0b);
                mma16h(S0[1], qa[1][kc], k0a, k0b);
                const uint32_t k1a = *(const uint32_t*)&Kh[nc1 * 8 + g][c];
                const uint32_t k1b = *(const uint32_t*)&Kh[nc1 * 8 + g][c + 8];
                mma16h(S1[0], qa[0][kc], k1a, k1b);
                mma16h(S1[1], qa[1][kc], k1a, k1b);
            }

            float P0[2][4], P1[2][4];
#pragma unroll
            for (int m = 0; m < 2; m++) {
                if (isdiag) {
                    const int rbase = 32 * (w & 1) + m * 16 + g;
                    const int c00 = nc0 * 8 + 2 * t4;
                    const int c10 = nc1 * 8 + 2 * t4;
                    P0[m][0] = (c00     <= rbase)     ? __expf(S0[m][0]) : 0.f;
                    P0[m][1] = (c00 + 1 <= rbase)     ? __expf(S0[m][1]) : 0.f;
                    P0[m][2] = (c00     <= rbase + 8) ? __expf(S0[m][2]) : 0.f;
                    P0[m][3] = (c00 + 1 <= rbase + 8) ? __expf(S0[m][3]) : 0.f;
                    P1[m][0] = (c10     <= rbase)     ? __expf(S1[m][0]) : 0.f;
                    P1[m][1] = (c10 + 1 <= rbase)     ? __expf(S1[m][1]) : 0.f;
                    P1[m][2] = (c10     <= rbase + 8) ? __expf(S1[m][2]) : 0.f;
                    P1[m][3] = (c10 + 1 <= rbase + 8) ? __expf(S1[m][3]) : 0.f;
                } else {
                    P0[m][0] = __expf(S0[m][0]); P0[m][1] = __expf(S0[m][1]);
                    P0[m][2] = __expf(S0[m][2]); P0[m][3] = __expf(S0[m][3]);
                    P1[m][0] = __expf(S1[m][0]); P1[m][1] = __expf(S1[m][1]);
                    P1[m][2] = __expf(S1[m][2]); P1[m][3] = __expf(S1[m][3]);
                }
                lsum[m][0] += P0[m][0] + P0[m][1] + P1[m][0] + P1[m][1];
                lsum[m][1] += P0[m][2] + P0[m][3] + P1[m][2] + P1[m][3];
            }

            // Pack S C-frag pairs directly into fp16 A-frag
            uint32_t A[2][4];
#pragma unroll
            for (int m = 0; m < 2; m++) {
                A[m][0] = packh2(P0[m][0], P0[m][1]);
                A[m][1] = packh2(P0[m][2], P0[m][3]);
                A[m][2] = packh2(P1[m][0], P1[m][1]);
                A[m][3] = packh2(P1[m][2], P1[m][3]);
            }

            // PV: O += P[:, k0:k0+16] @ V[k0:k0+16, :]
            const int k0 = pr * 16;
#pragma unroll
            for (int dc = 0; dc < 4; dc++) {
                const uint32_t b0 = *(const uint32_t*)&Vst[dc * 8 + g][k0 + 2 * t4];
                const uint32_t b1 = *(const uint32_t*)&Vst[dc * 8 + g][k0 + 2 * t4 + 8];
                mma16h(O[0][dc], A[0], b0, b1);
                mma16h(O[1][dc], A[1], b0, b1);
            }
        }
    }

    // ---- store partials (unnormalized) ----
    const size_t pbase = ((size_t)split * (B_ * H_) + bh) * T_;
#pragma unroll
    for (int m = 0; m < 2; m++) {
        float l0 = lsum[m][0];
        l0 += __shfl_xor_sync(0xFFFFFFFFu, l0, 1);
        l0 += __shfl_xor_sync(0xFFFFFFFFu, l0, 2);
        float l1 = lsum[m][1];
        l1 += __shfl_xor_sync(0xFFFFFFFFu, l1, 1);
        l1 += __shfl_xor_sync(0xFFFFFFFFu, l1, 2);
        const int r0 = wq + m * 16 + g;
        if (t4 == 0) {
            g_pl[pbase + r0] = l0;
            g_pl[pbase + r0 + 8] = l1;
        }
        float* p0 = g_pacc + (pbase + r0) * HD;
        float* p1 = g_pacc + (pbase + r0 + 8) * HD;
#pragma unroll
        for (int dc = 0; dc < 4; dc++) {
            const int col = dc * 8 + 2 * t4;
            *(float2*)&p0[col] = make_float2(O[m][dc][0], O[m][dc][1]);
            *(float2*)&p1[col] = make_float2(O[m][dc][2], O[m][dc][3]);
        }
    }
}

// ---------------- combine splits -> g_ctx ------------------------------------
__global__ void __launch_bounds__(256) attn_combine() {
    const int idx = blockIdx.x * 256 + threadIdx.x;
    const int q_lin = idx >> 3;
    const int f = idx & 7;
    const int bh = q_lin >> 12;
    const int qi = q_lin & (T_ - 1);
    const int b = bh >> 2;
    const int h = bh & 3;

    float l = 0.f;
    float4 acc = make_float4(0.f, 0.f, 0.f, 0.f);
#pragma unroll
    for (int s = 0; s < KS; s++) {
        const size_t pb = ((size_t)s * (B_ * H_) + bh) * T_;
        l += g_pl[pb + qi];
        const float4 v = *(const float4*)(g_pacc + (pb + qi) * HD + f * 4);
        acc.x += v.x; acc.y += v.y; acc.z += v.z; acc.w += v.w;
    }
    const float inv = 1.f / l;
    float* op = g_ctx + ((size_t)b * T_ + qi) * DM + h * HD + f * 4;
    *(float4*)op = make_float4(acc.x * inv, acc.y * inv, acc.z * inv, acc.w * inv);
}

// ---------------- GEMM 2: out = g_ctx @ Wout --------------------------------
__global__ void __launch_bounds__(256) gemm_out(const float* __restrict__ W,
                                               float* __restrict__ out) {
    __shared__ float As[16][68];
    __shared__ float Ws[16][68];
    const int tx = threadIdx.x & 15;
    const int ty = threadIdx.x >> 4;
    const int m0 = blockIdx.x * 64;
    const int n0 = blockIdx.y * 64;

    float c[4][4];
#pragma unroll
    for (int i = 0; i < 4; i++)
#pragma unroll
        for (int j = 0; j < 4; j++) c[i][j] = 0.f;

    for (int k0 = 0; k0 < 128; k0 += 16) {
#pragma unroll
        for (int i = 0; i < 4; i++) {
            int lin = threadIdx.x + 256 * i;
            int m = lin >> 4, kk = lin & 15;
            As[kk][m] = g_ctx[(size_t)(m0 + m) * 128 + k0 + kk];
        }
#pragma unroll
        for (int i = 0; i < 4; i++) {
            int lin = threadIdx.x + 256 * i;
            int kk = lin >> 6, n = lin & 63;
            Ws[kk][n] = W[(size_t)(k0 + kk) * 128 + n0 + n];
        }
        __syncthreads();
#pragma unroll
        for (int kk = 0; kk < 16; kk++) {
            float4 a = *(const float4*)&As[kk][4 * ty];
            float4 b = *(const float4*)&Ws[kk][4 * tx];
            const float av[4] = {a.x, a.y, a.z, a.w};
            const float bv[4] = {b.x, b.y, b.z, b.w};
#pragma unroll
            for (int i = 0; i < 4; i++)
#pragma unroll
                for (int j = 0; j < 4; j++) c[i][j] = fmaf(av[i], bv[j], c[i][j]);
        }
        __syncthreads();
    }

#pragma unroll
    for (int i = 0; i < 4; i++) {
        const int m = m0 + 4 * ty + i;
#pragma unroll
        for (int j = 0; j < 4; j++) {
            const int n = n0 + 4 * tx + j;
            out[(size_t)m * 128 + n] = c[i][j];
        }
    }
}

// ---------------- launch ----------------------------------------------------
extern "C" void kernel_launch(void* const* d_in, const int* in_sizes, int n_in,
                              void* d_out, int out_size) {
    const float* x    = (const float*)d_in[0];
    const float* pk   = (const float*)d_in[1];
    const float* pv   = (const float*)d_in[2];
    const float* Wqkv = (const float*)d_in[3];
    const float* Wout = (const float*)d_in[4];
    float* out = (float*)d_out;

    {
        int n4 = B_ * H_ * P_ * HD / 4;
        prefix_copy<<<(n4 + 255) / 256, 256>>>((const float4*)pk, (const float4*)pv);
    }
    {
        dim3 grid(8192 / 64, 384 / 64);
        gemm_qkv<<<grid, 256>>>(x, Wqkv);
    }
    {
        dim3 grid(TK / 64, B_ * H_);
        v_transpose<<<grid, 128>>>();
    }
    {
        dim3 grid(32, KS, B_ * H_);
        attn_tc<<<grid, 128>>>();
    }
    {
        attn_combine<<<(B_ * H_ * T_ * 8) / 256, 256>>>();
    }
    {
        dim3 grid(8192 / 64, 128 / 64);
        gemm_out<<<grid, 256>>>(Wout, out);
    }
}

// round 10
// speedup vs baseline: 10.1501x; 1.4771x over previous
#include <cuda_runtime.h>
#include <cuda_fp16.h>
#include <cstdint>

// Problem constants
#define B_ 2
#define T_ 4096
#define H_ 4
#define HD 32
#define P_ 2048
#define TK 6144           // P_ + T_
#define DM 128            // D_MODEL
#define KS 4              // key splits
#define RSQRT_HD 0.17677669529663687f
#define LOG2E 1.4426950408889634f
#define QSCALE (RSQRT_HD * LOG2E)

// ---------------- scratch (device globals; no allocation allowed) ------------
__device__ __align__(16) __half g_xh[(size_t)B_ * T_ * DM];        // x fp16
__device__ __align__(16) __half g_wqkvT[(size_t)3 * DM * DM];      // Wqkv^T [384][128]
__device__ __align__(16) __half g_woutT[(size_t)DM * DM];          // Wout^T [128][128]
__device__ __align__(16) __half g_qh[(size_t)B_ * H_ * T_ * HD];   // pre-scaled by QSCALE
__device__ __align__(16) __half g_kh[(size_t)B_ * H_ * TK * HD];   // [bh][key][d]
__device__ __align__(16) __half g_vh[(size_t)B_ * H_ * TK * HD];   // [bh][key][d]
__device__ __align__(16) __half g_vt[(size_t)B_ * H_ * HD * TK];   // [bh][d][key]
__device__ __align__(16) __half g_ctxh[(size_t)B_ * T_ * DM];      // fp16 ctx
__device__ float g_pacc[(size_t)KS * B_ * H_ * T_ * HD];
__device__ float g_pl[(size_t)KS * B_ * H_ * T_];

// ---------------- helpers ----------------------------------------------------
__device__ __forceinline__ void mma16h(float* c, const uint32_t* a, uint32_t b0, uint32_t b1) {
    asm("mma.sync.aligned.m16n8k16.row.col.f32.f16.f16.f32 "
        "{%0,%1,%2,%3},{%4,%5,%6,%7},{%8,%9},{%0,%1,%2,%3};"
        : "+f"(c[0]), "+f"(c[1]), "+f"(c[2]), "+f"(c[3])
        : "r"(a[0]), "r"(a[1]), "r"(a[2]), "r"(a[3]), "r"(b0), "r"(b1));
}
__device__ __forceinline__ uint32_t packh2(float lo, float hi) {
    __half2 h = __float22half2_rn(make_float2(lo, hi));
    return *reinterpret_cast<uint32_t*>(&h);
}
__device__ __forceinline__ uint32_t ex2h2(uint32_t a) {
    uint32_t d;
    asm("ex2.approx.f16x2 %0, %1;" : "=r"(d) : "r"(a));
    return d;
}
#define ONE2 0x3C003C00u

// ---------------- prep: x -> fp16, transpose W's to [n][k] fp16 --------------
__global__ void __launch_bounds__(256) prep(const float4* __restrict__ x4,
                                            const float* __restrict__ Wqkv,
                                            const float* __restrict__ Wout) {
    const int i = blockIdx.x * 256 + threadIdx.x;
    if (i < (B_ * T_ * DM) / 4) {                       // 262144
        float4 v = x4[i];
        uint2 o = make_uint2(packh2(v.x, v.y), packh2(v.z, v.w));
        ((uint2*)g_xh)[i] = o;
    } else if (i < 262144 + 3 * DM * DM) {              // Wqkv^T: 49152
        const int j = i - 262144;
        const int n = j >> 7, k = j & 127;
        g_wqkvT[j] = __float2half_rn(Wqkv[k * 384 + n]);
    } else if (i < 262144 + 3 * DM * DM + DM * DM) {    // Wout^T: 16384
        const int j = i - 262144 - 3 * DM * DM;
        const int n = j >> 7, k = j & 127;
        g_woutT[j] = __float2half_rn(Wout[k * 128 + n]);
    }
}

// ---------------- prefix copy (K,V to fp16) ----------------------------------
__global__ void __launch_bounds__(256) prefix_copy(const float4* __restrict__ pk,
                                                   const float4* __restrict__ pv) {
    int idx = blockIdx.x * blockDim.x + threadIdx.x;
    if (idx < B_ * H_ * P_ * HD / 4) {
        const int per_bh = P_ * HD / 4;
        int bh = idx / per_bh;
        int rem = idx - bh * per_bh;
        float4 k = pk[idx];
        uint2 kk = make_uint2(packh2(k.x, k.y), packh2(k.z, k.w));
        *(uint2*)(g_kh + ((size_t)bh * TK * HD) + rem * 4) = kk;
        float4 v = pv[idx];
        uint2 vv = make_uint2(packh2(v.x, v.y), packh2(v.z, v.w));
        *(uint2*)(g_vh + ((size_t)bh * TK * HD) + rem * 4) = vv;
    }
}

// ---------------- TC GEMM 1: qkv = x @ Wqkv, scatter to g_qh/g_kh/g_vh -------
// Block 128 thr / 4 warps; tile M=128, N=64; K=128 in 2 chunks of 64.
__global__ void __launch_bounds__(128) gemm_qkv_tc() {
    __shared__ __half Ah[128][72];
    __shared__ __half Wts[64][72];
    const int tid = threadIdx.x;
    const int w = tid >> 5;
    const int lane = tid & 31;
    const int g = lane >> 2;
    const int t4 = lane & 3;
    const int m0 = blockIdx.x * 128;
    const int n0 = blockIdx.y * 64;

    float c[2][8][4];
#pragma unroll
    for (int m = 0; m < 2; m++)
#pragma unroll
        for (int nc = 0; nc < 8; nc++)
#pragma unroll
            for (int r = 0; r < 4; r++) c[m][nc][r] = 0.f;

    for (int k0 = 0; k0 < 128; k0 += 64) {
        __syncthreads();
        // Ah: 128 rows x 64 halves = 1024 uint4 (8 per thread)
#pragma unroll
        for (int i = 0; i < 8; i++) {
            const int f = tid + (i << 7);
            const int row = f >> 3, part = f & 7;
            *(uint4*)&Ah[row][part * 8] =
                *(const uint4*)(g_xh + (size_t)(m0 + row) * 128 + k0 + part * 8);
        }
        // Wts: 64 rows x 64 halves = 512 uint4 (4 per thread)
#pragma unroll
        for (int i = 0; i < 4; i++) {
            const int f = tid + (i << 7);
            const int row = f >> 3, part = f & 7;
            *(uint4*)&Wts[row][part * 8] =
                *(const uint4*)(g_wqkvT + (size_t)(n0 + row) * 128 + k0 + part * 8);
        }
        __syncthreads();

        uint32_t a[2][4][4];
#pragma unroll
        for (int m = 0; m < 2; m++) {
            const int r0 = w * 32 + m * 16 + g;
#pragma unroll
            for (int kc = 0; kc < 4; kc++) {
                const int cb = kc * 16 + 2 * t4;
                a[m][kc][0] = *(const uint32_t*)&Ah[r0][cb];
                a[m][kc][1] = *(const uint32_t*)&Ah[r0 + 8][cb];
                a[m][kc][2] = *(const uint32_t*)&Ah[r0][cb + 8];
                a[m][kc][3] = *(const uint32_t*)&Ah[r0 + 8][cb + 8];
            }
        }
#pragma unroll
        for (int nc = 0; nc < 8; nc++) {
#pragma unroll
            for (int kc = 0; kc < 4; kc++) {
                const uint32_t b0 = *(const uint32_t*)&Wts[nc * 8 + g][kc * 16 + 2 * t4];
                const uint32_t b1 = *(const uint32_t*)&Wts[nc * 8 + g][kc * 16 + 2 * t4 + 8];
                mma16h(c[0][nc], a[0][kc], b0, b1);
                mma16h(c[1][nc], a[1][kc], b0, b1);
            }
        }
    }

    // scatter epilogue (each 64-wide N tile lies in exactly one of q/k/v)
    const int sec = n0 >> 7;
    const int n0r = n0 & 127;
#pragma unroll
    for (int m = 0; m < 2; m++) {
#pragma unroll
        for (int rr = 0; rr < 2; rr++) {
            const int row = m0 + w * 32 + m * 16 + g + rr * 8;
            const int b = row >> 12;
            const int t = row & (T_ - 1);
#pragma unroll
            for (int nc = 0; nc < 8; nc++) {
                const int n = n0r + nc * 8 + 2 * t4;
                const int h = n >> 5;
                const int d = n & 31;
                const float v0 = c[m][nc][rr * 2 + 0];
                const float v1 = c[m][nc][rr * 2 + 1];
                if (sec == 0) {
                    *(uint32_t*)(g_qh + (((size_t)(b * H_ + h) * T_) + t) * HD + d) =
                        packh2(v0 * QSCALE, v1 * QSCALE);
                } else if (sec == 1) {
                    *(uint32_t*)(g_kh + (((size_t)(b * H_ + h) * TK) + P_ + t) * HD + d) =
                        packh2(v0, v1);
                } else {
                    *(uint32_t*)(g_vh + (((size_t)(b * H_ + h) * TK) + P_ + t) * HD + d) =
                        packh2(v0, v1);
                }
            }
        }
    }
}

// ---------------- V transpose: g_vh [bh][key][d] -> g_vt [bh][d][key] --------
__global__ void __launch_bounds__(128) v_transpose() {
    __shared__ __half S[HD][72];
    const int bh = blockIdx.y;
    const int j0 = blockIdx.x * 64;
    const int tid = threadIdx.x;

#pragma unroll
    for (int i = 0; i < 4; i++) {
        const int f = tid + i * 128;       // 0..511 uint2 groups (4 halves)
        const int key = f >> 3;
        const int d0 = (f & 7) * 4;
        uint2 v = *(const uint2*)(g_vh + ((size_t)bh * TK + j0 + key) * HD + d0);
        __half2 p0 = *(__half2*)&v.x;
        __half2 p1 = *(__half2*)&v.y;
        S[d0 + 0][key] = __low2half(p0);
        S[d0 + 1][key] = __high2half(p0);
        S[d0 + 2][key] = __low2half(p1);
        S[d0 + 3][key] = __high2half(p1);
    }
    __syncthreads();
#pragma unroll
    for (int i = 0; i < 2; i++) {
        const int f = tid + i * 128;       // 0..255 uint4s
        const int d = f >> 3;
        const int part = f & 7;
        *(uint4*)(g_vt + ((size_t)(bh * HD + d)) * TK + j0 + part * 8) =
            *(const uint4*)&S[d][part * 8];
    }
}

// ---------------- attention: fp16 mma, ex2.f16x2 softmax, ones-mma lsum ------
__global__ void __launch_bounds__(128) attn_tc() {
    __shared__ __half Kh[64][40];
    __shared__ __half Vst[HD][72];

    const int tid = threadIdx.x;
    const int w = tid >> 5;
    const int lane = tid & 31;
    const int g = lane >> 2;
    const int t4 = lane & 3;

    const int qt = 31 - blockIdx.x;      // heavy q-tiles first
    const int split = blockIdx.y;
    const int bh = blockIdx.z;
    const int q0 = qt * 128;
    const int wq = q0 + w * 32;

    // Q fragments (fp16, pre-scaled by 1/sqrt(hd)*log2e)
    uint32_t qa[2][2][4];
    {
        const __half* qb = g_qh + ((size_t)bh * T_) * HD;
#pragma unroll
        for (int m = 0; m < 2; m++) {
            const int r0 = wq + m * 16 + g;
#pragma unroll
            for (int kc = 0; kc < 2; kc++) {
                const int c = kc * 16 + 2 * t4;
                qa[m][kc][0] = *(const uint32_t*)(qb + (size_t)r0 * HD + c);
                qa[m][kc][1] = *(const uint32_t*)(qb + (size_t)(r0 + 8) * HD + c);
                qa[m][kc][2] = *(const uint32_t*)(qb + (size_t)r0 * HD + c + 8);
                qa[m][kc][3] = *(const uint32_t*)(qb + (size_t)(r0 + 8) * HD + c + 8);
            }
        }
    }

    float O[2][4][4];
    float Lc[2][4];                        // row-sum C-frags (ones-mma)
#pragma unroll
    for (int m = 0; m < 2; m++) {
#pragma unroll
        for (int dc = 0; dc < 4; dc++)
#pragma unroll
            for (int r = 0; r < 4; r++) O[m][dc][r] = 0.f;
#pragma unroll
        for (int r = 0; r < 4; r++) Lc[m][r] = 0.f;
    }

    const uint4* kb = (const uint4*)(g_kh + (size_t)bh * TK * HD);
    const int nfull = (P_ + q0) >> 6;
    const int ntot = nfull + 2;
    const int t_begin = (ntot * split) / KS;
    const int t_end = (ntot * (split + 1)) / KS;

    for (int t = t_begin; t < t_end; t++) {
        const int j0 = t << 6;
        __syncthreads();
#pragma unroll
        for (int i = 0; i < 2; i++) {
            const int f = tid + (i << 7);
            const int key = f >> 2;
            const int part = f & 3;
            *(uint4*)&Kh[key][part * 8] = kb[(size_t)j0 * 4 + f];
        }
#pragma unroll
        for (int i = 0; i < 2; i++) {
            const int f = tid + (i << 7);
            const int d = f >> 3;
            const int part = f & 7;
            *(uint4*)&Vst[d][part * 8] =
                *(const uint4*)(g_vt + ((size_t)(bh * HD + d)) * TK + j0 + part * 8);
        }
        __syncthreads();

        const bool isdiag = (t == nfull + (w >> 1));
        if (t > nfull && (w >> 1) == 0) continue;

#pragma unroll
        for (int pr = 0; pr < 4; pr++) {
            const int nc0 = 2 * pr, nc1 = 2 * pr + 1;
            float S0[2][4], S1[2][4];
#pragma unroll
            for (int m = 0; m < 2; m++)
#pragma unroll
                for (int r = 0; r < 4; r++) { S0[m][r] = 0.f; S1[m][r] = 0.f; }
#pragma unroll
            for (int kc = 0; kc < 2; kc++) {
                const int c = kc * 16 + 2 * t4;
                const uint32_t k0a = *(const uint32_t*)&Kh[nc0 * 8 + g][c];
                const uint32_t k0b = *(const uint32_t*)&Kh[nc0 * 8 + g][c + 8];
                mma16h(S0[0], qa[0][kc], k0a, k0b);
                mma16h(S0[1], qa[1][kc], k0a, k0b);
                const uint32_t k1a = *(const uint32_t*)&Kh[nc1 * 8 + g][c];
                const uint32_t k1b = *(const uint32_t*)&Kh[nc1 * 8 + g][c + 8];
                mma16h(S1[0], qa[0][kc], k1a, k1b);
                mma16h(S1[1], qa[1][kc], k1a, k1b);
            }

            if (isdiag) {
#pragma unroll
                for (int m = 0; m < 2; m++) {
                    const int rbase = 32 * (w & 1) + m * 16 + g;
                    const int c00 = nc0 * 8 + 2 * t4;
                    const int c10 = nc1 * 8 + 2 * t4;
                    S0[m][0] = (c00     <= rbase)     ? S0[m][0] : -100.f;
                    S0[m][1] = (c00 + 1 <= rbase)     ? S0[m][1] : -100.f;
                    S0[m][2] = (c00     <= rbase + 8) ? S0[m][2] : -100.f;
                    S0[m][3] = (c00 + 1 <= rbase + 8) ? S0[m][3] : -100.f;
                    S1[m][0] = (c10     <= rbase)     ? S1[m][0] : -100.f;
                    S1[m][1] = (c10 + 1 <= rbase)     ? S1[m][1] : -100.f;
                    S1[m][2] = (c10     <= rbase + 8) ? S1[m][2] : -100.f;
                    S1[m][3] = (c10 + 1 <= rbase + 8) ? S1[m][3] : -100.f;
                }
            }

            // P = 2^S via f16x2 MUFU; result IS the PV A-fragment
            uint32_t A[2][4];
#pragma unroll
            for (int m = 0; m < 2; m++) {
                A[m][0] = ex2h2(packh2(S0[m][0], S0[m][1]));
                A[m][1] = ex2h2(packh2(S0[m][2], S0[m][3]));
                A[m][2] = ex2h2(packh2(S1[m][0], S1[m][1]));
                A[m][3] = ex2h2(packh2(S1[m][2], S1[m][3]));
                mma16h(Lc[m], A[m], ONE2, ONE2);   // row sums on tensor pipe
            }

            const int k0 = pr * 16;
#pragma unroll
            for (int dc = 0; dc < 4; dc++) {
                const uint32_t b0 = *(const uint32_t*)&Vst[dc * 8 + g][k0 + 2 * t4];
                const uint32_t b1 = *(const uint32_t*)&Vst[dc * 8 + g][k0 + 2 * t4 + 8];
                mma16h(O[0][dc], A[0], b0, b1);
                mma16h(O[1][dc], A[1], b0, b1);
            }
        }
    }

    // store partials (Lc[m][0] = row-g sum; Lc[m][2] = row g+8 sum)
    const size_t pbase = ((size_t)split * (B_ * H_) + bh) * T_;
#pragma unroll
    for (int m = 0; m < 2; m++) {
        const int r0 = wq + m * 16 + g;
        if (t4 == 0) {
            g_pl[pbase + r0] = Lc[m][0];
            g_pl[pbase + r0 + 8] = Lc[m][2];
        }
        float* p0 = g_pacc + (pbase + r0) * HD;
        float* p1 = g_pacc + (pbase + r0 + 8) * HD;
#pragma unroll
        for (int dc = 0; dc < 4; dc++) {
            const int col = dc * 8 + 2 * t4;
            *(float2*)&p0[col] = make_float2(O[m][dc][0], O[m][dc][1]);
            *(float2*)&p1[col] = make_float2(O[m][dc][2], O[m][dc][3]);
        }
    }
}

// ---------------- combine splits -> g_ctxh (fp16) ----------------------------
__global__ void __launch_bounds__(256) attn_combine() {
    const int idx = blockIdx.x * 256 + threadIdx.x;
    const int q_lin = idx >> 3;
    const int f = idx & 7;
    const int bh = q_lin >> 12;
    const int qi = q_lin & (T_ - 1);
    const int b = bh >> 2;
    const int h = bh & 3;

    float l = 0.f;
    float4 acc = make_float4(0.f, 0.f, 0.f, 0.f);
#pragma unroll
    for (int s = 0; s < KS; s++) {
        const size_t pb = ((size_t)s * (B_ * H_) + bh) * T_;
        l += g_pl[pb + qi];
        const float4 v = *(const float4*)(g_pacc + (pb + qi) * HD + f * 4);
        acc.x += v.x; acc.y += v.y; acc.z += v.z; acc.w += v.w;
    }
    const float inv = 1.f / l;
    uint2 o = make_uint2(packh2(acc.x * inv, acc.y * inv),
                         packh2(acc.z * inv, acc.w * inv));
    *(uint2*)(g_ctxh + ((size_t)b * T_ + qi) * DM + h * HD + f * 4) = o;
}

// ---------------- TC GEMM 2: out = ctx @ Wout (fp32 out) ---------------------
__global__ void __launch_bounds__(128) gemm_out_tc(float* __restrict__ out) {
    __shared__ __half Ah[128][72];
    __shared__ __half Wts[64][72];
    const int tid = threadIdx.x;
    const int w = tid >> 5;
    const int lane = tid & 31;
    const int g = lane >> 2;
    const int t4 = lane & 3;
    const int m0 = blockIdx.x * 128;
    const int n0 = blockIdx.y * 64;

    float c[2][8][4];
#pragma unroll
    for (int m = 0; m < 2; m++)
#pragma unroll
        for (int nc = 0; nc < 8; nc++)
#pragma unroll
            for (int r = 0; r < 4; r++) c[m][nc][r] = 0.f;

    for (int k0 = 0; k0 < 128; k0 += 64) {
        __syncthreads();
        // Ah: 128 rows x 64 halves = 1024 uint4 (8 per thread)
#pragma unroll
        for (int i = 0; i < 8; i++) {
            const int f = tid + (i << 7);
            const int row = f >> 3, part = f & 7;
            *(uint4*)&Ah[row][part * 8] =
                *(const uint4*)(g_ctxh + (size_t)(m0 + row) * 128 + k0 + part * 8);
        }
        // Wts: 64 rows x 64 halves = 512 uint4 (4 per thread)
#pragma unroll
        for (int i = 0; i < 4; i++) {
            const int f = tid + (i << 7);
            const int row = f >> 3, part = f & 7;
            *(uint4*)&Wts[row][part * 8] =
                *(const uint4*)(g_woutT + (size_t)(n0 + row) * 128 + k0 + part * 8);
        }
        __syncthreads();

        uint32_t a[2][4][4];
#pragma unroll
        for (int m = 0; m < 2; m++) {
            const int r0 = w * 32 + m * 16 + g;
#pragma unroll
            for (int kc = 0; kc < 4; kc++) {
                const int cb = kc * 16 + 2 * t4;
                a[m][kc][0] = *(const uint32_t*)&Ah[r0][cb];
                a[m][kc][1] = *(const uint32_t*)&Ah[r0 + 8][cb];
                a[m][kc][2] = *(const uint32_t*)&Ah[r0][cb + 8];
                a[m][kc][3] = *(const uint32_t*)&Ah[r0 + 8][cb + 8];
            }
        }
#pragma unroll
        for (int nc = 0; nc < 8; nc++) {
#pragma unroll
            for (int kc = 0; kc < 4; kc++) {
                const uint32_t b0 = *(const uint32_t*)&Wts[nc * 8 + g][kc * 16 + 2 * t4];
                const uint32_t b1 = *(const uint32_t*)&Wts[nc * 8 + g][kc * 16 + 2 * t4 + 8];
                mma16h(c[0][nc], a[0][kc], b0, b1);
                mma16h(c[1][nc], a[1][kc], b0, b1);
            }
        }
    }

#pragma unroll
    for (int m = 0; m < 2; m++) {
#pragma unroll
        for (int rr = 0; rr < 2; rr++) {
            const int row = m0 + w * 32 + m * 16 + g + rr * 8;
#pragma unroll
            for (int nc = 0; nc < 8; nc++) {
                const int n = n0 + nc * 8 + 2 * t4;
                *(float2*)(out + (size_t)row * 128 + n) =
                    make_float2(c[m][nc][rr * 2 + 0], c[m][nc][rr * 2 + 1]);
            }
        }
    }
}

// ---------------- launch ----------------------------------------------------
extern "C" void kernel_launch(void* const* d_in, const int* in_sizes, int n_in,
                              void* d_out, int out_size) {
    const float* x    = (const float*)d_in[0];
    const float* pk   = (const float*)d_in[1];
    const float* pv   = (const float*)d_in[2];
    const float* Wqkv = (const float*)d_in[3];
    const float* Wout = (const float*)d_in[4];
    float* out = (float*)d_out;

    prep<<<1280, 256>>>((const float4*)x, Wqkv, Wout);
    {
        int n4 = B_ * H_ * P_ * HD / 4;
        prefix_copy<<<(n4 + 255) / 256, 256>>>((const float4*)pk, (const float4*)pv);
    }
    {
        dim3 grid(64, 6);
        gemm_qkv_tc<<<grid, 128>>>();
    }
    {
        dim3 grid(TK / 64, B_ * H_);
        v_transpose<<<grid, 128>>>();
    }
    {
        dim3 grid(32, KS, B_ * H_);
        attn_tc<<<grid, 128>>>();
    }
    {
        attn_combine<<<(B_ * H_ * T_ * 8) / 256, 256>>>();
    }
    {
        dim3 grid(64, 2);
        gemm_out_tc<<<grid, 128>>>(out);
    }
}

// round 11
// speedup vs baseline: 10.5621x; 1.0406x over previous
#include <cuda_runtime.h>
#include <cuda_fp16.h>
#include <cstdint>

// Problem constants
#define B_ 2
#define T_ 4096
#define H_ 4
#define HD 32
#define P_ 2048
#define TK 6144           // P_ + T_
#define DM 128            // D_MODEL
#define KS 4              // key splits
#define RSQRT_HD 0.17677669529663687f
#define LOG2E 1.4426950408889634f
#define QSCALE (RSQRT_HD * LOG2E)

// ---------------- scratch (device globals; no allocation allowed) ------------
__device__ __align__(16) __half g_xh[(size_t)B_ * T_ * DM];        // x fp16
__device__ __align__(16) __half g_wqkvT[(size_t)3 * DM * DM];      // Wqkv^T [384][128]
__device__ __align__(16) __half g_woutT[(size_t)DM * DM];          // Wout^T [128][128]
__device__ __align__(16) __half g_qh[(size_t)B_ * H_ * T_ * HD];   // pre-scaled by QSCALE
__device__ __align__(16) __half g_kh[(size_t)B_ * H_ * TK * HD];   // [bh][key][d]
__device__ __align__(16) __half g_vh[(size_t)B_ * H_ * TK * HD];   // [bh][key][d]
__device__ __align__(16) __half g_vt[(size_t)B_ * H_ * HD * TK];   // [bh][d][key]
__device__ __align__(16) __half g_ctxh[(size_t)B_ * T_ * DM];      // fp16 ctx
__device__ float g_pacc[(size_t)KS * B_ * H_ * T_ * HD];
__device__ float g_pl[(size_t)KS * B_ * H_ * T_];

// ---------------- helpers ----------------------------------------------------
__device__ __forceinline__ void mma16h(float* c, const uint32_t* a, uint32_t b0, uint32_t b1) {
    asm("mma.sync.aligned.m16n8k16.row.col.f32.f16.f16.f32 "
        "{%0,%1,%2,%3},{%4,%5,%6,%7},{%8,%9},{%0,%1,%2,%3};"
        : "+f"(c[0]), "+f"(c[1]), "+f"(c[2]), "+f"(c[3])
        : "r"(a[0]), "r"(a[1]), "r"(a[2]), "r"(a[3]), "r"(b0), "r"(b1));
}
__device__ __forceinline__ uint32_t packh2(float lo, float hi) {
    __half2 h = __float22half2_rn(make_float2(lo, hi));
    return *reinterpret_cast<uint32_t*>(&h);
}
__device__ __forceinline__ uint32_t ex2h2(uint32_t a) {
    uint32_t d;
    asm("ex2.approx.f16x2 %0, %1;" : "=r"(d) : "r"(a));
    return d;
}
__device__ __forceinline__ void cp16(void* sptr, const void* gptr) {
    uint32_t sa = (uint32_t)__cvta_generic_to_shared(sptr);
    asm volatile("cp.async.ca.shared.global [%0], [%1], 16;" :: "r"(sa), "l"(gptr) : "memory");
}
#define CP_COMMIT() asm volatile("cp.async.commit_group;" ::: "memory")
#define ONE2 0x3C003C00u

// ---------------- prep: x->fp16, W transposes, prefix K/V -> fp16 ------------
__global__ void __launch_bounds__(256) prep_all(const float4* __restrict__ x4,
                                                const float* __restrict__ Wqkv,
                                                const float* __restrict__ Wout,
                                                const float4* __restrict__ pk,
                                                const float4* __restrict__ pv) {
    const int i = blockIdx.x * 256 + threadIdx.x;
    if (i < 262144) {                                   // x: B*T*DM/4 uint2 stores
        float4 v = x4[i];
        uint2 o = make_uint2(packh2(v.x, v.y), packh2(v.z, v.w));
        ((uint2*)g_xh)[i] = o;
    } else if (i < 262144 + 49152) {                    // Wqkv^T
        const int j = i - 262144;
        const int n = j >> 7, k = j & 127;
        g_wqkvT[j] = __float2half_rn(Wqkv[k * 384 + n]);
    } else if (i < 262144 + 49152 + 16384) {            // Wout^T
        const int j = i - 262144 - 49152;
        const int n = j >> 7, k = j & 127;
        g_woutT[j] = __float2half_rn(Wout[k * 128 + n]);
    } else if (i < 262144 + 49152 + 16384 + 131072) {   // prefix K/V
        const int idx = i - 262144 - 49152 - 16384;
        const int per_bh = P_ * HD / 4;
        const int bh = idx / per_bh;
        const int rem = idx - bh * per_bh;
        float4 k = pk[idx];
        uint2 kk = make_uint2(packh2(k.x, k.y), packh2(k.z, k.w));
        *(uint2*)(g_kh + ((size_t)bh * TK * HD) + rem * 4) = kk;
        float4 v = pv[idx];
        uint2 vv = make_uint2(packh2(v.x, v.y), packh2(v.z, v.w));
        *(uint2*)(g_vh + ((size_t)bh * TK * HD) + rem * 4) = vv;
    }
}

// ---------------- TC GEMM 1: qkv = x @ Wqkv, scatter to g_qh/g_kh/g_vh -------
__global__ void __launch_bounds__(128) gemm_qkv_tc() {
    __shared__ __half Ah[128][72];
    __shared__ __half Wts[64][72];
    const int tid = threadIdx.x;
    const int w = tid >> 5;
    const int lane = tid & 31;
    const int g = lane >> 2;
    const int t4 = lane & 3;
    const int m0 = blockIdx.x * 128;
    const int n0 = blockIdx.y * 64;

    float c[2][8][4];
#pragma unroll
    for (int m = 0; m < 2; m++)
#pragma unroll
        for (int nc = 0; nc < 8; nc++)
#pragma unroll
            for (int r = 0; r < 4; r++) c[m][nc][r] = 0.f;

    for (int k0 = 0; k0 < 128; k0 += 64) {
        __syncthreads();
#pragma unroll
        for (int i = 0; i < 8; i++) {
            const int f = tid + (i << 7);
            const int row = f >> 3, part = f & 7;
            *(uint4*)&Ah[row][part * 8] =
                *(const uint4*)(g_xh + (size_t)(m0 + row) * 128 + k0 + part * 8);
        }
#pragma unroll
        for (int i = 0; i < 4; i++) {
            const int f = tid + (i << 7);
            const int row = f >> 3, part = f & 7;
            *(uint4*)&Wts[row][part * 8] =
                *(const uint4*)(g_wqkvT + (size_t)(n0 + row) * 128 + k0 + part * 8);
        }
        __syncthreads();

        uint32_t a[2][4][4];
#pragma unroll
        for (int m = 0; m < 2; m++) {
            const int r0 = w * 32 + m * 16 + g;
#pragma unroll
            for (int kc = 0; kc < 4; kc++) {
                const int cb = kc * 16 + 2 * t4;
                a[m][kc][0] = *(const uint32_t*)&Ah[r0][cb];
                a[m][kc][1] = *(const uint32_t*)&Ah[r0 + 8][cb];
                a[m][kc][2] = *(const uint32_t*)&Ah[r0][cb + 8];
                a[m][kc][3] = *(const uint32_t*)&Ah[r0 + 8][cb + 8];
            }
        }
#pragma unroll
        for (int nc = 0; nc < 8; nc++) {
#pragma unroll
            for (int kc = 0; kc < 4; kc++) {
                const uint32_t b0 = *(const uint32_t*)&Wts[nc * 8 + g][kc * 16 + 2 * t4];
                const uint32_t b1 = *(const uint32_t*)&Wts[nc * 8 + g][kc * 16 + 2 * t4 + 8];
                mma16h(c[0][nc], a[0][kc], b0, b1);
                mma16h(c[1][nc], a[1][kc], b0, b1);
            }
        }
    }

    const int sec = n0 >> 7;
    const int n0r = n0 & 127;
#pragma unroll
    for (int m = 0; m < 2; m++) {
#pragma unroll
        for (int rr = 0; rr < 2; rr++) {
            const int row = m0 + w * 32 + m * 16 + g + rr * 8;
            const int b = row >> 12;
            const int t = row & (T_ - 1);
#pragma unroll
            for (int nc = 0; nc < 8; nc++) {
                const int n = n0r + nc * 8 + 2 * t4;
                const int h = n >> 5;
                const int d = n & 31;
                const float v0 = c[m][nc][rr * 2 + 0];
                const float v1 = c[m][nc][rr * 2 + 1];
                if (sec == 0) {
                    *(uint32_t*)(g_qh + (((size_t)(b * H_ + h) * T_) + t) * HD + d) =
                        packh2(v0 * QSCALE, v1 * QSCALE);
                } else if (sec == 1) {
                    *(uint32_t*)(g_kh + (((size_t)(b * H_ + h) * TK) + P_ + t) * HD + d) =
                        packh2(v0, v1);
                } else {
                    *(uint32_t*)(g_vh + (((size_t)(b * H_ + h) * TK) + P_ + t) * HD + d) =
                        packh2(v0, v1);
                }
            }
        }
    }
}

// ---------------- V transpose: g_vh [bh][key][d] -> g_vt [bh][d][key] --------
__global__ void __launch_bounds__(128) v_transpose() {
    __shared__ __half S[HD][72];
    const int bh = blockIdx.y;
    const int j0 = blockIdx.x * 64;
    const int tid = threadIdx.x;

#pragma unroll
    for (int i = 0; i < 4; i++) {
        const int f = tid + i * 128;
        const int key = f >> 3;
        const int d0 = (f & 7) * 4;
        uint2 v = *(const uint2*)(g_vh + ((size_t)bh * TK + j0 + key) * HD + d0);
        __half2 p0 = *(__half2*)&v.x;
        __half2 p1 = *(__half2*)&v.y;
        S[d0 + 0][key] = __low2half(p0);
        S[d0 + 1][key] = __high2half(p0);
        S[d0 + 2][key] = __low2half(p1);
        S[d0 + 3][key] = __high2half(p1);
    }
    __syncthreads();
#pragma unroll
    for (int i = 0; i < 2; i++) {
        const int f = tid + i * 128;
        const int d = f >> 3;
        const int part = f & 7;
        *(uint4*)(g_vt + ((size_t)(bh * HD + d)) * TK + j0 + part * 8) =
            *(const uint4*)&S[d][part * 8];
    }
}

// ---------------- attention: fp16 mma, ex2 softmax, cp.async double-buffer ---
__global__ void __launch_bounds__(128) attn_tc() {
    __shared__ __half Kh[2][64][40];
    __shared__ __half Vst[2][HD][72];

    const int tid = threadIdx.x;
    const int w = tid >> 5;
    const int lane = tid & 31;
    const int g = lane >> 2;
    const int t4 = lane & 3;

    const int qt = 31 - blockIdx.x;      // heavy q-tiles first
    const int split = blockIdx.y;
    const int bh = blockIdx.z;
    const int q0 = qt * 128;
    const int wq = q0 + w * 32;

    // Q fragments (fp16, pre-scaled by 1/sqrt(hd)*log2e)
    uint32_t qa[2][2][4];
    {
        const __half* qb = g_qh + ((size_t)bh * T_) * HD;
#pragma unroll
        for (int m = 0; m < 2; m++) {
            const int r0 = wq + m * 16 + g;
#pragma unroll
            for (int kc = 0; kc < 2; kc++) {
                const int c = kc * 16 + 2 * t4;
                qa[m][kc][0] = *(const uint32_t*)(qb + (size_t)r0 * HD + c);
                qa[m][kc][1] = *(const uint32_t*)(qb + (size_t)(r0 + 8) * HD + c);
                qa[m][kc][2] = *(const uint32_t*)(qb + (size_t)r0 * HD + c + 8);
                qa[m][kc][3] = *(const uint32_t*)(qb + (size_t)(r0 + 8) * HD + c + 8);
            }
        }
    }

    float O[2][4][4];
    float Lc[2][4];
#pragma unroll
    for (int m = 0; m < 2; m++) {
#pragma unroll
        for (int dc = 0; dc < 4; dc++)
#pragma unroll
            for (int r = 0; r < 4; r++) O[m][dc][r] = 0.f;
#pragma unroll
        for (int r = 0; r < 4; r++) Lc[m][r] = 0.f;
    }

    const uint4* kb = (const uint4*)(g_kh + (size_t)bh * TK * HD);
    const __half* vtb = g_vt + (size_t)bh * HD * TK;
    const int nfull = (P_ + q0) >> 6;
    const int ntot = nfull + 2;
    const int t_begin = (ntot * split) / KS;
    const int t_end = (ntot * (split + 1)) / KS;

    // async tile loader: K 256 uint4, V 256 uint4 (2 each per thread)
    auto load_tile = [&](int t, int buf) {
        const int j0 = t << 6;
#pragma unroll
        for (int i = 0; i < 2; i++) {
            const int f = tid + (i << 7);
            const int key = f >> 2;
            const int part = f & 3;
            cp16(&Kh[buf][key][part * 8], kb + (size_t)j0 * 4 + f);
        }
#pragma unroll
        for (int i = 0; i < 2; i++) {
            const int f = tid + (i << 7);
            const int d = f >> 3;
            const int part = f & 7;
            cp16(&Vst[buf][d][part * 8], vtb + (size_t)d * TK + j0 + part * 8);
        }
        CP_COMMIT();
    };

    load_tile(t_begin, 0);

    for (int t = t_begin; t < t_end; t++) {
        const int cur = (t - t_begin) & 1;
        const bool more = (t + 1 < t_end);
        if (more) {
            load_tile(t + 1, cur ^ 1);
            asm volatile("cp.async.wait_group 1;" ::: "memory");
        } else {
            asm volatile("cp.async.wait_group 0;" ::: "memory");
        }
        __syncthreads();

        const bool isdiag = (t == nfull + (w >> 1));
        const bool active = !(t > nfull && (w >> 1) == 0);
        if (active) {
#pragma unroll
            for (int pr = 0; pr < 4; pr++) {
                const int nc0 = 2 * pr, nc1 = 2 * pr + 1;
                float S0[2][4], S1[2][4];
#pragma unroll
                for (int m = 0; m < 2; m++)
#pragma unroll
                    for (int r = 0; r < 4; r++) { S0[m][r] = 0.f; S1[m][r] = 0.f; }
#pragma unroll
                for (int kc = 0; kc < 2; kc++) {
                    const int c = kc * 16 + 2 * t4;
                    const uint32_t k0a = *(const uint32_t*)&Kh[cur][nc0 * 8 + g][c];
                    const uint32_t k0b = *(const uint32_t*)&Kh[cur][nc0 * 8 + g][c + 8];
                    mma16h(S0[0], qa[0][kc], k0a, k0b);
                    mma16h(S0[1], qa[1][kc], k0a, k0b);
                    const uint32_t k1a = *(const uint32_t*)&Kh[cur][nc1 * 8 + g][c];
                    const uint32_t k1b = *(const uint32_t*)&Kh[cur][nc1 * 8 + g][c + 8];
                    mma16h(S1[0], qa[0][kc], k1a, k1b);
                    mma16h(S1[1], qa[1][kc], k1a, k1b);
                }

                if (isdiag) {
#pragma unroll
                    for (int m = 0; m < 2; m++) {
                        const int rbase = 32 * (w & 1) + m * 16 + g;
                        const int c00 = nc0 * 8 + 2 * t4;
                        const int c10 = nc1 * 8 + 2 * t4;
                        S0[m][0] = (c00     <= rbase)     ? S0[m][0] : -100.f;
                        S0[m][1] = (c00 + 1 <= rbase)     ? S0[m][1] : -100.f;
                        S0[m][2] = (c00     <= rbase + 8) ? S0[m][2] : -100.f;
                        S0[m][3] = (c00 + 1 <= rbase + 8) ? S0[m][3] : -100.f;
                        S1[m][0] = (c10     <= rbase)     ? S1[m][0] : -100.f;
                        S1[m][1] = (c10 + 1 <= rbase)     ? S1[m][1] : -100.f;
                        S1[m][2] = (c10     <= rbase + 8) ? S1[m][2] : -100.f;
                        S1[m][3] = (c10 + 1 <= rbase + 8) ? S1[m][3] : -100.f;
                    }
                }

                // P = 2^S via f16x2 MUFU; result IS the PV A-fragment
                uint32_t A[2][4];
#pragma unroll
                for (int m = 0; m < 2; m++) {
                    A[m][0] = ex2h2(packh2(S0[m][0], S0[m][1]));
                    A[m][1] = ex2h2(packh2(S0[m][2], S0[m][3]));
                    A[m][2] = ex2h2(packh2(S1[m][0], S1[m][1]));
                    A[m][3] = ex2h2(packh2(S1[m][2], S1[m][3]));
                    mma16h(Lc[m], A[m], ONE2, ONE2);   // row sums on tensor pipe
                }

                const int k0 = pr * 16;
#pragma unroll
                for (int dc = 0; dc < 4; dc++) {
                    const uint32_t b0 = *(const uint32_t*)&Vst[cur][dc * 8 + g][k0 + 2 * t4];
                    const uint32_t b1 = *(const uint32_t*)&Vst[cur][dc * 8 + g][k0 + 2 * t4 + 8];
                    mma16h(O[0][dc], A[0], b0, b1);
                    mma16h(O[1][dc], A[1], b0, b1);
                }
            }
        }
        __syncthreads();
    }

    // store partials (Lc[m][0] = row-g sum; Lc[m][2] = row g+8 sum)
    const size_t pbase = ((size_t)split * (B_ * H_) + bh) * T_;
#pragma unroll
    for (int m = 0; m < 2; m++) {
        const int r0 = wq + m * 16 + g;
        if (t4 == 0) {
            g_pl[pbase + r0] = Lc[m][0];
            g_pl[pbase + r0 + 8] = Lc[m][2];
        }
        float* p0 = g_pacc + (pbase + r0) * HD;
        float* p1 = g_pacc + (pbase + r0 + 8) * HD;
#pragma unroll
        for (int dc = 0; dc < 4; dc++) {
            const int col = dc * 8 + 2 * t4;
            *(float2*)&p0[col] = make_float2(O[m][dc][0], O[m][dc][1]);
            *(float2*)&p1[col] = make_float2(O[m][dc][2], O[m][dc][3]);
        }
    }
}

// ---------------- combine splits -> g_ctxh (fp16) ----------------------------
__global__ void __launch_bounds__(256) attn_combine() {
    const int idx = blockIdx.x * 256 + threadIdx.x;
    const int q_lin = idx >> 3;
    const int f = idx & 7;
    const int bh = q_lin >> 12;
    const int qi = q_lin & (T_ - 1);
    const int b = bh >> 2;
    const int h = bh & 3;

    float l = 0.f;
    float4 acc = make_float4(0.f, 0.f, 0.f, 0.f);
#pragma unroll
    for (int s = 0; s < KS; s++) {
        const size_t pb = ((size_t)s * (B_ * H_) + bh) * T_;
        l += g_pl[pb + qi];
        const float4 v = *(const float4*)(g_pacc + (pb + qi) * HD + f * 4);
        acc.x += v.x; acc.y += v.y; acc.z += v.z; acc.w += v.w;
    }
    const float inv = 1.f / l;
    uint2 o = make_uint2(packh2(acc.x * inv, acc.y * inv),
                         packh2(acc.z * inv, acc.w * inv));
    *(uint2*)(g_ctxh + ((size_t)b * T_ + qi) * DM + h * HD + f * 4) = o;
}

// ---------------- TC GEMM 2: out = ctx @ Wout (fp32 out) ---------------------
__global__ void __launch_bounds__(128) gemm_out_tc(float* __restrict__ out) {
    __shared__ __half Ah[128][72];
    __shared__ __half Wts[64][72];
    const int tid = threadIdx.x;
    const int w = tid >> 5;
    const int lane = tid & 31;
    const int g = lane >> 2;
    const int t4 = lane & 3;
    const int m0 = blockIdx.x * 128;
    const int n0 = blockIdx.y * 64;

    float c[2][8][4];
#pragma unroll
    for (int m = 0; m < 2; m++)
#pragma unroll
        for (int nc = 0; nc < 8; nc++)
#pragma unroll
            for (int r = 0; r < 4; r++) c[m][nc][r] = 0.f;

    for (int k0 = 0; k0 < 128; k0 += 64) {
        __syncthreads();
#pragma unroll
        for (int i = 0; i < 8; i++) {
            const int f = tid + (i << 7);
            const int row = f >> 3, part = f & 7;
            *(uint4*)&Ah[row][part * 8] =
                *(const uint4*)(g_ctxh + (size_t)(m0 + row) * 128 + k0 + part * 8);
        }
#pragma unroll
        for (int i = 0; i < 4; i++) {
            const int f = tid + (i << 7);
            const int row = f >> 3, part = f & 7;
            *(uint4*)&Wts[row][part * 8] =
                *(const uint4*)(g_woutT + (size_t)(n0 + row) * 128 + k0 + part * 8);
        }
        __syncthreads();

        uint32_t a[2][4][4];
#pragma unroll
        for (int m = 0; m < 2; m++) {
            const int r0 = w * 32 + m * 16 + g;
#pragma unroll
            for (int kc = 0; kc < 4; kc++) {
                const int cb = kc * 16 + 2 * t4;
                a[m][kc][0] = *(const uint32_t*)&Ah[r0][cb];
                a[m][kc][1] = *(const uint32_t*)&Ah[r0 + 8][cb];
                a[m][kc][2] = *(const uint32_t*)&Ah[r0][cb + 8];
                a[m][kc][3] = *(const uint32_t*)&Ah[r0 + 8][cb + 8];
            }
        }
#pragma unroll
        for (int nc = 0; nc < 8; nc++) {
#pragma unroll
            for (int kc = 0; kc < 4; kc++) {
                const uint32_t b0 = *(const uint32_t*)&Wts[nc * 8 + g][kc * 16 + 2 * t4];
                const uint32_t b1 = *(const uint32_t*)&Wts[nc * 8 + g][kc * 16 + 2 * t4 + 8];
                mma16h(c[0][nc], a[0][kc], b0, b1);
                mma16h(c[1][nc], a[1][kc], b0, b1);
            }
        }
    }

#pragma unroll
    for (int m = 0; m < 2; m++) {
#pragma unroll
        for (int rr = 0; rr < 2; rr++) {
            const int row = m0 + w * 32 + m * 16 + g + rr * 8;
#pragma unroll
            for (int nc = 0; nc < 8; nc++) {
                const int n = n0 + nc * 8 + 2 * t4;
                *(float2*)(out + (size_t)row * 128 + n) =
                    make_float2(c[m][nc][rr * 2 + 0], c[m][nc][rr * 2 + 1]);
            }
        }
    }
}

// ---------------- launch ----------------------------------------------------
extern "C" void kernel_launch(void* const* d_in, const int* in_sizes, int n_in,
                              void* d_out, int out_size) {
    const float* x    = (const float*)d_in[0];
    const float* pk   = (const float*)d_in[1];
    const float* pv   = (const float*)d_in[2];
    const float* Wqkv = (const float*)d_in[3];
    const float* Wout = (const float*)d_in[4];
    float* out = (float*)d_out;

    prep_all<<<1792, 256>>>((const float4*)x, Wqkv, Wout,
                            (const float4*)pk, (const float4*)pv);
    {
        dim3 grid(64, 6);
        gemm_qkv_tc<<<grid, 128>>>();
    }
    {
        dim3 grid(TK / 64, B_ * H_);
        v_transpose<<<grid, 128>>>();
    }
    {
        dim3 grid(32, KS, B_ * H_);
        attn_tc<<<grid, 128>>>();
    }
    {
        attn_combine<<<(B_ * H_ * T_ * 8) / 256, 256>>>();
    }
    {
        dim3 grid(64, 2);
        gemm_out_tc<<<grid, 128>>>(out);
    }
}

// round 14
// speedup vs baseline: 10.6087x; 1.0044x over previous
#include <cuda_runtime.h>
#include <cuda_fp16.h>
#include <cstdint>

// Problem constants
#define B_ 2
#define T_ 4096
#define H_ 4
#define HD 32
#define P_ 2048
#define TK 6144           // P_ + T_
#define DM 128            // D_MODEL
#define KS 4              // key splits
#define RSQRT_HD 0.17677669529663687f
#define LOG2E 1.4426950408889634f
#define QSCALE (RSQRT_HD * LOG2E)

// ---------------- scratch (device globals; no allocation allowed) ------------
__device__ __align__(16) __half g_xh[(size_t)B_ * T_ * DM];        // x fp16
__device__ __align__(16) __half g_wqkvT[(size_t)3 * DM * DM];      // Wqkv^T [384][128]
__device__ __align__(16) __half g_woutT[(size_t)DM * DM];          // Wout^T [128][128]
__device__ __align__(16) __half g_qh[(size_t)B_ * H_ * T_ * HD];   // pre-scaled by QSCALE
__device__ __align__(16) __half g_kh[(size_t)B_ * H_ * TK * HD];   // [bh][key][d]
__device__ __align__(16) __half g_vh[(size_t)B_ * H_ * TK * HD];   // [bh][key][d]
__device__ __align__(16) __half g_vt[(size_t)B_ * H_ * HD * TK];   // [bh][d][key]
__device__ __align__(16) __half g_ctxh[(size_t)B_ * T_ * DM];      // fp16 ctx
__device__ float g_pacc[(size_t)KS * B_ * H_ * T_ * HD];
__device__ float g_pl[(size_t)KS * B_ * H_ * T_];

// ---------------- helpers ----------------------------------------------------
__device__ __forceinline__ void mma16h(float* c, const uint32_t* a, uint32_t b0, uint32_t b1) {
    asm("mma.sync.aligned.m16n8k16.row.col.f32.f16.f16.f32 "
        "{%0,%1,%2,%3},{%4,%5,%6,%7},{%8,%9},{%0,%1,%2,%3};"
        : "+f"(c[0]), "+f"(c[1]), "+f"(c[2]), "+f"(c[3])
        : "r"(a[0]), "r"(a[1]), "r"(a[2]), "r"(a[3]), "r"(b0), "r"(b1));
}
__device__ __forceinline__ uint32_t packh2(float lo, float hi) {
    __half2 h = __float22half2_rn(make_float2(lo, hi));
    return *reinterpret_cast<uint32_t*>(&h);
}
__device__ __forceinline__ uint32_t ex2h2(uint32_t a) {
    uint32_t d;
    asm("ex2.approx.f16x2 %0, %1;" : "=r"(d) : "r"(a));
    return d;
}
__device__ __forceinline__ void cp16(void* sptr, const void* gptr) {
    uint32_t sa = (uint32_t)__cvta_generic_to_shared(sptr);
    asm volatile("cp.async.ca.shared.global [%0], [%1], 16;" :: "r"(sa), "l"(gptr) : "memory");
}
__device__ __forceinline__ void ldsm4(uint32_t* r, const void* p) {
    uint32_t a = (uint32_t)__cvta_generic_to_shared(p);
    asm volatile("ldmatrix.sync.aligned.m8n8.x4.shared.b16 {%0,%1,%2,%3}, [%4];"
        : "=r"(r[0]), "=r"(r[1]), "=r"(r[2]), "=r"(r[3]) : "r"(a));
}
#define CP_COMMIT() asm volatile("cp.async.commit_group;" ::: "memory")
#define ONE2 0x3C003C00u

// ---------------- prep: x->fp16, W transposes, prefix K/V -> fp16 ------------
__global__ void __launch_bounds__(256) prep_all(const float4* __restrict__ x4,
                                                const float* __restrict__ Wqkv,
                                                const float* __restrict__ Wout,
                                                const float4* __restrict__ pk,
                                                const float4* __restrict__ pv) {
    const int i = blockIdx.x * 256 + threadIdx.x;
    if (i < 262144) {                                   // x: B*T*DM/4 uint2 stores
        float4 v = x4[i];
        uint2 o = make_uint2(packh2(v.x, v.y), packh2(v.z, v.w));
        ((uint2*)g_xh)[i] = o;
    } else if (i < 262144 + 49152) {                    // Wqkv^T
        const int j = i - 262144;
        const int n = j >> 7, k = j & 127;
        g_wqkvT[j] = __float2half_rn(Wqkv[k * 384 + n]);
    } else if (i < 262144 + 49152 + 16384) {            // Wout^T
        const int j = i - 262144 - 49152;
        const int n = j >> 7, k = j & 127;
        g_woutT[j] = __float2half_rn(Wout[k * 128 + n]);
    } else if (i < 262144 + 49152 + 16384 + 131072) {   // prefix K/V
        const int idx = i - 262144 - 49152 - 16384;
        const int per_bh = P_ * HD / 4;
        const int bh = idx / per_bh;
        const int rem = idx - bh * per_bh;
        float4 k = pk[idx];
        uint2 kk = make_uint2(packh2(k.x, k.y), packh2(k.z, k.w));
        *(uint2*)(g_kh + ((size_t)bh * TK * HD) + rem * 4) = kk;
        float4 v = pv[idx];
        uint2 vv = make_uint2(packh2(v.x, v.y), packh2(v.z, v.w));
        *(uint2*)(g_vh + ((size_t)bh * TK * HD) + rem * 4) = vv;
    }
}

// ---------------- TC GEMM 1: qkv = x @ Wqkv, scatter to g_qh/g_kh/g_vh -------
__global__ void __launch_bounds__(128) gemm_qkv_tc() {
    __shared__ __half Ah[128][72];
    __shared__ __half Wts[64][72];
    const int tid = threadIdx.x;
    const int w = tid >> 5;
    const int lane = tid & 31;
    const int g = lane >> 2;
    const int t4 = lane & 3;
    const int m0 = blockIdx.x * 128;
    const int n0 = blockIdx.y * 64;

    float c[2][8][4];
#pragma unroll
    for (int m = 0; m < 2; m++)
#pragma unroll
        for (int nc = 0; nc < 8; nc++)
#pragma unroll
            for (int r = 0; r < 4; r++) c[m][nc][r] = 0.f;

    for (int k0 = 0; k0 < 128; k0 += 64) {
        __syncthreads();
#pragma unroll
        for (int i = 0; i < 8; i++) {
            const int f = tid + (i << 7);
            const int row = f >> 3, part = f & 7;
            *(uint4*)&Ah[row][part * 8] =
                *(const uint4*)(g_xh + (size_t)(m0 + row) * 128 + k0 + part * 8);
        }
#pragma unroll
        for (int i = 0; i < 4; i++) {
            const int f = tid + (i << 7);
            const int row = f >> 3, part = f & 7;
            *(uint4*)&Wts[row][part * 8] =
                *(const uint4*)(g_wqkvT + (size_t)(n0 + row) * 128 + k0 + part * 8);
        }
        __syncthreads();

        uint32_t a[2][4][4];
#pragma unroll
        for (int m = 0; m < 2; m++) {
            const int r0 = w * 32 + m * 16 + g;
#pragma unroll
            for (int kc = 0; kc < 4; kc++) {
                const int cb = kc * 16 + 2 * t4;
                a[m][kc][0] = *(const uint32_t*)&Ah[r0][cb];
                a[m][kc][1] = *(const uint32_t*)&Ah[r0 + 8][cb];
                a[m][kc][2] = *(const uint32_t*)&Ah[r0][cb + 8];
                a[m][kc][3] = *(const uint32_t*)&Ah[r0 + 8][cb + 8];
            }
        }
#pragma unroll
        for (int nc = 0; nc < 8; nc++) {
#pragma unroll
            for (int kc = 0; kc < 4; kc++) {
                const uint32_t b0 = *(const uint32_t*)&Wts[nc * 8 + g][kc * 16 + 2 * t4];
                const uint32_t b1 = *(const uint32_t*)&Wts[nc * 8 + g][kc * 16 + 2 * t4 + 8];
                mma16h(c[0][nc], a[0][kc], b0, b1);
                mma16h(c[1][nc], a[1][kc], b0, b1);
            }
        }
    }

    const int sec = n0 >> 7;
    const int n0r = n0 & 127;
#pragma unroll
    for (int m = 0; m < 2; m++) {
#pragma unroll
        for (int rr = 0; rr < 2; rr++) {
            const int row = m0 + w * 32 + m * 16 + g + rr * 8;
            const int b = row >> 12;
            const int t = row & (T_ - 1);
#pragma unroll
            for (int nc = 0; nc < 8; nc++) {
                const int n = n0r + nc * 8 + 2 * t4;
                const int h = n >> 5;
                const int d = n & 31;
                const float v0 = c[m][nc][rr * 2 + 0];
                const float v1 = c[m][nc][rr * 2 + 1];
                if (sec == 0) {
                    *(uint32_t*)(g_qh + (((size_t)(b * H_ + h) * T_) + t) * HD + d) =
                        packh2(v0 * QSCALE, v1 * QSCALE);
                } else if (sec == 1) {
                    *(uint32_t*)(g_kh + (((size_t)(b * H_ + h) * TK) + P_ + t) * HD + d) =
                        packh2(v0, v1);
                } else {
                    *(uint32_t*)(g_vh + (((size_t)(b * H_ + h) * TK) + P_ + t) * HD + d) =
                        packh2(v0, v1);
                }
            }
        }
    }
}

// ---------------- V transpose: g_vh [bh][key][d] -> g_vt [bh][d][key] --------
__global__ void __launch_bounds__(128) v_transpose() {
    __shared__ __half S[HD][72];
    const int bh = blockIdx.y;
    const int j0 = blockIdx.x * 64;
    const int tid = threadIdx.x;

#pragma unroll
    for (int i = 0; i < 4; i++) {
        const int f = tid + i * 128;
        const int key = f >> 3;
        const int d0 = (f & 7) * 4;
        uint2 v = *(const uint2*)(g_vh + ((size_t)bh * TK + j0 + key) * HD + d0);
        __half2 p0 = *(__half2*)&v.x;
        __half2 p1 = *(__half2*)&v.y;
        S[d0 + 0][key] = __low2half(p0);
        S[d0 + 1][key] = __high2half(p0);
        S[d0 + 2][key] = __low2half(p1);
        S[d0 + 3][key] = __high2half(p1);
    }
    __syncthreads();
#pragma unroll
    for (int i = 0; i < 2; i++) {
        const int f = tid + i * 128;
        const int d = f >> 3;
        const int part = f & 7;
        *(uint4*)(g_vt + ((size_t)(bh * HD + d)) * TK + j0 + part * 8) =
            *(const uint4*)&S[d][part * 8];
    }
}

// ---------------- attention: fp16 mma, ex2 softmax, cp.async, ldmatrix -------
__global__ void __launch_bounds__(128, 5) attn_tc() {
    __shared__ __half Kh[2][64][40];
    __shared__ __half Vst[2][HD][72];

    const int tid = threadIdx.x;
    const int w = tid >> 5;
    const int lane = tid & 31;
    const int g = lane >> 2;
    const int t4 = lane & 3;
    const int l8 = lane & 7;             // ldmatrix row within 8x8 block
    const int lj = lane >> 3;            // ldmatrix block index 0..3

    const int qt = 31 - blockIdx.x;      // heavy q-tiles first
    const int split = blockIdx.y;
    const int bh = blockIdx.z;
    const int q0 = qt * 128;
    const int wq = q0 + w * 32;

    // Q fragments (fp16, pre-scaled by 1/sqrt(hd)*log2e)
    uint32_t qa[2][2][4];
    {
        const __half* qb = g_qh + ((size_t)bh * T_) * HD;
#pragma unroll
        for (int m = 0; m < 2; m++) {
            const int r0 = wq + m * 16 + g;
#pragma unroll
            for (int kc = 0; kc < 2; kc++) {
                const int c = kc * 16 + 2 * t4;
                qa[m][kc][0] = *(const uint32_t*)(qb + (size_t)r0 * HD + c);
                qa[m][kc][1] = *(const uint32_t*)(qb + (size_t)(r0 + 8) * HD + c);
                qa[m][kc][2] = *(const uint32_t*)(qb + (size_t)r0 * HD + c + 8);
                qa[m][kc][3] = *(const uint32_t*)(qb + (size_t)(r0 + 8) * HD + c + 8);
            }
        }
    }

    float O[2][4][4];
    float Lc[2][4];
#pragma unroll
    for (int m = 0; m < 2; m++) {
#pragma unroll
        for (int dc = 0; dc < 4; dc++)
#pragma unroll
            for (int r = 0; r < 4; r++) O[m][dc][r] = 0.f;
#pragma unroll
        for (int r = 0; r < 4; r++) Lc[m][r] = 0.f;
    }

    const uint4* kb = (const uint4*)(g_kh + (size_t)bh * TK * HD);
    const __half* vtb = g_vt + (size_t)bh * HD * TK;
    const int nfull = (P_ + q0) >> 6;
    const int ntot = nfull + 2;
    const int t_begin = (ntot * split) / KS;
    const int t_end = (ntot * (split + 1)) / KS;

    auto load_tile = [&](int t, int buf) {
        const int j0 = t << 6;
#pragma unroll
        for (int i = 0; i < 2; i++) {
            const int f = tid + (i << 7);
            const int key = f >> 2;
            const int part = f & 3;
            cp16(&Kh[buf][key][part * 8], kb + (size_t)j0 * 4 + f);
        }
#pragma unroll
        for (int i = 0; i < 2; i++) {
            const int f = tid + (i << 7);
            const int d = f >> 3;
            const int part = f & 7;
            cp16(&Vst[buf][d][part * 8], vtb + (size_t)d * TK + j0 + part * 8);
        }
        CP_COMMIT();
    };

    load_tile(t_begin, 0);

    for (int t = t_begin; t < t_end; t++) {
        const int cur = (t - t_begin) & 1;
        const bool more = (t + 1 < t_end);
        if (more) {
            load_tile(t + 1, cur ^ 1);
            asm volatile("cp.async.wait_group 1;" ::: "memory");
        } else {
            asm volatile("cp.async.wait_group 0;" ::: "memory");
        }
        __syncthreads();

        const bool isdiag = (t == nfull + (w >> 1));
        const bool active = !(t > nfull && (w >> 1) == 0);
        if (active) {
#pragma unroll
            for (int pr = 0; pr < 4; pr++) {
                const int nc0 = 2 * pr, nc1 = 2 * pr + 1;
                // K B-fragments via ldmatrix: regs [kc0 b0, kc0 b1, kc1 b0, kc1 b1]
                uint32_t kf0[4], kf1[4];
                ldsm4(kf0, &Kh[cur][nc0 * 8 + l8][lj * 8]);
                ldsm4(kf1, &Kh[cur][nc1 * 8 + l8][lj * 8]);

                float S0[2][4], S1[2][4];
#pragma unroll
                for (int m = 0; m < 2; m++)
#pragma unroll
                    for (int r = 0; r < 4; r++) { S0[m][r] = 0.f; S1[m][r] = 0.f; }
#pragma unroll
                for (int kc = 0; kc < 2; kc++) {
                    mma16h(S0[0], qa[0][kc], kf0[kc * 2], kf0[kc * 2 + 1]);
                    mma16h(S0[1], qa[1][kc], kf0[kc * 2], kf0[kc * 2 + 1]);
                    mma16h(S1[0], qa[0][kc], kf1[kc * 2], kf1[kc * 2 + 1]);
                    mma16h(S1[1], qa[1][kc], kf1[kc * 2], kf1[kc * 2 + 1]);
                }

                if (isdiag) {
#pragma unroll
                    for (int m = 0; m < 2; m++) {
                        const int rbase = 32 * (w & 1) + m * 16 + g;
                        const int c00 = nc0 * 8 + 2 * t4;
                        const int c10 = nc1 * 8 + 2 * t4;
                        S0[m][0] = (c00     <= rbase)     ? S0[m][0] : -100.f;
                        S0[m][1] = (c00 + 1 <= rbase)     ? S0[m][1] : -100.f;
                        S0[m][2] = (c00     <= rbase + 8) ? S0[m][2] : -100.f;
                        S0[m][3] = (c00 + 1 <= rbase + 8) ? S0[m][3] : -100.f;
                        S1[m][0] = (c10     <= rbase)     ? S1[m][0] : -100.f;
                        S1[m][1] = (c10 + 1 <= rbase)     ? S1[m][1] : -100.f;
                        S1[m][2] = (c10     <= rbase + 8) ? S1[m][2] : -100.f;
                        S1[m][3] = (c10 + 1 <= rbase + 8) ? S1[m][3] : -100.f;
                    }
                }

                // P = 2^S via f16x2 MUFU; result IS the PV A-fragment
                uint32_t A[2][4];
#pragma unroll
                for (int m = 0; m < 2; m++) {
                    A[m][0] = ex2h2(packh2(S0[m][0], S0[m][1]));
                    A[m][1] = ex2h2(packh2(S0[m][2], S0[m][3]));
                    A[m][2] = ex2h2(packh2(S1[m][0], S1[m][1]));
                    A[m][3] = ex2h2(packh2(S1[m][2], S1[m][3]));
                    mma16h(Lc[m], A[m], ONE2, ONE2);   // row sums on tensor pipe
                }

                // V B-fragments via ldmatrix:
                // call A: blocks [dc0 k0, dc0 k0+8, dc1 k0, dc1 k0+8]
                // call B: blocks [dc2 k0, dc2 k0+8, dc3 k0, dc3 k0+8]
                const int k0 = pr * 16;
                uint32_t vfA[4], vfB[4];
                ldsm4(vfA, &Vst[cur][(lj >> 1) * 8 + l8][k0 + (lj & 1) * 8]);
                ldsm4(vfB, &Vst[cur][16 + (lj >> 1) * 8 + l8][k0 + (lj & 1) * 8]);

                mma16h(O[0][0], A[0], vfA[0], vfA[1]);
                mma16h(O[1][0], A[1], vfA[0], vfA[1]);
                mma16h(O[0][1], A[0], vfA[2], vfA[3]);
                mma16h(O[1][1], A[1], vfA[2], vfA[3]);
                mma16h(O[0][2], A[0], vfB[0], vfB[1]);
                mma16h(O[1][2], A[1], vfB[0], vfB[1]);
                mma16h(O[0][3], A[0], vfB[2], vfB[3]);
                mma16h(O[1][3], A[1], vfB[2], vfB[3]);
            }
        }
        __syncthreads();
    }

    // store partials (Lc[m][0] = row-g sum; Lc[m][2] = row g+8 sum)
    const size_t pbase = ((size_t)split * (B_ * H_) + bh) * T_;
#pragma unroll
    for (int m = 0; m < 2; m++) {
        const int r0 = wq + m * 16 + g;
        if (t4 == 0) {
            g_pl[pbase + r0] = Lc[m][0];
            g_pl[pbase + r0 + 8] = Lc[m][2];
        }
        float* p0 = g_pacc + (pbase + r0) * HD;
        float* p1 = g_pacc + (pbase + r0 + 8) * HD;
#pragma unroll
        for (int dc = 0; dc < 4; dc++) {
            const int col = dc * 8 + 2 * t4;
            *(float2*)&p0[col] = make_float2(O[m][dc][0], O[m][dc][1]);
            *(float2*)&p1[col] = make_float2(O[m][dc][2], O[m][dc][3]);
        }
    }
}

// ---------------- combine splits -> g_ctxh (fp16) ----------------------------
__global__ void __launch_bounds__(256) attn_combine() {
    const int idx = blockIdx.x * 256 + threadIdx.x;
    const int q_lin = idx >> 3;
    const int f = idx & 7;
    const int bh = q_lin >> 12;
    const int qi = q_lin & (T_ - 1);
    const int b = bh >> 2;
    const int h = bh & 3;

    float l = 0.f;
    float4 acc = make_float4(0.f, 0.f, 0.f, 0.f);
#pragma unroll
    for (int s = 0; s < KS; s++) {
        const size_t pb = ((size_t)s * (B_ * H_) + bh) * T_;
        l += g_pl[pb + qi];
        const float4 v = *(const float4*)(g_pacc + (pb + qi) * HD + f * 4);
        acc.x += v.x; acc.y += v.y; acc.z += v.z; acc.w += v.w;
    }
    const float inv = 1.f / l;
    uint2 o = make_uint2(packh2(acc.x * inv, acc.y * inv),
                         packh2(acc.z * inv, acc.w * inv));
    *(uint2*)(g_ctxh + ((size_t)b * T_ + qi) * DM + h * HD + f * 4) = o;
}

// ---------------- TC GEMM 2: out = ctx @ Wout (fp32 out) ---------------------
__global__ void __launch_bounds__(128) gemm_out_tc(float* __restrict__ out) {
    __shared__ __half Ah[128][72];
    __shared__ __half Wts[64][72];
    const int tid = threadIdx.x;
    const int w = tid >> 5;
    const int lane = tid & 31;
    const int g = lane >> 2;
    const int t4 = lane & 3;
    const int m0 = blockIdx.x * 128;
    const int n0 = blockIdx.y * 64;

    float c[2][8][4];
#pragma unroll
    for (int m = 0; m < 2; m++)
#pragma unroll
        for (int nc = 0; nc < 8; nc++)
#pragma unroll
            for (int r = 0; r < 4; r++) c[m][nc][r] = 0.f;

    for (int k0 = 0; k0 < 128; k0 += 64) {
        __syncthreads();
#pragma unroll
        for (int i = 0; i < 8; i++) {
            const int f = tid + (i << 7);
            const int row = f >> 3, part = f & 7;
            *(uint4*)&Ah[row][part * 8] =
                *(const uint4*)(g_ctxh + (size_t)(m0 + row) * 128 + k0 + part * 8);
        }
#pragma unroll
        for (int i = 0; i < 4; i++) {
            const int f = tid + (i << 7);
            const int row = f >> 3, part = f & 7;
            *(uint4*)&Wts[row][part * 8] =
                *(const uint4*)(g_woutT + (size_t)(n0 + row) * 128 + k0 + part * 8);
        }
        __syncthreads();

        uint32_t a[2][4][4];
#pragma unroll
        for (int m = 0; m < 2; m++) {
            const int r0 = w * 32 + m * 16 + g;
#pragma unroll
            for (int kc = 0; kc < 4; kc++) {
                const int cb = kc * 16 + 2 * t4;
                a[m][kc][0] = *(const uint32_t*)&Ah[r0][cb];
                a[m][kc][1] = *(const uint32_t*)&Ah[r0 + 8][cb];
                a[m][kc][2] = *(const uint32_t*)&Ah[r0][cb + 8];
                a[m][kc][3] = *(const uint32_t*)&Ah[r0 + 8][cb + 8];
            }
        }
#pragma unroll
        for (int nc = 0; nc < 8; nc++) {
#pragma unroll
            for (int kc = 0; kc < 4; kc++) {
                const uint32_t b0 = *(const uint32_t*)&Wts[nc * 8 + g][kc * 16 + 2 * t4];
                const uint32_t b1 = *(const uint32_t*)&Wts[nc * 8 + g][kc * 16 + 2 * t4 + 8];
                mma16h(c[0][nc], a[0][kc], b0, b1);
                mma16h(c[1][nc], a[1][kc], b0, b1);
            }
        }
    }

#pragma unroll
    for (int m = 0; m < 2; m++) {
#pragma unroll
        for (int rr = 0; rr < 2; rr++) {
            const int row = m0 + w * 32 + m * 16 + g + rr * 8;
#pragma unroll
            for (int nc = 0; nc < 8; nc++) {
                const int n = n0 + nc * 8 + 2 * t4;
                *(float2*)(out + (size_t)row * 128 + n) =
                    make_float2(c[m][nc][rr * 2 + 0], c[m][nc][rr * 2 + 1]);
            }
        }
    }
}

// ---------------- launch ----------------------------------------------------
extern "C" void kernel_launch(void* const* d_in, const int* in_sizes, int n_in,
                              void* d_out, int out_size) {
    const float* x    = (const float*)d_in[0];
    const float* pk   = (const float*)d_in[1];
    const float* pv   = (const float*)d_in[2];
    const float* Wqkv = (const float*)d_in[3];
    const float* Wout = (const float*)d_in[4];
    float* out = (float*)d_out;

    prep_all<<<1792, 256>>>((const float4*)x, Wqkv, Wout,
                            (const float4*)pk, (const float4*)pv);
    {
        dim3 grid(64, 6);
        gemm_qkv_tc<<<grid, 128>>>();
    }
    {
        dim3 grid(TK / 64, B_ * H_);
        v_transpose<<<grid, 128>>>();
    }
    {
        dim3 grid(32, KS, B_ * H_);
        attn_tc<<<grid, 128>>>();
    }
    {
        attn_combine<<<(B_ * H_ * T_ * 8) / 256, 256>>>();
    }
    {
        dim3 grid(64, 2);
        gemm_out_tc<<<grid, 128>>>(out);
    }
}

// round 15
// speedup vs baseline: 10.8219x; 1.0201x over previous
#include <cuda_runtime.h>
#include <cuda_fp16.h>
#include <cstdint>

// Problem constants
#define B_ 2
#define T_ 4096
#define H_ 4
#define HD 32
#define P_ 2048
#define TK 6144           // P_ + T_
#define DM 128            // D_MODEL
#define KS 4              // key splits
#define RSQRT_HD 0.17677669529663687f
#define LOG2E 1.4426950408889634f
#define QSCALE (RSQRT_HD * LOG2E)

// ---------------- scratch (device globals; no allocation allowed) ------------
__device__ __align__(16) __half g_xh[(size_t)B_ * T_ * DM];        // x fp16
__device__ __align__(16) __half g_wqkvT[(size_t)3 * DM * DM];      // Wqkv^T [384][128]
__device__ __align__(16) __half g_woutT[(size_t)DM * DM];          // Wout^T [128][128]
__device__ __align__(16) __half g_qh[(size_t)B_ * H_ * T_ * HD];   // pre-scaled by QSCALE
__device__ __align__(16) __half g_kh[(size_t)B_ * H_ * TK * HD];   // [bh][key][d]
__device__ __align__(16) __half g_vh[(size_t)B_ * H_ * TK * HD];   // [bh][key][d]
__device__ __align__(16) __half g_vt[(size_t)B_ * H_ * HD * TK];   // [bh][d][key]
__device__ __align__(16) __half g_ctxh[(size_t)B_ * T_ * DM];      // fp16 ctx
__device__ float g_pacc[(size_t)KS * B_ * H_ * T_ * HD];
__device__ float g_pl[(size_t)KS * B_ * H_ * T_];

// ---------------- helpers ----------------------------------------------------
__device__ __forceinline__ void mma16h(float* c, const uint32_t* a, uint32_t b0, uint32_t b1) {
    asm("mma.sync.aligned.m16n8k16.row.col.f32.f16.f16.f32 "
        "{%0,%1,%2,%3},{%4,%5,%6,%7},{%8,%9},{%0,%1,%2,%3};"
        : "+f"(c[0]), "+f"(c[1]), "+f"(c[2]), "+f"(c[3])
        : "r"(a[0]), "r"(a[1]), "r"(a[2]), "r"(a[3]), "r"(b0), "r"(b1));
}
__device__ __forceinline__ uint32_t packh2(float lo, float hi) {
    __half2 h = __float22half2_rn(make_float2(lo, hi));
    return *reinterpret_cast<uint32_t*>(&h);
}
__device__ __forceinline__ uint32_t ex2h2(uint32_t a) {
    uint32_t d;
    asm("ex2.approx.f16x2 %0, %1;" : "=r"(d) : "r"(a));
    return d;
}
__device__ __forceinline__ void cp16(void* sptr, const void* gptr) {
    uint32_t sa = (uint32_t)__cvta_generic_to_shared(sptr);
    asm volatile("cp.async.ca.shared.global [%0], [%1], 16;" :: "r"(sa), "l"(gptr) : "memory");
}
__device__ __forceinline__ void ldsm4(uint32_t* r, const void* p) {
    uint32_t a = (uint32_t)__cvta_generic_to_shared(p);
    asm volatile("ldmatrix.sync.aligned.m8n8.x4.shared.b16 {%0,%1,%2,%3}, [%4];"
        : "=r"(r[0]), "=r"(r[1]), "=r"(r[2]), "=r"(r[3]) : "r"(a));
}
#define CP_COMMIT() asm volatile("cp.async.commit_group;" ::: "memory")
#define ONE2 0x3C003C00u

// ---------------- prep: x->fp16, W transposes, prefix K/V -> fp16 ------------
__global__ void __launch_bounds__(256) prep_all(const float4* __restrict__ x4,
                                                const float* __restrict__ Wqkv,
                                                const float* __restrict__ Wout,
                                                const float4* __restrict__ pk,
                                                const float4* __restrict__ pv) {
    const int i = blockIdx.x * 256 + threadIdx.x;
    if (i < 262144) {                                   // x: B*T*DM/4 uint2 stores
        float4 v = x4[i];
        uint2 o = make_uint2(packh2(v.x, v.y), packh2(v.z, v.w));
        ((uint2*)g_xh)[i] = o;
    } else if (i < 262144 + 49152) {                    // Wqkv^T
        const int j = i - 262144;
        const int n = j >> 7, k = j & 127;
        g_wqkvT[j] = __float2half_rn(Wqkv[k * 384 + n]);
    } else if (i < 262144 + 49152 + 16384) {            // Wout^T
        const int j = i - 262144 - 49152;
        const int n = j >> 7, k = j & 127;
        g_woutT[j] = __float2half_rn(Wout[k * 128 + n]);
    } else if (i < 262144 + 49152 + 16384 + 131072) {   // prefix K/V
        const int idx = i - 262144 - 49152 - 16384;
        const int per_bh = P_ * HD / 4;
        const int bh = idx / per_bh;
        const int rem = idx - bh * per_bh;
        float4 k = pk[idx];
        uint2 kk = make_uint2(packh2(k.x, k.y), packh2(k.z, k.w));
        *(uint2*)(g_kh + ((size_t)bh * TK * HD) + rem * 4) = kk;
        float4 v = pv[idx];
        uint2 vv = make_uint2(packh2(v.x, v.y), packh2(v.z, v.w));
        *(uint2*)(g_vh + ((size_t)bh * TK * HD) + rem * 4) = vv;
    }
}

// ---------------- TC GEMM 1: qkv = x @ Wqkv, scatter to g_qh/g_kh/g_vh -------
__global__ void __launch_bounds__(128) gemm_qkv_tc() {
    __shared__ __half Ah[128][72];
    __shared__ __half Wts[64][72];
    const int tid = threadIdx.x;
    const int w = tid >> 5;
    const int lane = tid & 31;
    const int g = lane >> 2;
    const int t4 = lane & 3;
    const int m0 = blockIdx.x * 128;
    const int n0 = blockIdx.y * 64;

    float c[2][8][4];
#pragma unroll
    for (int m = 0; m < 2; m++)
#pragma unroll
        for (int nc = 0; nc < 8; nc++)
#pragma unroll
            for (int r = 0; r < 4; r++) c[m][nc][r] = 0.f;

    for (int k0 = 0; k0 < 128; k0 += 64) {
        __syncthreads();
#pragma unroll
        for (int i = 0; i < 8; i++) {
            const int f = tid + (i << 7);
            const int row = f >> 3, part = f & 7;
            *(uint4*)&Ah[row][part * 8] =
                *(const uint4*)(g_xh + (size_t)(m0 + row) * 128 + k0 + part * 8);
        }
#pragma unroll
        for (int i = 0; i < 4; i++) {
            const int f = tid + (i << 7);
            const int row = f >> 3, part = f & 7;
            *(uint4*)&Wts[row][part * 8] =
                *(const uint4*)(g_wqkvT + (size_t)(n0 + row) * 128 + k0 + part * 8);
        }
        __syncthreads();

        uint32_t a[2][4][4];
#pragma unroll
        for (int m = 0; m < 2; m++) {
            const int r0 = w * 32 + m * 16 + g;
#pragma unroll
            for (int kc = 0; kc < 4; kc++) {
                const int cb = kc * 16 + 2 * t4;
                a[m][kc][0] = *(const uint32_t*)&Ah[r0][cb];
                a[m][kc][1] = *(const uint32_t*)&Ah[r0 + 8][cb];
                a[m][kc][2] = *(const uint32_t*)&Ah[r0][cb + 8];
                a[m][kc][3] = *(const uint32_t*)&Ah[r0 + 8][cb + 8];
            }
        }
#pragma unroll
        for (int nc = 0; nc < 8; nc++) {
#pragma unroll
            for (int kc = 0; kc < 4; kc++) {
                const uint32_t b0 = *(const uint32_t*)&Wts[nc * 8 + g][kc * 16 + 2 * t4];
                const uint32_t b1 = *(const uint32_t*)&Wts[nc * 8 + g][kc * 16 + 2 * t4 + 8];
                mma16h(c[0][nc], a[0][kc], b0, b1);
                mma16h(c[1][nc], a[1][kc], b0, b1);
            }
        }
    }

    const int sec = n0 >> 7;
    const int n0r = n0 & 127;
#pragma unroll
    for (int m = 0; m < 2; m++) {
#pragma unroll
        for (int rr = 0; rr < 2; rr++) {
            const int row = m0 + w * 32 + m * 16 + g + rr * 8;
            const int b = row >> 12;
            const int t = row & (T_ - 1);
#pragma unroll
            for (int nc = 0; nc < 8; nc++) {
                const int n = n0r + nc * 8 + 2 * t4;
                const int h = n >> 5;
                const int d = n & 31;
                const float v0 = c[m][nc][rr * 2 + 0];
                const float v1 = c[m][nc][rr * 2 + 1];
                if (sec == 0) {
                    *(uint32_t*)(g_qh + (((size_t)(b * H_ + h) * T_) + t) * HD + d) =
                        packh2(v0 * QSCALE, v1 * QSCALE);
                } else if (sec == 1) {
                    *(uint32_t*)(g_kh + (((size_t)(b * H_ + h) * TK) + P_ + t) * HD + d) =
                        packh2(v0, v1);
                } else {
                    *(uint32_t*)(g_vh + (((size_t)(b * H_ + h) * TK) + P_ + t) * HD + d) =
                        packh2(v0, v1);
                }
            }
        }
    }
}

// ---------------- V transpose: g_vh [bh][key][d] -> g_vt [bh][d][key] --------
__global__ void __launch_bounds__(128) v_transpose() {
    __shared__ __half S[HD][72];
    const int bh = blockIdx.y;
    const int j0 = blockIdx.x * 64;
    const int tid = threadIdx.x;

#pragma unroll
    for (int i = 0; i < 4; i++) {
        const int f = tid + i * 128;
        const int key = f >> 3;
        const int d0 = (f & 7) * 4;
        uint2 v = *(const uint2*)(g_vh + ((size_t)bh * TK + j0 + key) * HD + d0);
        __half2 p0 = *(__half2*)&v.x;
        __half2 p1 = *(__half2*)&v.y;
        S[d0 + 0][key] = __low2half(p0);
        S[d0 + 1][key] = __high2half(p0);
        S[d0 + 2][key] = __low2half(p1);
        S[d0 + 3][key] = __high2half(p1);
    }
    __syncthreads();
#pragma unroll
    for (int i = 0; i < 2; i++) {
        const int f = tid + i * 128;
        const int d = f >> 3;
        const int part = f & 7;
        *(uint4*)(g_vt + ((size_t)(bh * HD + d)) * TK + j0 + part * 8) =
            *(const uint4*)&S[d][part * 8];
    }
}

// ---------------- attention: fp16 mma, ex2 softmax, 3-buffer cp.async --------
__global__ void __launch_bounds__(128, 5) attn_tc() {
    __shared__ __half Kh[3][64][40];
    __shared__ __half Vst[3][HD][72];

    const int tid = threadIdx.x;
    const int w = tid >> 5;
    const int lane = tid & 31;
    const int g = lane >> 2;
    const int t4 = lane & 3;
    const int l8 = lane & 7;             // ldmatrix row within 8x8 block
    const int lj = lane >> 3;            // ldmatrix block index 0..3

    const int qt = 31 - blockIdx.x;      // heavy q-tiles first
    const int split = blockIdx.y;
    const int bh = blockIdx.z;
    const int q0 = qt * 128;
    const int wq = q0 + w * 32;

    // Q fragments (fp16, pre-scaled by 1/sqrt(hd)*log2e)
    uint32_t qa[2][2][4];
    {
        const __half* qb = g_qh + ((size_t)bh * T_) * HD;
#pragma unroll
        for (int m = 0; m < 2; m++) {
            const int r0 = wq + m * 16 + g;
#pragma unroll
            for (int kc = 0; kc < 2; kc++) {
                const int c = kc * 16 + 2 * t4;
                qa[m][kc][0] = *(const uint32_t*)(qb + (size_t)r0 * HD + c);
                qa[m][kc][1] = *(const uint32_t*)(qb + (size_t)(r0 + 8) * HD + c);
                qa[m][kc][2] = *(const uint32_t*)(qb + (size_t)r0 * HD + c + 8);
                qa[m][kc][3] = *(const uint32_t*)(qb + (size_t)(r0 + 8) * HD + c + 8);
            }
        }
    }

    float O[2][4][4];
    float Lc[2][4];
#pragma unroll
    for (int m = 0; m < 2; m++) {
#pragma unroll
        for (int dc = 0; dc < 4; dc++)
#pragma unroll
            for (int r = 0; r < 4; r++) O[m][dc][r] = 0.f;
#pragma unroll
        for (int r = 0; r < 4; r++) Lc[m][r] = 0.f;
    }

    const uint4* kb = (const uint4*)(g_kh + (size_t)bh * TK * HD);
    const __half* vtb = g_vt + (size_t)bh * HD * TK;
    const int nfull = (P_ + q0) >> 6;
    const int ntot = nfull + 2;
    const int t_begin = (ntot * split) / KS;
    const int t_end = (ntot * (split + 1)) / KS;

    auto load_tile = [&](int t, int buf) {
        const int j0 = t << 6;
#pragma unroll
        for (int i = 0; i < 2; i++) {
            const int f = tid + (i << 7);
            const int key = f >> 2;
            const int part = f & 3;
            cp16(&Kh[buf][key][part * 8], kb + (size_t)j0 * 4 + f);
        }
#pragma unroll
        for (int i = 0; i < 2; i++) {
            const int f = tid + (i << 7);
            const int d = f >> 3;
            const int part = f & 7;
            cp16(&Vst[buf][d][part * 8], vtb + (size_t)d * TK + j0 + part * 8);
        }
    };

    // prologue: prefetch 2 tiles (always commit both groups)
    load_tile(t_begin, 0);
    CP_COMMIT();
    if (t_begin + 1 < t_end) load_tile(t_begin + 1, 1);
    CP_COMMIT();

    int cur = 0;
    for (int t = t_begin; t < t_end; t++) {
        asm volatile("cp.async.wait_group 1;" ::: "memory");
        __syncthreads();           // single barrier per tile (3-buffer rotation)

        int tgt = cur + 2; if (tgt >= 3) tgt -= 3;
        if (t + 2 < t_end) load_tile(t + 2, tgt);
        CP_COMMIT();               // commit every iteration to keep group count aligned

        const bool isdiag = (t == nfull + (w >> 1));
        const bool active = !(t > nfull && (w >> 1) == 0);
        if (active) {
#pragma unroll
            for (int pr = 0; pr < 4; pr++) {
                const int nc0 = 2 * pr, nc1 = 2 * pr + 1;
                // K B-fragments via ldmatrix: regs [kc0 b0, kc0 b1, kc1 b0, kc1 b1]
                uint32_t kf0[4], kf1[4];
                ldsm4(kf0, &Kh[cur][nc0 * 8 + l8][lj * 8]);
                ldsm4(kf1, &Kh[cur][nc1 * 8 + l8][lj * 8]);

                float S0[2][4], S1[2][4];
#pragma unroll
                for (int m = 0; m < 2; m++)
#pragma unroll
                    for (int r = 0; r < 4; r++) { S0[m][r] = 0.f; S1[m][r] = 0.f; }
#pragma unroll
                for (int kc = 0; kc < 2; kc++) {
                    mma16h(S0[0], qa[0][kc], kf0[kc * 2], kf0[kc * 2 + 1]);
                    mma16h(S0[1], qa[1][kc], kf0[kc * 2], kf0[kc * 2 + 1]);
                    mma16h(S1[0], qa[0][kc], kf1[kc * 2], kf1[kc * 2 + 1]);
                    mma16h(S1[1], qa[1][kc], kf1[kc * 2], kf1[kc * 2 + 1]);
                }

                if (isdiag) {
#pragma unroll
                    for (int m = 0; m < 2; m++) {
                        const int rbase = 32 * (w & 1) + m * 16 + g;
                        const int c00 = nc0 * 8 + 2 * t4;
                        const int c10 = nc1 * 8 + 2 * t4;
                        S0[m][0] = (c00     <= rbase)     ? S0[m][0] : -100.f;
                        S0[m][1] = (c00 + 1 <= rbase)     ? S0[m][1] : -100.f;
                        S0[m][2] = (c00     <= rbase + 8) ? S0[m][2] : -100.f;
                        S0[m][3] = (c00 + 1 <= rbase + 8) ? S0[m][3] : -100.f;
                        S1[m][0] = (c10     <= rbase)     ? S1[m][0] : -100.f;
                        S1[m][1] = (c10 + 1 <= rbase)     ? S1[m][1] : -100.f;
                        S1[m][2] = (c10     <= rbase + 8) ? S1[m][2] : -100.f;
                        S1[m][3] = (c10 + 1 <= rbase + 8) ? S1[m][3] : -100.f;
                    }
                }

                // P = 2^S via f16x2 MUFU; result IS the PV A-fragment
                uint32_t A[2][4];
#pragma unroll
                for (int m = 0; m < 2; m++) {
                    A[m][0] = ex2h2(packh2(S0[m][0], S0[m][1]));
                    A[m][1] = ex2h2(packh2(S0[m][2], S0[m][3]));
                    A[m][2] = ex2h2(packh2(S1[m][0], S1[m][1]));
                    A[m][3] = ex2h2(packh2(S1[m][2], S1[m][3]));
                    mma16h(Lc[m], A[m], ONE2, ONE2);   // row sums on tensor pipe
                }

                // V B-fragments via ldmatrix
                const int k0 = pr * 16;
                uint32_t vfA[4], vfB[4];
                ldsm4(vfA, &Vst[cur][(lj >> 1) * 8 + l8][k0 + (lj & 1) * 8]);
                ldsm4(vfB, &Vst[cur][16 + (lj >> 1) * 8 + l8][k0 + (lj & 1) * 8]);

                mma16h(O[0][0], A[0], vfA[0], vfA[1]);
                mma16h(O[1][0], A[1], vfA[0], vfA[1]);
                mma16h(O[0][1], A[0], vfA[2], vfA[3]);
                mma16h(O[1][1], A[1], vfA[2], vfA[3]);
                mma16h(O[0][2], A[0], vfB[0], vfB[1]);
                mma16h(O[1][2], A[1], vfB[0], vfB[1]);
                mma16h(O[0][3], A[0], vfB[2], vfB[3]);
                mma16h(O[1][3], A[1], vfB[2], vfB[3]);
            }
        }
        cur = (cur == 2) ? 0 : cur + 1;
    }

    // store partials (Lc[m][0] = row-g sum; Lc[m][2] = row g+8 sum)
    const size_t pbase = ((size_t)split * (B_ * H_) + bh) * T_;
#pragma unroll
    for (int m = 0; m < 2; m++) {
        const int r0 = wq + m * 16 + g;
        if (t4 == 0) {
            g_pl[pbase + r0] = Lc[m][0];
            g_pl[pbase + r0 + 8] = Lc[m][2];
        }
        float* p0 = g_pacc + (pbase + r0) * HD;
        float* p1 = g_pacc + (pbase + r0 + 8) * HD;
#pragma unroll
        for (int dc = 0; dc < 4; dc++) {
            const int col = dc * 8 + 2 * t4;
            *(float2*)&p0[col] = make_float2(O[m][dc][0], O[m][dc][1]);
            *(float2*)&p1[col] = make_float2(O[m][dc][2], O[m][dc][3]);
        }
    }
}

// ---------------- combine splits -> g_ctxh (fp16) ----------------------------
__global__ void __launch_bounds__(256) attn_combine() {
    const int idx = blockIdx.x * 256 + threadIdx.x;
    const int q_lin = idx >> 3;
    const int f = idx & 7;
    const int bh = q_lin >> 12;
    const int qi = q_lin & (T_ - 1);
    const int b = bh >> 2;
    const int h = bh & 3;

    float l = 0.f;
    float4 acc = make_float4(0.f, 0.f, 0.f, 0.f);
#pragma unroll
    for (int s = 0; s < KS; s++) {
        const size_t pb = ((size_t)s * (B_ * H_) + bh) * T_;
        l += g_pl[pb + qi];
        const float4 v = *(const float4*)(g_pacc + (pb + qi) * HD + f * 4);
        acc.x += v.x; acc.y += v.y; acc.z += v.z; acc.w += v.w;
    }
    const float inv = 1.f / l;
    uint2 o = make_uint2(packh2(acc.x * inv, acc.y * inv),
                         packh2(acc.z * inv, acc.w * inv));
    *(uint2*)(g_ctxh + ((size_t)b * T_ + qi) * DM + h * HD + f * 4) = o;
}

// ---------------- TC GEMM 2: out = ctx @ Wout (fp32 out) ---------------------
__global__ void __launch_bounds__(128) gemm_out_tc(float* __restrict__ out) {
    __shared__ __half Ah[128][72];
    __shared__ __half Wts[64][72];
    const int tid = threadIdx.x;
    const int w = tid >> 5;
    const int lane = tid & 31;
    const int g = lane >> 2;
    const int t4 = lane & 3;
    const int m0 = blockIdx.x * 128;
    const int n0 = blockIdx.y * 64;

    float c[2][8][4];
#pragma unroll
    for (int m = 0; m < 2; m++)
#pragma unroll
        for (int nc = 0; nc < 8; nc++)
#pragma unroll
            for (int r = 0; r < 4; r++) c[m][nc][r] = 0.f;

    for (int k0 = 0; k0 < 128; k0 += 64) {
        __syncthreads();
#pragma unroll
        for (int i = 0; i < 8; i++) {
            const int f = tid + (i << 7);
            const int row = f >> 3, part = f & 7;
            *(uint4*)&Ah[row][part * 8] =
                *(const uint4*)(g_ctxh + (size_t)(m0 + row) * 128 + k0 + part * 8);
        }
#pragma unroll
        for (int i = 0; i < 4; i++) {
            const int f = tid + (i << 7);
            const int row = f >> 3, part = f & 7;
            *(uint4*)&Wts[row][part * 8] =
                *(const uint4*)(g_woutT + (size_t)(n0 + row) * 128 + k0 + part * 8);
        }
        __syncthreads();

        uint32_t a[2][4][4];
#pragma unroll
        for (int m = 0; m < 2; m++) {
            const int r0 = w * 32 + m * 16 + g;
#pragma unroll
            for (int kc = 0; kc < 4; kc++) {
                const int cb = kc * 16 + 2 * t4;
                a[m][kc][0] = *(const uint32_t*)&Ah[r0][cb];
                a[m][kc][1] = *(const uint32_t*)&Ah[r0 + 8][cb];
                a[m][kc][2] = *(const uint32_t*)&Ah[r0][cb + 8];
                a[m][kc][3] = *(const uint32_t*)&Ah[r0 + 8][cb + 8];
            }
        }
#pragma unroll
        for (int nc = 0; nc < 8; nc++) {
#pragma unroll
            for (int kc = 0; kc < 4; kc++) {
                const uint32_t b0 = *(const uint32_t*)&Wts[nc * 8 + g][kc * 16 + 2 * t4];
                const uint32_t b1 = *(const uint32_t*)&Wts[nc * 8 + g][kc * 16 + 2 * t4 + 8];
                mma16h(c[0][nc], a[0][kc], b0, b1);
                mma16h(c[1][nc], a[1][kc], b0, b1);
            }
        }
    }

#pragma unroll
    for (int m = 0; m < 2; m++) {
#pragma unroll
        for (int rr = 0; rr < 2; rr++) {
            const int row = m0 + w * 32 + m * 16 + g + rr * 8;
#pragma unroll
            for (int nc = 0; nc < 8; nc++) {
                const int n = n0 + nc * 8 + 2 * t4;
                *(float2*)(out + (size_t)row * 128 + n) =
                    make_float2(c[m][nc][rr * 2 + 0], c[m][nc][rr * 2 + 1]);
            }
        }
    }
}

// ---------------- launch ----------------------------------------------------
extern "C" void kernel_launch(void* const* d_in, const int* in_sizes, int n_in,
                              void* d_out, int out_size) {
    const float* x    = (const float*)d_in[0];
    const float* pk   = (const float*)d_in[1];
    const float* pv   = (const float*)d_in[2];
    const float* Wqkv = (const float*)d_in[3];
    const float* Wout = (const float*)d_in[4];
    float* out = (float*)d_out;

    prep_all<<<1792, 256>>>((const float4*)x, Wqkv, Wout,
                            (const float4*)pk, (const float4*)pv);
    {
        dim3 grid(64, 6);
        gemm_qkv_tc<<<grid, 128>>>();
    }
    {
        dim3 grid(TK / 64, B_ * H_);
        v_transpose<<<grid, 128>>>();
    }
    {
        dim3 grid(32, KS, B_ * H_);
        attn_tc<<<grid, 128>>>();
    }
    {
        attn_combine<<<(B_ * H_ * T_ * 8) / 256, 256>>>();
    }
    {
        dim3 grid(64, 2);
        gemm_out_tc<<<grid, 128>>>(out);
    }
}

// round 16
// speedup vs baseline: 11.3488x; 1.0487x over previous
#include <cuda_runtime.h>
#include <cuda_fp16.h>
#include <cstdint>

// Problem constants
#define B_ 2
#define T_ 4096
#define H_ 4
#define HD 32
#define P_ 2048
#define TK 6144           // P_ + T_
#define DM 128            // D_MODEL
#define KS 8              // key splits (finer blocks -> better wave packing)
#define RSQRT_HD 0.17677669529663687f
#define LOG2E 1.4426950408889634f
#define QSCALE (RSQRT_HD * LOG2E)

// ---------------- scratch (device globals; no allocation allowed) ------------
__device__ __align__(16) __half g_xh[(size_t)B_ * T_ * DM];        // x fp16
__device__ __align__(16) __half g_wqkvT[(size_t)3 * DM * DM];      // Wqkv^T [384][128]
__device__ __align__(16) __half g_woutT[(size_t)DM * DM];          // Wout^T [128][128]
__device__ __align__(16) __half g_qh[(size_t)B_ * H_ * T_ * HD];   // pre-scaled by QSCALE
__device__ __align__(16) __half g_kh[(size_t)B_ * H_ * TK * HD];   // [bh][key][d]
__device__ __align__(16) __half g_vh[(size_t)B_ * H_ * TK * HD];   // [bh][key][d]
__device__ __align__(16) __half g_vt[(size_t)B_ * H_ * HD * TK];   // [bh][d][key]
__device__ __align__(16) __half g_ctxh[(size_t)B_ * T_ * DM];      // fp16 ctx
__device__ float g_pacc[(size_t)KS * B_ * H_ * T_ * HD];
__device__ float g_pl[(size_t)KS * B_ * H_ * T_];

// ---------------- helpers ----------------------------------------------------
__device__ __forceinline__ void mma16h(float* c, const uint32_t* a, uint32_t b0, uint32_t b1) {
    asm("mma.sync.aligned.m16n8k16.row.col.f32.f16.f16.f32 "
        "{%0,%1,%2,%3},{%4,%5,%6,%7},{%8,%9},{%0,%1,%2,%3};"
        : "+f"(c[0]), "+f"(c[1]), "+f"(c[2]), "+f"(c[3])
        : "r"(a[0]), "r"(a[1]), "r"(a[2]), "r"(a[3]), "r"(b0), "r"(b1));
}
__device__ __forceinline__ uint32_t packh2(float lo, float hi) {
    __half2 h = __float22half2_rn(make_float2(lo, hi));
    return *reinterpret_cast<uint32_t*>(&h);
}
__device__ __forceinline__ uint32_t ex2h2(uint32_t a) {
    uint32_t d;
    asm("ex2.approx.f16x2 %0, %1;" : "=r"(d) : "r"(a));
    return d;
}
__device__ __forceinline__ void cp16(void* sptr, const void* gptr) {
    uint32_t sa = (uint32_t)__cvta_generic_to_shared(sptr);
    asm volatile("cp.async.ca.shared.global [%0], [%1], 16;" :: "r"(sa), "l"(gptr) : "memory");
}
__device__ __forceinline__ void ldsm4(uint32_t* r, const void* p) {
    uint32_t a = (uint32_t)__cvta_generic_to_shared(p);
    asm volatile("ldmatrix.sync.aligned.m8n8.x4.shared.b16 {%0,%1,%2,%3}, [%4];"
        : "=r"(r[0]), "=r"(r[1]), "=r"(r[2]), "=r"(r[3]) : "r"(a));
}
#define CP_COMMIT() asm volatile("cp.async.commit_group;" ::: "memory")
#define ONE2 0x3C003C00u

// ---------------- prep: x->fp16, W transposes, prefix K/V -> fp16 ------------
__global__ void __launch_bounds__(256) prep_all(const float4* __restrict__ x4,
                                                const float* __restrict__ Wqkv,
                                                const float* __restrict__ Wout,
                                                const float4* __restrict__ pk,
                                                const float4* __restrict__ pv) {
    const int i = blockIdx.x * 256 + threadIdx.x;
    if (i < 262144) {                                   // x: B*T*DM/4 uint2 stores
        float4 v = x4[i];
        uint2 o = make_uint2(packh2(v.x, v.y), packh2(v.z, v.w));
        ((uint2*)g_xh)[i] = o;
    } else if (i < 262144 + 49152) {                    // Wqkv^T
        const int j = i - 262144;
        const int n = j >> 7, k = j & 127;
        g_wqkvT[j] = __float2half_rn(Wqkv[k * 384 + n]);
    } else if (i < 262144 + 49152 + 16384) {            // Wout^T
        const int j = i - 262144 - 49152;
        const int n = j >> 7, k = j & 127;
        g_woutT[j] = __float2half_rn(Wout[k * 128 + n]);
    } else if (i < 262144 + 49152 + 16384 + 131072) {   // prefix K/V
        const int idx = i - 262144 - 49152 - 16384;
        const int per_bh = P_ * HD / 4;
        const int bh = idx / per_bh;
        const int rem = idx - bh * per_bh;
        float4 k = pk[idx];
        uint2 kk = make_uint2(packh2(k.x, k.y), packh2(k.z, k.w));
        *(uint2*)(g_kh + ((size_t)bh * TK * HD) + rem * 4) = kk;
        float4 v = pv[idx];
        uint2 vv = make_uint2(packh2(v.x, v.y), packh2(v.z, v.w));
        *(uint2*)(g_vh + ((size_t)bh * TK * HD) + rem * 4) = vv;
    }
}

// ---------------- TC GEMM 1: qkv = x @ Wqkv, scatter to g_qh/g_kh/g_vh -------
__global__ void __launch_bounds__(128) gemm_qkv_tc() {
    __shared__ __half Ah[128][72];
    __shared__ __half Wts[64][72];
    const int tid = threadIdx.x;
    const int w = tid >> 5;
    const int lane = tid & 31;
    const int g = lane >> 2;
    const int t4 = lane & 3;
    const int m0 = blockIdx.x * 128;
    const int n0 = blockIdx.y * 64;

    float c[2][8][4];
#pragma unroll
    for (int m = 0; m < 2; m++)
#pragma unroll
        for (int nc = 0; nc < 8; nc++)
#pragma unroll
            for (int r = 0; r < 4; r++) c[m][nc][r] = 0.f;

    for (int k0 = 0; k0 < 128; k0 += 64) {
        __syncthreads();
#pragma unroll
        for (int i = 0; i < 8; i++) {
            const int f = tid + (i << 7);
            const int row = f >> 3, part = f & 7;
            *(uint4*)&Ah[row][part * 8] =
                *(const uint4*)(g_xh + (size_t)(m0 + row) * 128 + k0 + part * 8);
        }
#pragma unroll
        for (int i = 0; i < 4; i++) {
            const int f = tid + (i << 7);
            const int row = f >> 3, part = f & 7;
            *(uint4*)&Wts[row][part * 8] =
                *(const uint4*)(g_wqkvT + (size_t)(n0 + row) * 128 + k0 + part * 8);
        }
        __syncthreads();

        uint32_t a[2][4][4];
#pragma unroll
        for (int m = 0; m < 2; m++) {
            const int r0 = w * 32 + m * 16 + g;
#pragma unroll
            for (int kc = 0; kc < 4; kc++) {
                const int cb = kc * 16 + 2 * t4;
                a[m][kc][0] = *(const uint32_t*)&Ah[r0][cb];
                a[m][kc][1] = *(const uint32_t*)&Ah[r0 + 8][cb];
                a[m][kc][2] = *(const uint32_t*)&Ah[r0][cb + 8];
                a[m][kc][3] = *(const uint32_t*)&Ah[r0 + 8][cb + 8];
            }
        }
#pragma unroll
        for (int nc = 0; nc < 8; nc++) {
#pragma unroll
            for (int kc = 0; kc < 4; kc++) {
                const uint32_t b0 = *(const uint32_t*)&Wts[nc * 8 + g][kc * 16 + 2 * t4];
                const uint32_t b1 = *(const uint32_t*)&Wts[nc * 8 + g][kc * 16 + 2 * t4 + 8];
                mma16h(c[0][nc], a[0][kc], b0, b1);
                mma16h(c[1][nc], a[1][kc], b0, b1);
            }
        }
    }

    const int sec = n0 >> 7;
    const int n0r = n0 & 127;
#pragma unroll
    for (int m = 0; m < 2; m++) {
#pragma unroll
        for (int rr = 0; rr < 2; rr++) {
            const int row = m0 + w * 32 + m * 16 + g + rr * 8;
            const int b = row >> 12;
            const int t = row & (T_ - 1);
#pragma unroll
            for (int nc = 0; nc < 8; nc++) {
                const int n = n0r + nc * 8 + 2 * t4;
                const int h = n >> 5;
                const int d = n & 31;
                const float v0 = c[m][nc][rr * 2 + 0];
                const float v1 = c[m][nc][rr * 2 + 1];
                if (sec == 0) {
                    *(uint32_t*)(g_qh + (((size_t)(b * H_ + h) * T_) + t) * HD + d) =
                        packh2(v0 * QSCALE, v1 * QSCALE);
                } else if (sec == 1) {
                    *(uint32_t*)(g_kh + (((size_t)(b * H_ + h) * TK) + P_ + t) * HD + d) =
                        packh2(v0, v1);
                } else {
                    *(uint32_t*)(g_vh + (((size_t)(b * H_ + h) * TK) + P_ + t) * HD + d) =
                        packh2(v0, v1);
                }
            }
        }
    }
}

// ---------------- V transpose: g_vh [bh][key][d] -> g_vt [bh][d][key] --------
__global__ void __launch_bounds__(128) v_transpose() {
    __shared__ __half S[HD][72];
    const int bh = blockIdx.y;
    const int j0 = blockIdx.x * 64;
    const int tid = threadIdx.x;

#pragma unroll
    for (int i = 0; i < 4; i++) {
        const int f = tid + i * 128;
        const int key = f >> 3;
        const int d0 = (f & 7) * 4;
        uint2 v = *(const uint2*)(g_vh + ((size_t)bh * TK + j0 + key) * HD + d0);
        __half2 p0 = *(__half2*)&v.x;
        __half2 p1 = *(__half2*)&v.y;
        S[d0 + 0][key] = __low2half(p0);
        S[d0 + 1][key] = __high2half(p0);
        S[d0 + 2][key] = __low2half(p1);
        S[d0 + 3][key] = __high2half(p1);
    }
    __syncthreads();
#pragma unroll
    for (int i = 0; i < 2; i++) {
        const int f = tid + i * 128;
        const int d = f >> 3;
        const int part = f & 7;
        *(uint4*)(g_vt + ((size_t)(bh * HD + d)) * TK + j0 + part * 8) =
            *(const uint4*)&S[d][part * 8];
    }
}

// ---------------- attention: fp16 mma, ex2 softmax, 3-buffer cp.async --------
__global__ void __launch_bounds__(128, 5) attn_tc() {
    __shared__ __half Kh[3][64][40];
    __shared__ __half Vst[3][HD][72];

    const int tid = threadIdx.x;
    const int w = tid >> 5;
    const int lane = tid & 31;
    const int g = lane >> 2;
    const int t4 = lane & 3;
    const int l8 = lane & 7;             // ldmatrix row within 8x8 block
    const int lj = lane >> 3;            // ldmatrix block index 0..3

    const int qt = 31 - blockIdx.x;      // heavy q-tiles first
    const int split = blockIdx.y;
    const int bh = blockIdx.z;
    const int q0 = qt * 128;
    const int wq = q0 + w * 32;

    // Q fragments (fp16, pre-scaled by 1/sqrt(hd)*log2e)
    uint32_t qa[2][2][4];
    {
        const __half* qb = g_qh + ((size_t)bh * T_) * HD;
#pragma unroll
        for (int m = 0; m < 2; m++) {
            const int r0 = wq + m * 16 + g;
#pragma unroll
            for (int kc = 0; kc < 2; kc++) {
                const int c = kc * 16 + 2 * t4;
                qa[m][kc][0] = *(const uint32_t*)(qb + (size_t)r0 * HD + c);
                qa[m][kc][1] = *(const uint32_t*)(qb + (size_t)(r0 + 8) * HD + c);
                qa[m][kc][2] = *(const uint32_t*)(qb + (size_t)r0 * HD + c + 8);
                qa[m][kc][3] = *(const uint32_t*)(qb + (size_t)(r0 + 8) * HD + c + 8);
            }
        }
    }

    float O[2][4][4];
    float Lc[2][4];
#pragma unroll
    for (int m = 0; m < 2; m++) {
#pragma unroll
        for (int dc = 0; dc < 4; dc++)
#pragma unroll
            for (int r = 0; r < 4; r++) O[m][dc][r] = 0.f;
#pragma unroll
        for (int r = 0; r < 4; r++) Lc[m][r] = 0.f;
    }

    const uint4* kb = (const uint4*)(g_kh + (size_t)bh * TK * HD);
    const __half* vtb = g_vt + (size_t)bh * HD * TK;
    const int nfull = (P_ + q0) >> 6;
    const int ntot = nfull + 2;
    const int t_begin = (ntot * split) / KS;
    const int t_end = (ntot * (split + 1)) / KS;

    auto load_tile = [&](int t, int buf) {
        const int j0 = t << 6;
#pragma unroll
        for (int i = 0; i < 2; i++) {
            const int f = tid + (i << 7);
            const int key = f >> 2;
            const int part = f & 3;
            cp16(&Kh[buf][key][part * 8], kb + (size_t)j0 * 4 + f);
        }
#pragma unroll
        for (int i = 0; i < 2; i++) {
            const int f = tid + (i << 7);
            const int d = f >> 3;
            const int part = f & 7;
            cp16(&Vst[buf][d][part * 8], vtb + (size_t)d * TK + j0 + part * 8);
        }
    };

    // prologue: prefetch 2 tiles (always commit both groups)
    load_tile(t_begin, 0);
    CP_COMMIT();
    if (t_begin + 1 < t_end) load_tile(t_begin + 1, 1);
    CP_COMMIT();

    int cur = 0;
    for (int t = t_begin; t < t_end; t++) {
        asm volatile("cp.async.wait_group 1;" ::: "memory");
        __syncthreads();           // single barrier per tile (3-buffer rotation)

        int tgt = cur + 2; if (tgt >= 3) tgt -= 3;
        if (t + 2 < t_end) load_tile(t + 2, tgt);
        CP_COMMIT();               // commit every iteration to keep group count aligned

        const bool isdiag = (t == nfull + (w >> 1));
        const bool active = !(t > nfull && (w >> 1) == 0);
        if (active) {
#pragma unroll
            for (int pr = 0; pr < 4; pr++) {
                const int nc0 = 2 * pr, nc1 = 2 * pr + 1;
                // K B-fragments via ldmatrix: regs [kc0 b0, kc0 b1, kc1 b0, kc1 b1]
                uint32_t kf0[4], kf1[4];
                ldsm4(kf0, &Kh[cur][nc0 * 8 + l8][lj * 8]);
                ldsm4(kf1, &Kh[cur][nc1 * 8 + l8][lj * 8]);

                float S0[2][4], S1[2][4];
#pragma unroll
                for (int m = 0; m < 2; m++)
#pragma unroll
                    for (int r = 0; r < 4; r++) { S0[m][r] = 0.f; S1[m][r] = 0.f; }
#pragma unroll
                for (int kc = 0; kc < 2; kc++) {
                    mma16h(S0[0], qa[0][kc], kf0[kc * 2], kf0[kc * 2 + 1]);
                    mma16h(S0[1], qa[1][kc], kf0[kc * 2], kf0[kc * 2 + 1]);
                    mma16h(S1[0], qa[0][kc], kf1[kc * 2], kf1[kc * 2 + 1]);
                    mma16h(S1[1], qa[1][kc], kf1[kc * 2], kf1[kc * 2 + 1]);
                }

                if (isdiag) {
#pragma unroll
                    for (int m = 0; m < 2; m++) {
                        const int rbase = 32 * (w & 1) + m * 16 + g;
                        const int c00 = nc0 * 8 + 2 * t4;
                        const int c10 = nc1 * 8 + 2 * t4;
                        S0[m][0] = (c00     <= rbase)     ? S0[m][0] : -100.f;
                        S0[m][1] = (c00 + 1 <= rbase)     ? S0[m][1] : -100.f;
                        S0[m][2] = (c00     <= rbase + 8) ? S0[m][2] : -100.f;
                        S0[m][3] = (c00 + 1 <= rbase + 8) ? S0[m][3] : -100.f;
                        S1[m][0] = (c10     <= rbase)     ? S1[m][0] : -100.f;
                        S1[m][1] = (c10 + 1 <= rbase)     ? S1[m][1] : -100.f;
                        S1[m][2] = (c10     <= rbase + 8) ? S1[m][2] : -100.f;
                        S1[m][3] = (c10 + 1 <= rbase + 8) ? S1[m][3] : -100.f;
                    }
                }

                // P = 2^S via f16x2 MUFU; result IS the PV A-fragment
                uint32_t A[2][4];
#pragma unroll
                for (int m = 0; m < 2; m++) {
                    A[m][0] = ex2h2(packh2(S0[m][0], S0[m][1]));
                    A[m][1] = ex2h2(packh2(S0[m][2], S0[m][3]));
                    A[m][2] = ex2h2(packh2(S1[m][0], S1[m][1]));
                    A[m][3] = ex2h2(packh2(S1[m][2], S1[m][3]));
                    mma16h(Lc[m], A[m], ONE2, ONE2);   // row sums on tensor pipe
                }

                // V B-fragments via ldmatrix
                const int k0 = pr * 16;
                uint32_t vfA[4], vfB[4];
                ldsm4(vfA, &Vst[cur][(lj >> 1) * 8 + l8][k0 + (lj & 1) * 8]);
                ldsm4(vfB, &Vst[cur][16 + (lj >> 1) * 8 + l8][k0 + (lj & 1) * 8]);

                mma16h(O[0][0], A[0], vfA[0], vfA[1]);
                mma16h(O[1][0], A[1], vfA[0], vfA[1]);
                mma16h(O[0][1], A[0], vfA[2], vfA[3]);
                mma16h(O[1][1], A[1], vfA[2], vfA[3]);
                mma16h(O[0][2], A[0], vfB[0], vfB[1]);
                mma16h(O[1][2], A[1], vfB[0], vfB[1]);
                mma16h(O[0][3], A[0], vfB[2], vfB[3]);
                mma16h(O[1][3], A[1], vfB[2], vfB[3]);
            }
        }
        cur = (cur == 2) ? 0 : cur + 1;
    }

    // store partials (Lc[m][0] = row-g sum; Lc[m][2] = row g+8 sum)
    const size_t pbase = ((size_t)split * (B_ * H_) + bh) * T_;
#pragma unroll
    for (int m = 0; m < 2; m++) {
        const int r0 = wq + m * 16 + g;
        if (t4 == 0) {
            g_pl[pbase + r0] = Lc[m][0];
            g_pl[pbase + r0 + 8] = Lc[m][2];
        }
        float* p0 = g_pacc + (pbase + r0) * HD;
        float* p1 = g_pacc + (pbase + r0 + 8) * HD;
#pragma unroll
        for (int dc = 0; dc < 4; dc++) {
            const int col = dc * 8 + 2 * t4;
            *(float2*)&p0[col] = make_float2(O[m][dc][0], O[m][dc][1]);
            *(float2*)&p1[col] = make_float2(O[m][dc][2], O[m][dc][3]);
        }
    }
}

// ---------------- combine splits -> g_ctxh (fp16) ----------------------------
__global__ void __launch_bounds__(256) attn_combine() {
    const int idx = blockIdx.x * 256 + threadIdx.x;
    const int q_lin = idx >> 3;
    const int f = idx & 7;
    const int bh = q_lin >> 12;
    const int qi = q_lin & (T_ - 1);
    const int b = bh >> 2;
    const int h = bh & 3;

    float l = 0.f;
    float4 acc = make_float4(0.f, 0.f, 0.f, 0.f);
#pragma unroll
    for (int s = 0; s < KS; s++) {
        const size_t pb = ((size_t)s * (B_ * H_) + bh) * T_;
        l += g_pl[pb + qi];
        const float4 v = *(const float4*)(g_pacc + (pb + qi) * HD + f * 4);
        acc.x += v.x; acc.y += v.y; acc.z += v.z; acc.w += v.w;
    }
    const float inv = 1.f / l;
    uint2 o = make_uint2(packh2(acc.x * inv, acc.y * inv),
                         packh2(acc.z * inv, acc.w * inv));
    *(uint2*)(g_ctxh + ((size_t)b * T_ + qi) * DM + h * HD + f * 4) = o;
}

// ---------------- TC GEMM 2: out = ctx @ Wout (fp32 out) ---------------------
__global__ void __launch_bounds__(128) gemm_out_tc(float* __restrict__ out) {
    __shared__ __half Ah[128][72];
    __shared__ __half Wts[64][72];
    const int tid = threadIdx.x;
    const int w = tid >> 5;
    const int lane = tid & 31;
    const int g = lane >> 2;
    const int t4 = lane & 3;
    const int m0 = blockIdx.x * 128;
    const int n0 = blockIdx.y * 64;

    float c[2][8][4];
#pragma unroll
    for (int m = 0; m < 2; m++)
#pragma unroll
        for (int nc = 0; nc < 8; nc++)
#pragma unroll
            for (int r = 0; r < 4; r++) c[m][nc][r] = 0.f;

    for (int k0 = 0; k0 < 128; k0 += 64) {
        __syncthreads();
#pragma unroll
        for (int i = 0; i < 8; i++) {
            const int f = tid + (i << 7);
            const int row = f >> 3, part = f & 7;
            *(uint4*)&Ah[row][part * 8] =
                *(const uint4*)(g_ctxh + (size_t)(m0 + row) * 128 + k0 + part * 8);
        }
#pragma unroll
        for (int i = 0; i < 4; i++) {
            const int f = tid + (i << 7);
            const int row = f >> 3, part = f & 7;
            *(uint4*)&Wts[row][part * 8] =
                *(const uint4*)(g_woutT + (size_t)(n0 + row) * 128 + k0 + part * 8);
        }
        __syncthreads();

        uint32_t a[2][4][4];
#pragma unroll
        for (int m = 0; m < 2; m++) {
            const int r0 = w * 32 + m * 16 + g;
#pragma unroll
            for (int kc = 0; kc < 4; kc++) {
                const int cb = kc * 16 + 2 * t4;
                a[m][kc][0] = *(const uint32_t*)&Ah[r0][cb];
                a[m][kc][1] = *(const uint32_t*)&Ah[r0 + 8][cb];
                a[m][kc][2] = *(const uint32_t*)&Ah[r0][cb + 8];
                a[m][kc][3] = *(const uint32_t*)&Ah[r0 + 8][cb + 8];
            }
        }
#pragma unroll
        for (int nc = 0; nc < 8; nc++) {
#pragma unroll
            for (int kc = 0; kc < 4; kc++) {
                const uint32_t b0 = *(const uint32_t*)&Wts[nc * 8 + g][kc * 16 + 2 * t4];
                const uint32_t b1 = *(const uint32_t*)&Wts[nc * 8 + g][kc * 16 + 2 * t4 + 8];
                mma16h(c[0][nc], a[0][kc], b0, b1);
                mma16h(c[1][nc], a[1][kc], b0, b1);
            }
        }
    }

#pragma unroll
    for (int m = 0; m < 2; m++) {
#pragma unroll
        for (int rr = 0; rr < 2; rr++) {
            const int row = m0 + w * 32 + m * 16 + g + rr * 8;
#pragma unroll
            for (int nc = 0; nc < 8; nc++) {
                const int n = n0 + nc * 8 + 2 * t4;
                *(float2*)(out + (size_t)row * 128 + n) =
                    make_float2(c[m][nc][rr * 2 + 0], c[m][nc][rr * 2 + 1]);
            }
        }
    }
}

// ---------------- launch ----------------------------------------------------
extern "C" void kernel_launch(void* const* d_in, const int* in_sizes, int n_in,
                              void* d_out, int out_size) {
    const float* x    = (const float*)d_in[0];
    const float* pk   = (const float*)d_in[1];
    const float* pv   = (const float*)d_in[2];
    const float* Wqkv = (const float*)d_in[3];
    const float* Wout = (const float*)d_in[4];
    float* out = (float*)d_out;

    prep_all<<<1792, 256>>>((const float4*)x, Wqkv, Wout,
                            (const float4*)pk, (const float4*)pv);
    {
        dim3 grid(64, 6);
        gemm_qkv_tc<<<grid, 128>>>();
    }
    {
        dim3 grid(TK / 64, B_ * H_);
        v_transpose<<<grid, 128>>>();
    }
    {
        dim3 grid(32, KS, B_ * H_);
        attn_tc<<<grid, 128>>>();
    }
    {
        attn_combine<<<(B_ * H_ * T_ * 8) / 256, 256>>>();
    }
    {
        dim3 grid(64, 2);
        gemm_out_tc<<<grid, 128>>>(out);
    }
}

// round 17
// speedup vs baseline: 12.2000x; 1.0750x over previous
#include <cuda_runtime.h>
#include <cuda_fp16.h>
#include <cstdint>

// Problem constants
#define B_ 2
#define T_ 4096
#define H_ 4
#define HD 32
#define P_ 2048
#define TK 6144           // P_ + T_
#define DM 128            // D_MODEL
#define KS 8              // key splits (finer blocks -> better wave packing)
#define RSQRT_HD 0.17677669529663687f
#define LOG2E 1.4426950408889634f
#define QSCALE (RSQRT_HD * LOG2E)

// ---------------- scratch (device globals; no allocation allowed) ------------
__device__ __align__(16) __half g_xh[(size_t)B_ * T_ * DM];        // x fp16
__device__ __align__(16) __half g_wqkvT[(size_t)3 * DM * DM];      // Wqkv^T [384][128]
__device__ __align__(16) __half g_woutT[(size_t)DM * DM];          // Wout^T [128][128]
__device__ __align__(16) __half g_qh[(size_t)B_ * H_ * T_ * HD];   // pre-scaled by QSCALE
__device__ __align__(16) __half g_kh[(size_t)B_ * H_ * TK * HD];   // [bh][key][d]
__device__ __align__(16) __half g_vh[(size_t)B_ * H_ * TK * HD];   // [bh][key][d]
__device__ __align__(16) __half g_vt[(size_t)B_ * H_ * HD * TK];   // [bh][d][key]
__device__ __align__(16) __half g_ctxh[(size_t)B_ * T_ * DM];      // fp16 ctx
__device__ float g_pacc[(size_t)KS * B_ * H_ * T_ * HD];
__device__ float g_pl[(size_t)KS * B_ * H_ * T_];

// ---------------- helpers ----------------------------------------------------
__device__ __forceinline__ void mma16h(float* c, const uint32_t* a, uint32_t b0, uint32_t b1) {
    asm("mma.sync.aligned.m16n8k16.row.col.f32.f16.f16.f32 "
        "{%0,%1,%2,%3},{%4,%5,%6,%7},{%8,%9},{%0,%1,%2,%3};"
        : "+f"(c[0]), "+f"(c[1]), "+f"(c[2]), "+f"(c[3])
        : "r"(a[0]), "r"(a[1]), "r"(a[2]), "r"(a[3]), "r"(b0), "r"(b1));
}
__device__ __forceinline__ uint32_t packh2(float lo, float hi) {
    __half2 h = __float22half2_rn(make_float2(lo, hi));
    return *reinterpret_cast<uint32_t*>(&h);
}
__device__ __forceinline__ uint32_t ex2h2(uint32_t a) {
    uint32_t d;
    asm("ex2.approx.f16x2 %0, %1;" : "=r"(d) : "r"(a));
    return d;
}
__device__ __forceinline__ void cp16(void* sptr, const void* gptr) {
    uint32_t sa = (uint32_t)__cvta_generic_to_shared(sptr);
    asm volatile("cp.async.ca.shared.global [%0], [%1], 16;" :: "r"(sa), "l"(gptr) : "memory");
}
__device__ __forceinline__ void ldsm4(uint32_t* r, const void* p) {
    uint32_t a = (uint32_t)__cvta_generic_to_shared(p);
    asm volatile("ldmatrix.sync.aligned.m8n8.x4.shared.b16 {%0,%1,%2,%3}, [%4];"
        : "=r"(r[0]), "=r"(r[1]), "=r"(r[2]), "=r"(r[3]) : "r"(a));
}
#define CP_COMMIT() asm volatile("cp.async.commit_group;" ::: "memory")
#define ONE2 0x3C003C00u

// ---------------- prep: x->fp16, W transposes, prefix K/V -> fp16 ------------
__global__ void __launch_bounds__(256) prep_all(const float4* __restrict__ x4,
                                                const float* __restrict__ Wqkv,
                                                const float* __restrict__ Wout,
                                                const float4* __restrict__ pk,
                                                const float4* __restrict__ pv) {
    const int i = blockIdx.x * 256 + threadIdx.x;
    if (i < 262144) {                                   // x: B*T*DM/4 uint2 stores
        float4 v = x4[i];
        uint2 o = make_uint2(packh2(v.x, v.y), packh2(v.z, v.w));
        ((uint2*)g_xh)[i] = o;
    } else if (i < 262144 + 49152) {                    // Wqkv^T
        const int j = i - 262144;
        const int n = j >> 7, k = j & 127;
        g_wqkvT[j] = __float2half_rn(Wqkv[k * 384 + n]);
    } else if (i < 262144 + 49152 + 16384) {            // Wout^T
        const int j = i - 262144 - 49152;
        const int n = j >> 7, k = j & 127;
        g_woutT[j] = __float2half_rn(Wout[k * 128 + n]);
    } else if (i < 262144 + 49152 + 16384 + 131072) {   // prefix K/V
        const int idx = i - 262144 - 49152 - 16384;
        const int per_bh = P_ * HD / 4;
        const int bh = idx / per_bh;
        const int rem = idx - bh * per_bh;
        float4 k = pk[idx];
        uint2 kk = make_uint2(packh2(k.x, k.y), packh2(k.z, k.w));
        *(uint2*)(g_kh + ((size_t)bh * TK * HD) + rem * 4) = kk;
        float4 v = pv[idx];
        uint2 vv = make_uint2(packh2(v.x, v.y), packh2(v.z, v.w));
        *(uint2*)(g_vh + ((size_t)bh * TK * HD) + rem * 4) = vv;
    }
}

// ---------------- TC GEMM 1: qkv = x @ Wqkv, scatter to g_qh/g_kh/g_vh -------
__global__ void __launch_bounds__(128) gemm_qkv_tc() {
    __shared__ __half Ah[128][72];
    __shared__ __half Wts[64][72];
    const int tid = threadIdx.x;
    const int w = tid >> 5;
    const int lane = tid & 31;
    const int g = lane >> 2;
    const int t4 = lane & 3;
    const int m0 = blockIdx.x * 128;
    const int n0 = blockIdx.y * 64;

    float c[2][8][4];
#pragma unroll
    for (int m = 0; m < 2; m++)
#pragma unroll
        for (int nc = 0; nc < 8; nc++)
#pragma unroll
            for (int r = 0; r < 4; r++) c[m][nc][r] = 0.f;

    for (int k0 = 0; k0 < 128; k0 += 64) {
        __syncthreads();
#pragma unroll
        for (int i = 0; i < 8; i++) {
            const int f = tid + (i << 7);
            const int row = f >> 3, part = f & 7;
            *(uint4*)&Ah[row][part * 8] =
                *(const uint4*)(g_xh + (size_t)(m0 + row) * 128 + k0 + part * 8);
        }
#pragma unroll
        for (int i = 0; i < 4; i++) {
            const int f = tid + (i << 7);
            const int row = f >> 3, part = f & 7;
            *(uint4*)&Wts[row][part * 8] =
                *(const uint4*)(g_wqkvT + (size_t)(n0 + row) * 128 + k0 + part * 8);
        }
        __syncthreads();

        uint32_t a[2][4][4];
#pragma unroll
        for (int m = 0; m < 2; m++) {
            const int r0 = w * 32 + m * 16 + g;
#pragma unroll
            for (int kc = 0; kc < 4; kc++) {
                const int cb = kc * 16 + 2 * t4;
                a[m][kc][0] = *(const uint32_t*)&Ah[r0][cb];
                a[m][kc][1] = *(const uint32_t*)&Ah[r0 + 8][cb];
                a[m][kc][2] = *(const uint32_t*)&Ah[r0][cb + 8];
                a[m][kc][3] = *(const uint32_t*)&Ah[r0 + 8][cb + 8];
            }
        }
#pragma unroll
        for (int nc = 0; nc < 8; nc++) {
#pragma unroll
            for (int kc = 0; kc < 4; kc++) {
                const uint32_t b0 = *(const uint32_t*)&Wts[nc * 8 + g][kc * 16 + 2 * t4];
                const uint32_t b1 = *(const uint32_t*)&Wts[nc * 8 + g][kc * 16 + 2 * t4 + 8];
                mma16h(c[0][nc], a[0][kc], b0, b1);
                mma16h(c[1][nc], a[1][kc], b0, b1);
            }
        }
    }

    const int sec = n0 >> 7;
    const int n0r = n0 & 127;
#pragma unroll
    for (int m = 0; m < 2; m++) {
#pragma unroll
        for (int rr = 0; rr < 2; rr++) {
            const int row = m0 + w * 32 + m * 16 + g + rr * 8;
            const int b = row >> 12;
            const int t = row & (T_ - 1);
#pragma unroll
            for (int nc = 0; nc < 8; nc++) {
                const int n = n0r + nc * 8 + 2 * t4;
                const int h = n >> 5;
                const int d = n & 31;
                const float v0 = c[m][nc][rr * 2 + 0];
                const float v1 = c[m][nc][rr * 2 + 1];
                if (sec == 0) {
                    *(uint32_t*)(g_qh + (((size_t)(b * H_ + h) * T_) + t) * HD + d) =
                        packh2(v0 * QSCALE, v1 * QSCALE);
                } else if (sec == 1) {
                    *(uint32_t*)(g_kh + (((size_t)(b * H_ + h) * TK) + P_ + t) * HD + d) =
                        packh2(v0, v1);
                } else {
                    *(uint32_t*)(g_vh + (((size_t)(b * H_ + h) * TK) + P_ + t) * HD + d) =
                        packh2(v0, v1);
                }
            }
        }
    }
}

// ---------------- V transpose: g_vh [bh][key][d] -> g_vt [bh][d][key] --------
__global__ void __launch_bounds__(128) v_transpose() {
    __shared__ __half S[HD][72];
    const int bh = blockIdx.y;
    const int j0 = blockIdx.x * 64;
    const int tid = threadIdx.x;

#pragma unroll
    for (int i = 0; i < 4; i++) {
        const int f = tid + i * 128;
        const int key = f >> 3;
        const int d0 = (f & 7) * 4;
        uint2 v = *(const uint2*)(g_vh + ((size_t)bh * TK + j0 + key) * HD + d0);
        __half2 p0 = *(__half2*)&v.x;
        __half2 p1 = *(__half2*)&v.y;
        S[d0 + 0][key] = __low2half(p0);
        S[d0 + 1][key] = __high2half(p0);
        S[d0 + 2][key] = __low2half(p1);
        S[d0 + 3][key] = __high2half(p1);
    }
    __syncthreads();
#pragma unroll
    for (int i = 0; i < 2; i++) {
        const int f = tid + i * 128;
        const int d = f >> 3;
        const int part = f & 7;
        *(uint4*)(g_vt + ((size_t)(bh * HD + d)) * TK + j0 + part * 8) =
            *(const uint4*)&S[d][part * 8];
    }
}

// ---------------- attention: fp16 mma, ex2 softmax, 3-buffer cp.async --------
// 1D grid, LPT order: longest blocks (qt=31) first across all (split,bh).
__global__ void __launch_bounds__(128, 5) attn_tc() {
    __shared__ __half Kh[3][64][40];
    __shared__ __half Vst[3][HD][72];

    const int tid = threadIdx.x;
    const int w = tid >> 5;
    const int lane = tid & 31;
    const int g = lane >> 2;
    const int t4 = lane & 3;
    const int l8 = lane & 7;             // ldmatrix row within 8x8 block
    const int lj = lane >> 3;            // ldmatrix block index 0..3

    // LPT decode: qt descending in the major position
    const int bidx = blockIdx.x;         // 0..2047
    const int qt = 31 - (bidx >> 6);
    const int rest = bidx & 63;
    const int split = rest >> 3;
    const int bh = rest & 7;
    const int q0 = qt * 128;
    const int wq = q0 + w * 32;

    // Q fragments (fp16, pre-scaled by 1/sqrt(hd)*log2e)
    uint32_t qa[2][2][4];
    {
        const __half* qb = g_qh + ((size_t)bh * T_) * HD;
#pragma unroll
        for (int m = 0; m < 2; m++) {
            const int r0 = wq + m * 16 + g;
#pragma unroll
            for (int kc = 0; kc < 2; kc++) {
                const int c = kc * 16 + 2 * t4;
                qa[m][kc][0] = *(const uint32_t*)(qb + (size_t)r0 * HD + c);
                qa[m][kc][1] = *(const uint32_t*)(qb + (size_t)(r0 + 8) * HD + c);
                qa[m][kc][2] = *(const uint32_t*)(qb + (size_t)r0 * HD + c + 8);
                qa[m][kc][3] = *(const uint32_t*)(qb + (size_t)(r0 + 8) * HD + c + 8);
            }
        }
    }

    float O[2][4][4];
    float Lc[2][4];
#pragma unroll
    for (int m = 0; m < 2; m++) {
#pragma unroll
        for (int dc = 0; dc < 4; dc++)
#pragma unroll
            for (int r = 0; r < 4; r++) O[m][dc][r] = 0.f;
#pragma unroll
        for (int r = 0; r < 4; r++) Lc[m][r] = 0.f;
    }

    const uint4* kb = (const uint4*)(g_kh + (size_t)bh * TK * HD);
    const __half* vtb = g_vt + (size_t)bh * HD * TK;
    const int nfull = (P_ + q0) >> 6;
    const int ntot = nfull + 2;
    const int t_begin = (ntot * split) / KS;
    const int t_end = (ntot * (split + 1)) / KS;

    auto load_tile = [&](int t, int buf) {
        const int j0 = t << 6;
#pragma unroll
        for (int i = 0; i < 2; i++) {
            const int f = tid + (i << 7);
            const int key = f >> 2;
            const int part = f & 3;
            cp16(&Kh[buf][key][part * 8], kb + (size_t)j0 * 4 + f);
        }
#pragma unroll
        for (int i = 0; i < 2; i++) {
            const int f = tid + (i << 7);
            const int d = f >> 3;
            const int part = f & 7;
            cp16(&Vst[buf][d][part * 8], vtb + (size_t)d * TK + j0 + part * 8);
        }
    };

    // prologue: prefetch 2 tiles (always commit both groups)
    load_tile(t_begin, 0);
    CP_COMMIT();
    if (t_begin + 1 < t_end) load_tile(t_begin + 1, 1);
    CP_COMMIT();

    int cur = 0;
    for (int t = t_begin; t < t_end; t++) {
        asm volatile("cp.async.wait_group 1;" ::: "memory");
        __syncthreads();           // single barrier per tile (3-buffer rotation)

        int tgt = cur + 2; if (tgt >= 3) tgt -= 3;
        if (t + 2 < t_end) load_tile(t + 2, tgt);
        CP_COMMIT();               // commit every iteration to keep group count aligned

        const bool isdiag = (t == nfull + (w >> 1));
        const bool active = !(t > nfull && (w >> 1) == 0);
        if (active) {
#pragma unroll
            for (int pr = 0; pr < 4; pr++) {
                const int nc0 = 2 * pr, nc1 = 2 * pr + 1;
                // K B-fragments via ldmatrix: regs [kc0 b0, kc0 b1, kc1 b0, kc1 b1]
                uint32_t kf0[4], kf1[4];
                ldsm4(kf0, &Kh[cur][nc0 * 8 + l8][lj * 8]);
                ldsm4(kf1, &Kh[cur][nc1 * 8 + l8][lj * 8]);

                float S0[2][4], S1[2][4];
#pragma unroll
                for (int m = 0; m < 2; m++)
#pragma unroll
                    for (int r = 0; r < 4; r++) { S0[m][r] = 0.f; S1[m][r] = 0.f; }
#pragma unroll
                for (int kc = 0; kc < 2; kc++) {
                    mma16h(S0[0], qa[0][kc], kf0[kc * 2], kf0[kc * 2 + 1]);
                    mma16h(S0[1], qa[1][kc], kf0[kc * 2], kf0[kc * 2 + 1]);
                    mma16h(S1[0], qa[0][kc], kf1[kc * 2], kf1[kc * 2 + 1]);
                    mma16h(S1[1], qa[1][kc], kf1[kc * 2], kf1[kc * 2 + 1]);
                }

                if (isdiag) {
#pragma unroll
                    for (int m = 0; m < 2; m++) {
                        const int rbase = 32 * (w & 1) + m * 16 + g;
                        const int c00 = nc0 * 8 + 2 * t4;
                        const int c10 = nc1 * 8 + 2 * t4;
                        S0[m][0] = (c00     <= rbase)     ? S0[m][0] : -100.f;
                        S0[m][1] = (c00 + 1 <= rbase)     ? S0[m][1] : -100.f;
                        S0[m][2] = (c00     <= rbase + 8) ? S0[m][2] : -100.f;
                        S0[m][3] = (c00 + 1 <= rbase + 8) ? S0[m][3] : -100.f;
                        S1[m][0] = (c10     <= rbase)     ? S1[m][0] : -100.f;
                        S1[m][1] = (c10 + 1 <= rbase)     ? S1[m][1] : -100.f;
                        S1[m][2] = (c10     <= rbase + 8) ? S1[m][2] : -100.f;
                        S1[m][3] = (c10 + 1 <= rbase + 8) ? S1[m][3] : -100.f;
                    }
                }

                // P = 2^S via f16x2 MUFU; result IS the PV A-fragment
                uint32_t A[2][4];
#pragma unroll
                for (int m = 0; m < 2; m++) {
                    A[m][0] = ex2h2(packh2(S0[m][0], S0[m][1]));
                    A[m][1] = ex2h2(packh2(S0[m][2], S0[m][3]));
                    A[m][2] = ex2h2(packh2(S1[m][0], S1[m][1]));
                    A[m][3] = ex2h2(packh2(S1[m][2], S1[m][3]));
                    mma16h(Lc[m], A[m], ONE2, ONE2);   // row sums on tensor pipe
                }

                // V B-fragments via ldmatrix
                const int k0 = pr * 16;
                uint32_t vfA[4], vfB[4];
                ldsm4(vfA, &Vst[cur][(lj >> 1) * 8 + l8][k0 + (lj & 1) * 8]);
                ldsm4(vfB, &Vst[cur][16 + (lj >> 1) * 8 + l8][k0 + (lj & 1) * 8]);

                mma16h(O[0][0], A[0], vfA[0], vfA[1]);
                mma16h(O[1][0], A[1], vfA[0], vfA[1]);
                mma16h(O[0][1], A[0], vfA[2], vfA[3]);
                mma16h(O[1][1], A[1], vfA[2], vfA[3]);
                mma16h(O[0][2], A[0], vfB[0], vfB[1]);
                mma16h(O[1][2], A[1], vfB[0], vfB[1]);
                mma16h(O[0][3], A[0], vfB[2], vfB[3]);
                mma16h(O[1][3], A[1], vfB[2], vfB[3]);
            }
        }
        cur = (cur == 2) ? 0 : cur + 1;
    }

    // store partials (Lc[m][0] = row-g sum; Lc[m][2] = row g+8 sum)
    const size_t pbase = ((size_t)split * (B_ * H_) + bh) * T_;
#pragma unroll
    for (int m = 0; m < 2; m++) {
        const int r0 = wq + m * 16 + g;
        if (t4 == 0) {
            g_pl[pbase + r0] = Lc[m][0];
            g_pl[pbase + r0 + 8] = Lc[m][2];
        }
        float* p0 = g_pacc + (pbase + r0) * HD;
        float* p1 = g_pacc + (pbase + r0 + 8) * HD;
#pragma unroll
        for (int dc = 0; dc < 4; dc++) {
            const int col = dc * 8 + 2 * t4;
            *(float2*)&p0[col] = make_float2(O[m][dc][0], O[m][dc][1]);
            *(float2*)&p1[col] = make_float2(O[m][dc][2], O[m][dc][3]);
        }
    }
}

// ---------------- combine splits -> g_ctxh (fp16) ----------------------------
__global__ void __launch_bounds__(256) attn_combine() {
    const int idx = blockIdx.x * 256 + threadIdx.x;
    const int q_lin = idx >> 3;
    const int f = idx & 7;
    const int bh = q_lin >> 12;
    const int qi = q_lin & (T_ - 1);
    const int b = bh >> 2;
    const int h = bh & 3;

    float l = 0.f;
    float4 acc = make_float4(0.f, 0.f, 0.f, 0.f);
#pragma unroll
    for (int s = 0; s < KS; s++) {
        const size_t pb = ((size_t)s * (B_ * H_) + bh) * T_;
        l += g_pl[pb + qi];
        const float4 v = *(const float4*)(g_pacc + (pb + qi) * HD + f * 4);
        acc.x += v.x; acc.y += v.y; acc.z += v.z; acc.w += v.w;
    }
    const float inv = 1.f / l;
    uint2 o = make_uint2(packh2(acc.x * inv, acc.y * inv),
                         packh2(acc.z * inv, acc.w * inv));
    *(uint2*)(g_ctxh + ((size_t)b * T_ + qi) * DM + h * HD + f * 4) = o;
}

// ---------------- TC GEMM 2: out = ctx @ Wout (fp32 out) ---------------------
__global__ void __launch_bounds__(128) gemm_out_tc(float* __restrict__ out) {
    __shared__ __half Ah[128][72];
    __shared__ __half Wts[64][72];
    const int tid = threadIdx.x;
    const int w = tid >> 5;
    const int lane = tid & 31;
    const int g = lane >> 2;
    const int t4 = lane & 3;
    const int m0 = blockIdx.x * 128;
    const int n0 = blockIdx.y * 64;

    float c[2][8][4];
#pragma unroll
    for (int m = 0; m < 2; m++)
#pragma unroll
        for (int nc = 0; nc < 8; nc++)
#pragma unroll
            for (int r = 0; r < 4; r++) c[m][nc][r] = 0.f;

    for (int k0 = 0; k0 < 128; k0 += 64) {
        __syncthreads();
#pragma unroll
        for (int i = 0; i < 8; i++) {
            const int f = tid + (i << 7);
            const int row = f >> 3, part = f & 7;
            *(uint4*)&Ah[row][part * 8] =
                *(const uint4*)(g_ctxh + (size_t)(m0 + row) * 128 + k0 + part * 8);
        }
#pragma unroll
        for (int i = 0; i < 4; i++) {
            const int f = tid + (i << 7);
            const int row = f >> 3, part = f & 7;
            *(uint4*)&Wts[row][part * 8] =
                *(const uint4*)(g_woutT + (size_t)(n0 + row) * 128 + k0 + part * 8);
        }
        __syncthreads();

        uint32_t a[2][4][4];
#pragma unroll
        for (int m = 0; m < 2; m++) {
            const int r0 = w * 32 + m * 16 + g;
#pragma unroll
            for (int kc = 0; kc < 4; kc++) {
                const int cb = kc * 16 + 2 * t4;
                a[m][kc][0] = *(const uint32_t*)&Ah[r0][cb];
                a[m][kc][1] = *(const uint32_t*)&Ah[r0 + 8][cb];
                a[m][kc][2] = *(const uint32_t*)&Ah[r0][cb + 8];
                a[m][kc][3] = *(const uint32_t*)&Ah[r0 + 8][cb + 8];
            }
        }
#pragma unroll
        for (int nc = 0; nc < 8; nc++) {
#pragma unroll
            for (int kc = 0; kc < 4; kc++) {
                const uint32_t b0 = *(const uint32_t*)&Wts[nc * 8 + g][kc * 16 + 2 * t4];
                const uint32_t b1 = *(const uint32_t*)&Wts[nc * 8 + g][kc * 16 + 2 * t4 + 8];
                mma16h(c[0][nc], a[0][kc], b0, b1);
                mma16h(c[1][nc], a[1][kc], b0, b1);
            }
        }
    }

#pragma unroll
    for (int m = 0; m < 2; m++) {
#pragma unroll
        for (int rr = 0; rr < 2; rr++) {
            const int row = m0 + w * 32 + m * 16 + g + rr * 8;
#pragma unroll
            for (int nc = 0; nc < 8; nc++) {
                const int n = n0 + nc * 8 + 2 * t4;
                *(float2*)(out + (size_t)row * 128 + n) =
                    make_float2(c[m][nc][rr * 2 + 0], c[m][nc][rr * 2 + 1]);
            }
        }
    }
}

// ---------------- launch ----------------------------------------------------
extern "C" void kernel_launch(void* const* d_in, const int* in_sizes, int n_in,
                              void* d_out, int out_size) {
    const float* x    = (const float*)d_in[0];
    const float* pk   = (const float*)d_in[1];
    const float* pv   = (const float*)d_in[2];
    const float* Wqkv = (const float*)d_in[3];
    const float* Wout = (const float*)d_in[4];
    float* out = (float*)d_out;

    prep_all<<<1792, 256>>>((const float4*)x, Wqkv, Wout,
                            (const float4*)pk, (const float4*)pv);
    {
        dim3 grid(64, 6);
        gemm_qkv_tc<<<grid, 128>>>();
    }
    {
        dim3 grid(TK / 64, B_ * H_);
        v_transpose<<<grid, 128>>>();
    }
    {
        attn_tc<<<32 * KS * B_ * H_, 128>>>();
    }
    {
        attn_combine<<<(B_ * H_ * T_ * 8) / 256, 256>>>();
    }
    {
        dim3 grid(64, 2);
        gemm_out_tc<<<grid, 128>>>(out);
    }
}